// round 5
// baseline (speedup 1.0000x reference)
#include <cuda_runtime.h>
#include <cuda_bf16.h>
#include <mma.h>

using namespace nvcuda;

#define BB 4
#define NN 1024
#define JJ 2048
#define HH 16
#define DD 128
#define DIMM 2048
#define NQKV 6144
#define ROWS 4096

__device__ float g_xn[(size_t)ROWS * DIMM];
__device__ float g_qkv[(size_t)ROWS * NQKV];
__device__ float g_qrot[(size_t)BB * HH * NN * DD];
__device__ float g_krot[(size_t)BB * HH * JJ * DD];
__device__ float g_vfull[(size_t)BB * HH * JJ * DD];
__device__ float g_attnout[(size_t)ROWS * DIMM];
__device__ float g_cos[JJ * DD];
__device__ float g_sin[JJ * DD];

__global__ void __launch_bounds__(256) rope_table_kernel(const float* __restrict__ rot) {
    int idx = blockIdx.x * 256 + threadIdx.x;
    float p = rot[idx];
    g_cos[idx] = cosf(p);
    g_sin[idx] = sinf(p);
}

__global__ void __launch_bounds__(256) rmsnorm_kernel(const float* __restrict__ x,
                                                      const float* __restrict__ w) {
    int row = blockIdx.x;
    int tid = threadIdx.x;
    const float* xr = x + (size_t)row * DIMM;
    float ss = 0.0f;
    #pragma unroll
    for (int i = tid * 4; i < DIMM; i += 1024) {
        float4 v = *(const float4*)(xr + i);
        ss += v.x * v.x + v.y * v.y + v.z * v.z + v.w * v.w;
    }
    #pragma unroll
    for (int o = 16; o; o >>= 1) ss += __shfl_xor_sync(0xffffffffu, ss, o);
    __shared__ float red[8];
    if ((tid & 31) == 0) red[tid >> 5] = ss;
    __syncthreads();
    float tot = 0.0f;
    #pragma unroll
    for (int i = 0; i < 8; i++) tot += red[i];
    float inv = rsqrtf(tot * (1.0f / (float)DIMM) + 1.1920929e-7f);
    for (int i = tid; i < DIMM; i += 256)
        g_xn[(size_t)row * DIMM + i] = xr[i] * inv * w[i];
}

__global__ void __launch_bounds__(256) gemm_tf32_kernel(const float* __restrict__ A,
                                                        const float* __restrict__ B,
                                                        float* __restrict__ C,
                                                        int M, int N, int K) {
    __shared__ float As[128 * 36];
    __shared__ float Bs[32 * 132];

    int tid = threadIdx.x;
    int n0 = blockIdx.x * 128;
    int m0 = blockIdx.y * 128;
    int w = tid >> 5;
    int wm = w >> 2;
    int wn = w & 3;

    wmma::fragment<wmma::accumulator, 16, 16, 8, float> acc[4][2];
    #pragma unroll
    for (int i = 0; i < 4; i++)
        #pragma unroll
        for (int j = 0; j < 2; j++) wmma::fill_fragment(acc[i][j], 0.0f);

    int arow = tid >> 3;
    int acol = (tid & 7) * 4;
    int brow = tid >> 5;
    int bcol = (tid & 31) * 4;

    for (int kk = 0; kk < K; kk += 32) {
        #pragma unroll
        for (int it = 0; it < 4; it++) {
            *(float4*)&As[(arow + it * 32) * 36 + acol] =
                *(const float4*)&A[(size_t)(m0 + arow + it * 32) * K + kk + acol];
            *(float4*)&Bs[(brow + it * 8) * 132 + bcol] =
                *(const float4*)&B[(size_t)(kk + brow + it * 8) * N + n0 + bcol];
        }
        __syncthreads();

        #pragma unroll
        for (int kf = 0; kf < 4; kf++) {
            wmma::fragment<wmma::matrix_a, 16, 16, 8, wmma::precision::tf32, wmma::row_major> af[4];
            wmma::fragment<wmma::matrix_b, 16, 16, 8, wmma::precision::tf32, wmma::row_major> bf[2];
            #pragma unroll
            for (int i = 0; i < 4; i++) {
                wmma::load_matrix_sync(af[i], &As[(wm * 64 + i * 16) * 36 + kf * 8], 36);
                #pragma unroll
                for (int t = 0; t < af[i].num_elements; t++)
                    af[i].x[t] = wmma::__float_to_tf32(af[i].x[t]);
            }
            #pragma unroll
            for (int j = 0; j < 2; j++) {
                wmma::load_matrix_sync(bf[j], &Bs[(kf * 8) * 132 + wn * 32 + j * 16], 132);
                #pragma unroll
                for (int t = 0; t < bf[j].num_elements; t++)
                    bf[j].x[t] = wmma::__float_to_tf32(bf[j].x[t]);
            }
            #pragma unroll
            for (int i = 0; i < 4; i++)
                #pragma unroll
                for (int j = 0; j < 2; j++)
                    wmma::mma_sync(acc[i][j], af[i], bf[j], acc[i][j]);
        }
        __syncthreads();
    }

    #pragma unroll
    for (int i = 0; i < 4; i++)
        #pragma unroll
        for (int j = 0; j < 2; j++)
            wmma::store_matrix_sync(&C[(size_t)(m0 + wm * 64 + i * 16) * N + n0 + wn * 32 + j * 16],
                                    acc[i][j], N, wmma::mem_row_major);
}

__global__ void __launch_bounds__(256) scatter_rotary_kernel(const float* __restrict__ cache,
                                                             float* __restrict__ kv_out) {
    int idx = blockIdx.x * 256 + threadIdx.x;
    int dd = idx & 127;
    int j  = (idx >> 7) & 2047;
    int h  = (idx >> 18) & 15;
    int b  = idx >> 22;

    float c = g_cos[j * DD + dd];
    float s = g_sin[j * DD + dd];
    int pd = (dd < 64) ? dd + 64 : dd - 64;
    float sgn = (dd < 64) ? -1.0f : 1.0f;

    float kvl, kpart, vv;
    if (j < 1024) {
        const float* ckb = cache + (((size_t)(b * 2 + 0) * HH + h) * 1024 + j) * DD;
        const float* cvb = cache + (((size_t)(b * 2 + 1) * HH + h) * 1024 + j) * DD;
        kvl = ckb[dd];
        kpart = ckb[pd];
        vv = cvb[dd];
    } else {
        int rrow = b * NN + (j - 1024);
        const float* qr = g_qkv + (size_t)rrow * NQKV;
        kvl   = qr[2048 + h * DD + dd];
        kpart = qr[2048 + h * DD + pd];
        vv    = qr[4096 + h * DD + dd];
        float ql = qr[h * DD + dd];
        float qp = qr[h * DD + pd];
        g_qrot[(((size_t)(b * HH + h) * NN + (j - 1024)) * DD) + dd] = ql * c + sgn * qp * s;
    }

    size_t kvidx = ((size_t)(b * HH + h) * JJ + j) * DD + dd;
    g_krot[kvidx]  = kvl * c + sgn * kpart * s;
    g_vfull[kvidx] = vv;

    kv_out[(((size_t)(b * 2 + 0) * HH + h) * JJ + j) * DD + dd] = kvl;
    kv_out[(((size_t)(b * 2 + 1) * HH + h) * JJ + j) * DD + dd] = vv;
}

#define AT_SMEM_BYTES ((16 * 132 + 16 * 2064 + 128 * 132) * 4)

__global__ void __launch_bounds__(256) attn_kernel(const int* __restrict__ mask) {
    extern __shared__ float sm[];
    float* Qs  = sm;
    float* Ss  = sm + 16 * 132;
    float* KVs = sm + 16 * 132 + 16 * 2064;

    int tid = threadIdx.x;
    int w = tid >> 5;
    int bid = blockIdx.x;
    int qb = bid & 63;
    int h  = (bid >> 6) & 15;
    int b  = bid >> 10;
    int m0 = qb * 16;

    const float* qp = g_qrot + ((size_t)(b * HH + h) * NN + m0) * DD;
    const float* kp = g_krot + (size_t)(b * HH + h) * JJ * DD;
    const float* vp = g_vfull + (size_t)(b * HH + h) * JJ * DD;

    #pragma unroll
    for (int i = tid; i < 512; i += 256) {
        int r = i >> 5, c4 = (i & 31) * 4;
        *(float4*)&Qs[r * 132 + c4] = *(const float4*)&qp[r * DD + c4];
    }
    __syncthreads();

    wmma::fragment<wmma::matrix_a, 16, 16, 8, wmma::precision::tf32, wmma::row_major> aq[16];
    #pragma unroll
    for (int kf = 0; kf < 16; kf++) {
        wmma::load_matrix_sync(aq[kf], &Qs[kf * 8], 132);
        #pragma unroll
        for (int t = 0; t < aq[kf].num_elements; t++)
            aq[kf].x[t] = wmma::__float_to_tf32(aq[kf].x[t]);
    }

    int jmax = m0 + 16 - 1 + 1024 + 1;
    int nt = (jmax + 127) >> 7;

    for (int kt = 0; kt < nt; kt++) {
        #pragma unroll
        for (int i = tid; i < 4096; i += 256) {
            int r = i >> 5, c4 = (i & 31) * 4;
            *(float4*)&KVs[r * 132 + c4] = *(const float4*)&kp[(size_t)(kt * 128 + r) * DD + c4];
        }
        __syncthreads();

        wmma::fragment<wmma::accumulator, 16, 16, 8, float> sacc;
        wmma::fill_fragment(sacc, 0.0f);
        #pragma unroll
        for (int kf = 0; kf < 16; kf++) {
            wmma::fragment<wmma::matrix_b, 16, 16, 8, wmma::precision::tf32, wmma::col_major> bk;
            wmma::load_matrix_sync(bk, &KVs[(w * 16) * 132 + kf * 8], 132);
            #pragma unroll
            for (int t = 0; t < bk.num_elements; t++)
                bk.x[t] = wmma::__float_to_tf32(bk.x[t]);
            wmma::mma_sync(sacc, aq[kf], bk, sacc);
        }
        wmma::store_matrix_sync(&Ss[kt * 128 + w * 16], sacc, 2064, wmma::mem_row_major);
        __syncthreads();
    }

    {
        int r = tid >> 4;
        int l = tid & 15;
        int gr = m0 + r;
        int rowlim = gr + 1024;
        int Jt = nt << 7;
        const int* mrow = mask + (size_t)b * JJ;
        const float scale = 0.08838834764831845f;

        float mx = -1e30f;
        for (int j = l; j < Jt; j += 16) {
            float val = Ss[r * 2064 + j] * scale;
            if (j > rowlim || mrow[j] == 0) val = -1e30f;
            Ss[r * 2064 + j] = val;
            mx = fmaxf(mx, val);
        }
        #pragma unroll
        for (int o = 8; o; o >>= 1) mx = fmaxf(mx, __shfl_xor_sync(0xffffffffu, mx, o));
        float ls = 0.0f;
        for (int j = l; j < Jt; j += 16) {
            float p = __expf(Ss[r * 2064 + j] - mx);
            Ss[r * 2064 + j] = p;
            ls += p;
        }
        #pragma unroll
        for (int o = 8; o; o >>= 1) ls += __shfl_xor_sync(0xffffffffu, ls, o);
        float inv = 1.0f / ls;
        for (int j = l; j < Jt; j += 16) Ss[r * 2064 + j] *= inv;
    }
    __syncthreads();

    wmma::fragment<wmma::accumulator, 16, 16, 8, float> oac;
    wmma::fill_fragment(oac, 0.0f);
    for (int kt = 0; kt < nt; kt++) {
        #pragma unroll
        for (int i = tid; i < 4096; i += 256) {
            int r = i >> 5, c4 = (i & 31) * 4;
            *(float4*)&KVs[r * 132 + c4] = *(const float4*)&vp[(size_t)(kt * 128 + r) * DD + c4];
        }
        __syncthreads();

        #pragma unroll
        for (int kf = 0; kf < 16; kf++) {
            wmma::fragment<wmma::matrix_a, 16, 16, 8, wmma::precision::tf32, wmma::row_major> ap;
            wmma::fragment<wmma::matrix_b, 16, 16, 8, wmma::precision::tf32, wmma::row_major> bv;
            wmma::load_matrix_sync(ap, &Ss[kt * 128 + kf * 8], 2064);
            #pragma unroll
            for (int t = 0; t < ap.num_elements; t++)
                ap.x[t] = wmma::__float_to_tf32(ap.x[t]);
            wmma::load_matrix_sync(bv, &KVs[(kf * 8) * 132 + w * 16], 132);
            #pragma unroll
            for (int t = 0; t < bv.num_elements; t++)
                bv.x[t] = wmma::__float_to_tf32(bv.x[t]);
            wmma::mma_sync(oac, ap, bv, oac);
        }
        __syncthreads();
    }

    float* op = g_attnout + ((size_t)(b * NN + m0)) * DIMM + h * DD + w * 16;
    wmma::store_matrix_sync(op, oac, DIMM, wmma::mem_row_major);
}

extern "C" void kernel_launch(void* const* d_in, const int* in_sizes, int n_in,
                              void* d_out, int out_size) {
    const float* x       = (const float*)d_in[0];
    const float* cache   = (const float*)d_in[1];
    const float* rotary  = (const float*)d_in[2];
    const int*   mask    = (const int*)d_in[3];
    const float* norm_w  = (const float*)d_in[4];
    const float* w_qkv   = (const float*)d_in[5];
    const float* w_out   = (const float*)d_in[6];

    float* out    = (float*)d_out;
    float* kv_out = out + (size_t)ROWS * DIMM;

    float *xn_ptr, *qkv_ptr, *ao_ptr;
    cudaGetSymbolAddress((void**)&xn_ptr, g_xn);
    cudaGetSymbolAddress((void**)&qkv_ptr, g_qkv);
    cudaGetSymbolAddress((void**)&ao_ptr, g_attnout);

    cudaFuncSetAttribute(attn_kernel, cudaFuncAttributeMaxDynamicSharedMemorySize, AT_SMEM_BYTES);

    rope_table_kernel<<<(JJ * DD) / 256, 256>>>(rotary);
    rmsnorm_kernel<<<ROWS, 256>>>(x, norm_w);

    dim3 grid_qkv(NQKV / 128, ROWS / 128);
    gemm_tf32_kernel<<<grid_qkv, 256>>>(xn_ptr, w_qkv, qkv_ptr, ROWS, NQKV, DIMM);

    scatter_rotary_kernel<<<(BB * HH * JJ * DD) / 256, 256>>>(cache, kv_out);

    attn_kernel<<<BB * HH * (NN / 16), 256, AT_SMEM_BYTES>>>(mask);

    dim3 grid_out(DIMM / 128, ROWS / 128);
    gemm_tf32_kernel<<<grid_out, 256>>>(ao_ptr, w_out, out, ROWS, DIMM, DIMM);
}

// round 6
// speedup vs baseline: 1.3482x; 1.3482x over previous
#include <cuda_runtime.h>
#include <cuda_bf16.h>
#include <mma.h>

using namespace nvcuda;

#define BB 4
#define NN 1024
#define JJ 2048
#define HH 16
#define DD 128
#define DIMM 2048
#define NQKV 6144
#define ROWS 4096

__device__ float g_xn[(size_t)ROWS * DIMM];
__device__ float g_qkv[(size_t)ROWS * NQKV];
__device__ float g_qrot[(size_t)BB * HH * NN * DD];
__device__ float g_krot[(size_t)BB * HH * JJ * DD];
__device__ float g_vfull[(size_t)BB * HH * JJ * DD];
__device__ float g_attnout[(size_t)ROWS * DIMM];
__device__ float g_cos[JJ * DD];
__device__ float g_sin[JJ * DD];

__device__ __forceinline__ void cpa16(void* smem, const void* gmem) {
    unsigned s = (unsigned)__cvta_generic_to_shared(smem);
    asm volatile("cp.async.cg.shared.global [%0], [%1], 16;\n" :: "r"(s), "l"(gmem));
}

__global__ void __launch_bounds__(256) rope_table_kernel(const float* __restrict__ rot) {
    int idx = blockIdx.x * 256 + threadIdx.x;
    float p = rot[idx];
    g_cos[idx] = cosf(p);
    g_sin[idx] = sinf(p);
}

__global__ void __launch_bounds__(256) rmsnorm_kernel(const float* __restrict__ x,
                                                      const float* __restrict__ w) {
    int row = blockIdx.x;
    int tid = threadIdx.x;
    const float* xr = x + (size_t)row * DIMM;
    float ss = 0.0f;
    #pragma unroll
    for (int i = tid * 4; i < DIMM; i += 1024) {
        float4 v = *(const float4*)(xr + i);
        ss += v.x * v.x + v.y * v.y + v.z * v.z + v.w * v.w;
    }
    #pragma unroll
    for (int o = 16; o; o >>= 1) ss += __shfl_xor_sync(0xffffffffu, ss, o);
    __shared__ float red[8];
    if ((tid & 31) == 0) red[tid >> 5] = ss;
    __syncthreads();
    float tot = 0.0f;
    #pragma unroll
    for (int i = 0; i < 8; i++) tot += red[i];
    float inv = rsqrtf(tot * (1.0f / (float)DIMM) + 1.1920929e-7f);
    for (int i = tid; i < DIMM; i += 256)
        g_xn[(size_t)row * DIMM + i] = xr[i] * inv * w[i];
}

// ---------------- double-buffered tf32 GEMM (cp.async) ----------------
__global__ void __launch_bounds__(256) gemm_tf32_db(const float* __restrict__ A,
                                                    const float* __restrict__ B,
                                                    float* __restrict__ C,
                                                    int M, int N, int K) {
    __shared__ float As[2][128 * 36];
    __shared__ float Bs[2][32 * 132];

    int tid = threadIdx.x;
    int n0 = blockIdx.x * 128;
    int m0 = blockIdx.y * 128;
    int w = tid >> 5;
    int wm = w >> 2;
    int wn = w & 3;

    wmma::fragment<wmma::accumulator, 16, 16, 8, float> acc[4][2];
    #pragma unroll
    for (int i = 0; i < 4; i++)
        #pragma unroll
        for (int j = 0; j < 2; j++) wmma::fill_fragment(acc[i][j], 0.0f);

    int arow = tid >> 3;
    int acol = (tid & 7) * 4;
    int brow = tid >> 5;
    int bcol = (tid & 31) * 4;

    // prologue: stage 0
    {
        int kk = 0;
        #pragma unroll
        for (int it = 0; it < 4; it++) {
            cpa16(&As[0][(arow + it * 32) * 36 + acol],
                  &A[(size_t)(m0 + arow + it * 32) * K + kk + acol]);
            cpa16(&Bs[0][(brow + it * 8) * 132 + bcol],
                  &B[(size_t)(kk + brow + it * 8) * N + n0 + bcol]);
        }
        asm volatile("cp.async.commit_group;\n");
    }

    int nk = K >> 5;
    for (int kt = 0; kt < nk; kt++) {
        if (kt + 1 < nk) {
            int kk = (kt + 1) << 5;
            int st = (kt + 1) & 1;
            #pragma unroll
            for (int it = 0; it < 4; it++) {
                cpa16(&As[st][(arow + it * 32) * 36 + acol],
                      &A[(size_t)(m0 + arow + it * 32) * K + kk + acol]);
                cpa16(&Bs[st][(brow + it * 8) * 132 + bcol],
                      &B[(size_t)(kk + brow + it * 8) * N + n0 + bcol]);
            }
            asm volatile("cp.async.commit_group;\n");
            asm volatile("cp.async.wait_group 1;\n");
        } else {
            asm volatile("cp.async.wait_group 0;\n");
        }
        __syncthreads();

        const float* as = As[kt & 1];
        const float* bs = Bs[kt & 1];

        #pragma unroll
        for (int kf = 0; kf < 4; kf++) {
            wmma::fragment<wmma::matrix_a, 16, 16, 8, wmma::precision::tf32, wmma::row_major> af[4];
            wmma::fragment<wmma::matrix_b, 16, 16, 8, wmma::precision::tf32, wmma::row_major> bf[2];
            #pragma unroll
            for (int i = 0; i < 4; i++) {
                wmma::load_matrix_sync(af[i], &as[(wm * 64 + i * 16) * 36 + kf * 8], 36);
                #pragma unroll
                for (int t = 0; t < af[i].num_elements; t++)
                    af[i].x[t] = wmma::__float_to_tf32(af[i].x[t]);
            }
            #pragma unroll
            for (int j = 0; j < 2; j++) {
                wmma::load_matrix_sync(bf[j], &bs[(kf * 8) * 132 + wn * 32 + j * 16], 132);
                #pragma unroll
                for (int t = 0; t < bf[j].num_elements; t++)
                    bf[j].x[t] = wmma::__float_to_tf32(bf[j].x[t]);
            }
            #pragma unroll
            for (int i = 0; i < 4; i++)
                #pragma unroll
                for (int j = 0; j < 2; j++)
                    wmma::mma_sync(acc[i][j], af[i], bf[j], acc[i][j]);
        }
        __syncthreads();
    }

    #pragma unroll
    for (int i = 0; i < 4; i++)
        #pragma unroll
        for (int j = 0; j < 2; j++)
            wmma::store_matrix_sync(&C[(size_t)(m0 + wm * 64 + i * 16) * N + n0 + wn * 32 + j * 16],
                                    acc[i][j], N, wmma::mem_row_major);
}

__global__ void __launch_bounds__(256) scatter_rotary_kernel(const float* __restrict__ cache,
                                                             float* __restrict__ kv_out) {
    int idx = blockIdx.x * 256 + threadIdx.x;
    int dd = idx & 127;
    int j  = (idx >> 7) & 2047;
    int h  = (idx >> 18) & 15;
    int b  = idx >> 22;

    float c = g_cos[j * DD + dd];
    float s = g_sin[j * DD + dd];
    int pd = (dd < 64) ? dd + 64 : dd - 64;
    float sgn = (dd < 64) ? -1.0f : 1.0f;

    float kvl, kpart, vv;
    if (j < 1024) {
        const float* ckb = cache + (((size_t)(b * 2 + 0) * HH + h) * 1024 + j) * DD;
        const float* cvb = cache + (((size_t)(b * 2 + 1) * HH + h) * 1024 + j) * DD;
        kvl = ckb[dd];
        kpart = ckb[pd];
        vv = cvb[dd];
    } else {
        int rrow = b * NN + (j - 1024);
        const float* qr = g_qkv + (size_t)rrow * NQKV;
        kvl   = qr[2048 + h * DD + dd];
        kpart = qr[2048 + h * DD + pd];
        vv    = qr[4096 + h * DD + dd];
        float ql = qr[h * DD + dd];
        float qp = qr[h * DD + pd];
        g_qrot[(((size_t)(b * HH + h) * NN + (j - 1024)) * DD) + dd] = ql * c + sgn * qp * s;
    }

    size_t kvidx = ((size_t)(b * HH + h) * JJ + j) * DD + dd;
    g_krot[kvidx]  = kvl * c + sgn * kpart * s;
    g_vfull[kvidx] = vv;

    kv_out[(((size_t)(b * 2 + 0) * HH + h) * JJ + j) * DD + dd] = kvl;
    kv_out[(((size_t)(b * 2 + 1) * HH + h) * JJ + j) * DD + dd] = vv;
}

// ---------------- flash attention: 128-query blocks, online softmax ----------------
// smem: Ks 128x132 | Ss 128x132 | Os 128x128 | Mi[128] | Li[128]
#define AT_SMEM_FLOATS (128 * 132 * 2 + 128 * 128 + 256)
#define AT_SMEM_BYTES (AT_SMEM_FLOATS * 4)

__global__ void __launch_bounds__(256) attn_kernel(const int* __restrict__ mask) {
    extern __shared__ float sm[];
    float* Ks = sm;
    float* Ss = sm + 128 * 132;
    float* Os = sm + 2 * 128 * 132;
    float* Mi = Os + 128 * 128;
    float* Li = Mi + 128;

    int tid = threadIdx.x;
    int w = tid >> 5;
    int bid = blockIdx.x;
    int b  = bid & 3;
    int h  = (bid >> 2) & 15;
    int qb = 7 - (bid >> 6);     // heavy blocks (large nt) first
    int m0 = qb * 128;

    const float* qp = g_qrot + ((size_t)(b * HH + h) * NN + m0) * DD;
    const float* kp = g_krot + (size_t)(b * HH + h) * JJ * DD;
    const float* vp = g_vfull + (size_t)(b * HH + h) * JJ * DD;
    const int* mrow = mask + (size_t)b * JJ;

    // load Q into Ss (temp), build per-warp A fragments for rows [w*16, w*16+16)
    #pragma unroll
    for (int i = tid; i < 128 * 32; i += 256) {
        int r = i >> 5, c4 = (i & 31) * 4;
        *(float4*)&Ss[r * 132 + c4] = *(const float4*)&qp[(size_t)r * DD + c4];
    }
    __syncthreads();

    wmma::fragment<wmma::matrix_a, 16, 16, 8, wmma::precision::tf32, wmma::row_major> aq[16];
    #pragma unroll
    for (int kf = 0; kf < 16; kf++) {
        wmma::load_matrix_sync(aq[kf], &Ss[(w * 16) * 132 + kf * 8], 132);
        #pragma unroll
        for (int t = 0; t < aq[kf].num_elements; t++)
            aq[kf].x[t] = wmma::__float_to_tf32(aq[kf].x[t]);
    }

    #pragma unroll
    for (int i = tid; i < 128 * 128; i += 256) Os[i] = 0.0f;
    if (tid < 128) { Mi[tid] = -1e30f; Li[tid] = 0.0f; }

    int nt = qb + 9;   // tiles of 128 keys covering causal span
    const float scale = 0.08838834764831845f;

    for (int kt = 0; kt < nt; kt++) {
        __syncthreads();   // Ks (V of prev tile) fully consumed; Ss (Q/PV temp) consumed

        // load K tile
        #pragma unroll
        for (int i = tid; i < 128 * 32; i += 256) {
            int r = i >> 5, c4 = (i & 31) * 4;
            *(float4*)&Ks[r * 132 + c4] = *(const float4*)&kp[(size_t)(kt * 128 + r) * DD + c4];
        }
        __syncthreads();

        // S = Q K^T  (each warp: 16 rows x 128 cols)
        wmma::fragment<wmma::accumulator, 16, 16, 8, float> sacc[8];
        #pragma unroll
        for (int n = 0; n < 8; n++) wmma::fill_fragment(sacc[n], 0.0f);
        #pragma unroll
        for (int kf = 0; kf < 16; kf++) {
            #pragma unroll
            for (int n = 0; n < 8; n++) {
                wmma::fragment<wmma::matrix_b, 16, 16, 8, wmma::precision::tf32, wmma::col_major> bk;
                wmma::load_matrix_sync(bk, &Ks[(n * 16) * 132 + kf * 8], 132);
                #pragma unroll
                for (int t = 0; t < bk.num_elements; t++)
                    bk.x[t] = wmma::__float_to_tf32(bk.x[t]);
                wmma::mma_sync(sacc[n], aq[kf], bk, sacc[n]);
            }
        }
        #pragma unroll
        for (int n = 0; n < 8; n++)
            wmma::store_matrix_sync(&Ss[(w * 16) * 132 + n * 16], sacc[n], 132, wmma::mem_row_major);
        __syncthreads();

        // online softmax update: 2 threads per row, 64 cols each
        {
            int r = tid >> 1;
            int l = tid & 1;
            int gr = m0 + r;
            int rowlim = gr + 1024;
            int jbase = kt * 128;
            float* srow = &Ss[r * 132 + l * 64];

            float mx = -1e30f;
            #pragma unroll 8
            for (int j = 0; j < 64; j++) {
                int jg = jbase + l * 64 + j;
                float val = srow[j] * scale;
                if (jg > rowlim || mrow[jg] == 0) val = -1e30f;
                srow[j] = val;
                mx = fmaxf(mx, val);
            }
            mx = fmaxf(mx, __shfl_xor_sync(0xffffffffu, mx, 1));
            float mold = Mi[r];
            float mnew = fmaxf(mold, mx);
            float ls = 0.0f;
            #pragma unroll 8
            for (int j = 0; j < 64; j++) {
                float p = __expf(srow[j] - mnew);
                srow[j] = p;
                ls += p;
            }
            ls += __shfl_xor_sync(0xffffffffu, ls, 1);
            if (mx > mold) {
                float alpha = __expf(mold - mnew);
                float* orow = &Os[r * 128 + l * 64];
                #pragma unroll 8
                for (int j = 0; j < 64; j++) orow[j] *= alpha;
                if (l == 0) { Li[r] = Li[r] * alpha + ls; Mi[r] = mnew; }
            } else {
                if (l == 0) Li[r] += ls;
            }
        }
        __syncthreads();

        // load V tile (overwrites Ks)
        #pragma unroll
        for (int i = tid; i < 128 * 32; i += 256) {
            int r = i >> 5, c4 = (i & 31) * 4;
            *(float4*)&Ks[r * 132 + c4] = *(const float4*)&vp[(size_t)(kt * 128 + r) * DD + c4];
        }
        __syncthreads();

        // PV: each warp computes its own 16x128 slab, accumulates into Os
        wmma::fragment<wmma::accumulator, 16, 16, 8, float> pv[8];
        #pragma unroll
        for (int n = 0; n < 8; n++) wmma::fill_fragment(pv[n], 0.0f);
        #pragma unroll
        for (int kf = 0; kf < 16; kf++) {
            wmma::fragment<wmma::matrix_a, 16, 16, 8, wmma::precision::tf32, wmma::row_major> ap;
            wmma::load_matrix_sync(ap, &Ss[(w * 16) * 132 + kf * 8], 132);
            #pragma unroll
            for (int t = 0; t < ap.num_elements; t++)
                ap.x[t] = wmma::__float_to_tf32(ap.x[t]);
            #pragma unroll
            for (int n = 0; n < 8; n++) {
                wmma::fragment<wmma::matrix_b, 16, 16, 8, wmma::precision::tf32, wmma::row_major> bv;
                wmma::load_matrix_sync(bv, &Ks[(kf * 8) * 132 + n * 16], 132);
                #pragma unroll
                for (int t = 0; t < bv.num_elements; t++)
                    bv.x[t] = wmma::__float_to_tf32(bv.x[t]);
                wmma::mma_sync(pv[n], ap, bv, pv[n]);
            }
        }
        // stash pv into own Ss slab (P already consumed by own warp), then Os += pv
        #pragma unroll
        for (int n = 0; n < 8; n++)
            wmma::store_matrix_sync(&Ss[(w * 16) * 132 + n * 16], pv[n], 132, wmma::mem_row_major);
        int lane = tid & 31;
        #pragma unroll
        for (int i = lane; i < 16 * 128; i += 32) {
            int rr = w * 16 + (i >> 7);
            int cc = i & 127;
            Os[rr * 128 + cc] += Ss[rr * 132 + cc];
        }
    }
    __syncthreads();

    // normalize + write
    #pragma unroll
    for (int i = tid; i < 128 * 128; i += 256) {
        int r = i >> 7, c = i & 127;
        g_attnout[((size_t)(b * NN + m0 + r)) * DIMM + h * DD + c] = Os[i] / Li[r];
    }
}

extern "C" void kernel_launch(void* const* d_in, const int* in_sizes, int n_in,
                              void* d_out, int out_size) {
    const float* x       = (const float*)d_in[0];
    const float* cache   = (const float*)d_in[1];
    const float* rotary  = (const float*)d_in[2];
    const int*   mask    = (const int*)d_in[3];
    const float* norm_w  = (const float*)d_in[4];
    const float* w_qkv   = (const float*)d_in[5];
    const float* w_out   = (const float*)d_in[6];

    float* out    = (float*)d_out;
    float* kv_out = out + (size_t)ROWS * DIMM;

    float *xn_ptr, *qkv_ptr, *ao_ptr;
    cudaGetSymbolAddress((void**)&xn_ptr, g_xn);
    cudaGetSymbolAddress((void**)&qkv_ptr, g_qkv);
    cudaGetSymbolAddress((void**)&ao_ptr, g_attnout);

    cudaFuncSetAttribute(attn_kernel, cudaFuncAttributeMaxDynamicSharedMemorySize, AT_SMEM_BYTES);

    rope_table_kernel<<<(JJ * DD) / 256, 256>>>(rotary);
    rmsnorm_kernel<<<ROWS, 256>>>(x, norm_w);

    dim3 grid_qkv(NQKV / 128, ROWS / 128);
    gemm_tf32_db<<<grid_qkv, 256>>>(xn_ptr, w_qkv, qkv_ptr, ROWS, NQKV, DIMM);

    scatter_rotary_kernel<<<(BB * HH * JJ * DD) / 256, 256>>>(cache, kv_out);

    attn_kernel<<<BB * HH * (NN / 128), 256, AT_SMEM_BYTES>>>(mask);

    dim3 grid_out(DIMM / 128, ROWS / 128);
    gemm_tf32_db<<<grid_out, 256>>>(ao_ptr, w_out, out, ROWS, DIMM, DIMM);
}

// round 7
// speedup vs baseline: 1.3649x; 1.0124x over previous
#include <cuda_runtime.h>
#include <cuda_bf16.h>
#include <mma.h>

using namespace nvcuda;

#define BB 4
#define NN 1024
#define JJ 2048
#define HH 16
#define DD 128
#define DIMM 2048
#define NQKV 6144
#define ROWS 4096

__device__ float g_xn[(size_t)ROWS * DIMM];
__device__ float g_qkv[(size_t)ROWS * NQKV];
__device__ float g_qrot[(size_t)BB * HH * NN * DD];
__device__ float g_krot[(size_t)BB * HH * JJ * DD];
__device__ float g_vfull[(size_t)BB * HH * JJ * DD];
__device__ float g_attnout[(size_t)ROWS * DIMM];
__device__ float g_cos[JJ * DD];
__device__ float g_sin[JJ * DD];

__device__ __forceinline__ void cpa16(void* smem, const void* gmem) {
    unsigned s = (unsigned)__cvta_generic_to_shared(smem);
    asm volatile("cp.async.cg.shared.global [%0], [%1], 16;\n" :: "r"(s), "l"(gmem));
}

__global__ void __launch_bounds__(256) rope_table_kernel(const float* __restrict__ rot) {
    int idx = blockIdx.x * 256 + threadIdx.x;
    float p = rot[idx];
    g_cos[idx] = cosf(p);
    g_sin[idx] = sinf(p);
}

__global__ void __launch_bounds__(256) rmsnorm_kernel(const float* __restrict__ x,
                                                      const float* __restrict__ w) {
    int row = blockIdx.x;
    int tid = threadIdx.x;
    const float* xr = x + (size_t)row * DIMM;
    float ss = 0.0f;
    #pragma unroll
    for (int i = tid * 4; i < DIMM; i += 1024) {
        float4 v = *(const float4*)(xr + i);
        ss += v.x * v.x + v.y * v.y + v.z * v.z + v.w * v.w;
    }
    #pragma unroll
    for (int o = 16; o; o >>= 1) ss += __shfl_xor_sync(0xffffffffu, ss, o);
    __shared__ float red[8];
    if ((tid & 31) == 0) red[tid >> 5] = ss;
    __syncthreads();
    float tot = 0.0f;
    #pragma unroll
    for (int i = 0; i < 8; i++) tot += red[i];
    float inv = rsqrtf(tot * (1.0f / (float)DIMM) + 1.1920929e-7f);
    for (int i = tid; i < DIMM; i += 256)
        g_xn[(size_t)row * DIMM + i] = xr[i] * inv * w[i];
}

// ---------------- multi-stage tf32 GEMM: block 128x256, warp 64x64, 3-stage cp.async ----------------
#define GS 3
#define ASZ (128 * 20)
#define BSZ (16 * 264)
#define G_SMEM_BYTES (GS * (ASZ + BSZ) * 4)

__global__ void __launch_bounds__(256, 1) gemm_tf32_mp(const float* __restrict__ A,
                                                       const float* __restrict__ B,
                                                       float* __restrict__ C,
                                                       int M, int N, int K) {
    extern __shared__ float gsm[];
    float* As = gsm;
    float* Bs = gsm + GS * ASZ;

    int tid = threadIdx.x;
    int n0 = blockIdx.x * 256;
    int m0 = blockIdx.y * 128;
    int w = tid >> 5;
    int wm = w >> 2;   // 0..1
    int wn = w & 3;    // 0..3

    wmma::fragment<wmma::accumulator, 16, 16, 8, float> acc[4][4];
    #pragma unroll
    for (int i = 0; i < 4; i++)
        #pragma unroll
        for (int j = 0; j < 4; j++) wmma::fill_fragment(acc[i][j], 0.0f);

    // A stage: 128 rows x 16 cols = 512 float4 (2/thread); B stage: 16 x 256 = 1024 float4 (4/thread)
    int ar0 = tid >> 2;            // +0, +64 via it
    int ac0 = (tid & 3) * 4;
    int br0 = tid >> 6;            // +0,4,8,12
    int bc0 = (tid & 63) * 4;

    #define LOAD_STAGE(st, kk)                                                        \
        {                                                                             \
            float* as_ = As + (st) * ASZ;                                             \
            float* bs_ = Bs + (st) * BSZ;                                             \
            cpa16(&as_[ar0 * 20 + ac0], &A[(size_t)(m0 + ar0) * K + (kk) + ac0]);     \
            cpa16(&as_[(ar0 + 64) * 20 + ac0],                                        \
                  &A[(size_t)(m0 + ar0 + 64) * K + (kk) + ac0]);                      \
            _Pragma("unroll")                                                         \
            for (int it = 0; it < 4; it++) {                                          \
                int r = br0 + it * 4;                                                 \
                cpa16(&bs_[r * 264 + bc0], &B[(size_t)((kk) + r) * N + n0 + bc0]);    \
            }                                                                         \
            asm volatile("cp.async.commit_group;\n");                                 \
        }

    LOAD_STAGE(0, 0);
    LOAD_STAGE(1, 16);

    int nk = K >> 4;
    for (int kt = 0; kt < nk; kt++) {
        asm volatile("cp.async.wait_group 1;\n");
        __syncthreads();

        if (kt + 2 < nk) {
            int st = (kt + 2) % GS;
            LOAD_STAGE(st, (kt + 2) << 4);
        }

        const float* as = As + (kt % GS) * ASZ;
        const float* bs = Bs + (kt % GS) * BSZ;

        #pragma unroll
        for (int kf = 0; kf < 2; kf++) {
            wmma::fragment<wmma::matrix_a, 16, 16, 8, wmma::precision::tf32, wmma::row_major> af[4];
            wmma::fragment<wmma::matrix_b, 16, 16, 8, wmma::precision::tf32, wmma::row_major> bf[4];
            #pragma unroll
            for (int i = 0; i < 4; i++) {
                wmma::load_matrix_sync(af[i], &as[(wm * 64 + i * 16) * 20 + kf * 8], 20);
                #pragma unroll
                for (int t = 0; t < af[i].num_elements; t++)
                    af[i].x[t] = wmma::__float_to_tf32(af[i].x[t]);
            }
            #pragma unroll
            for (int j = 0; j < 4; j++) {
                wmma::load_matrix_sync(bf[j], &bs[(kf * 8) * 264 + wn * 64 + j * 16], 264);
                #pragma unroll
                for (int t = 0; t < bf[j].num_elements; t++)
                    bf[j].x[t] = wmma::__float_to_tf32(bf[j].x[t]);
            }
            #pragma unroll
            for (int i = 0; i < 4; i++)
                #pragma unroll
                for (int j = 0; j < 4; j++)
                    wmma::mma_sync(acc[i][j], af[i], bf[j], acc[i][j]);
        }
    }

    #pragma unroll
    for (int i = 0; i < 4; i++)
        #pragma unroll
        for (int j = 0; j < 4; j++)
            wmma::store_matrix_sync(&C[(size_t)(m0 + wm * 64 + i * 16) * N + n0 + wn * 64 + j * 16],
                                    acc[i][j], N, wmma::mem_row_major);
}

__global__ void __launch_bounds__(256) scatter_rotary_kernel(const float* __restrict__ cache,
                                                             float* __restrict__ kv_out) {
    int idx = blockIdx.x * 256 + threadIdx.x;
    int dd = idx & 127;
    int j  = (idx >> 7) & 2047;
    int h  = (idx >> 18) & 15;
    int b  = idx >> 22;

    float c = g_cos[j * DD + dd];
    float s = g_sin[j * DD + dd];
    int pd = (dd < 64) ? dd + 64 : dd - 64;
    float sgn = (dd < 64) ? -1.0f : 1.0f;

    float kvl, kpart, vv;
    if (j < 1024) {
        const float* ckb = cache + (((size_t)(b * 2 + 0) * HH + h) * 1024 + j) * DD;
        const float* cvb = cache + (((size_t)(b * 2 + 1) * HH + h) * 1024 + j) * DD;
        kvl = ckb[dd];
        kpart = ckb[pd];
        vv = cvb[dd];
    } else {
        int rrow = b * NN + (j - 1024);
        const float* qr = g_qkv + (size_t)rrow * NQKV;
        kvl   = qr[2048 + h * DD + dd];
        kpart = qr[2048 + h * DD + pd];
        vv    = qr[4096 + h * DD + dd];
        float ql = qr[h * DD + dd];
        float qp = qr[h * DD + pd];
        g_qrot[(((size_t)(b * HH + h) * NN + (j - 1024)) * DD) + dd] = ql * c + sgn * qp * s;
    }

    size_t kvidx = ((size_t)(b * HH + h) * JJ + j) * DD + dd;
    g_krot[kvidx]  = kvl * c + sgn * kpart * s;
    g_vfull[kvidx] = vv;

    kv_out[(((size_t)(b * 2 + 0) * HH + h) * JJ + j) * DD + dd] = kvl;
    kv_out[(((size_t)(b * 2 + 1) * HH + h) * JJ + j) * DD + dd] = vv;
}

// ---------------- flash attention: 128-query blocks, online softmax ----------------
#define AT_SMEM_FLOATS (128 * 132 * 2 + 128 * 128 + 256)
#define AT_SMEM_BYTES (AT_SMEM_FLOATS * 4)

__global__ void __launch_bounds__(256) attn_kernel(const int* __restrict__ mask) {
    extern __shared__ float sm[];
    float* Ks = sm;
    float* Ss = sm + 128 * 132;
    float* Os = sm + 2 * 128 * 132;
    float* Mi = Os + 128 * 128;
    float* Li = Mi + 128;

    int tid = threadIdx.x;
    int w = tid >> 5;
    int bid = blockIdx.x;
    int b  = bid & 3;
    int h  = (bid >> 2) & 15;
    int qb = 7 - (bid >> 6);
    int m0 = qb * 128;

    const float* qp = g_qrot + ((size_t)(b * HH + h) * NN + m0) * DD;
    const float* kp = g_krot + (size_t)(b * HH + h) * JJ * DD;
    const float* vp = g_vfull + (size_t)(b * HH + h) * JJ * DD;
    const int* mrow = mask + (size_t)b * JJ;

    #pragma unroll
    for (int i = tid; i < 128 * 32; i += 256) {
        int r = i >> 5, c4 = (i & 31) * 4;
        *(float4*)&Ss[r * 132 + c4] = *(const float4*)&qp[(size_t)r * DD + c4];
    }
    __syncthreads();

    wmma::fragment<wmma::matrix_a, 16, 16, 8, wmma::precision::tf32, wmma::row_major> aq[16];
    #pragma unroll
    for (int kf = 0; kf < 16; kf++) {
        wmma::load_matrix_sync(aq[kf], &Ss[(w * 16) * 132 + kf * 8], 132);
        #pragma unroll
        for (int t = 0; t < aq[kf].num_elements; t++)
            aq[kf].x[t] = wmma::__float_to_tf32(aq[kf].x[t]);
    }

    #pragma unroll
    for (int i = tid; i < 128 * 128; i += 256) Os[i] = 0.0f;
    if (tid < 128) { Mi[tid] = -1e30f; Li[tid] = 0.0f; }

    int nt = qb + 9;
    const float scale = 0.08838834764831845f;

    for (int kt = 0; kt < nt; kt++) {
        __syncthreads();

        #pragma unroll
        for (int i = tid; i < 128 * 32; i += 256) {
            int r = i >> 5, c4 = (i & 31) * 4;
            *(float4*)&Ks[r * 132 + c4] = *(const float4*)&kp[(size_t)(kt * 128 + r) * DD + c4];
        }
        __syncthreads();

        wmma::fragment<wmma::accumulator, 16, 16, 8, float> sacc[8];
        #pragma unroll
        for (int n = 0; n < 8; n++) wmma::fill_fragment(sacc[n], 0.0f);
        #pragma unroll
        for (int kf = 0; kf < 16; kf++) {
            #pragma unroll
            for (int n = 0; n < 8; n++) {
                wmma::fragment<wmma::matrix_b, 16, 16, 8, wmma::precision::tf32, wmma::col_major> bk;
                wmma::load_matrix_sync(bk, &Ks[(n * 16) * 132 + kf * 8], 132);
                #pragma unroll
                for (int t = 0; t < bk.num_elements; t++)
                    bk.x[t] = wmma::__float_to_tf32(bk.x[t]);
                wmma::mma_sync(sacc[n], aq[kf], bk, sacc[n]);
            }
        }
        #pragma unroll
        for (int n = 0; n < 8; n++)
            wmma::store_matrix_sync(&Ss[(w * 16) * 132 + n * 16], sacc[n], 132, wmma::mem_row_major);
        __syncthreads();

        {
            int r = tid >> 1;
            int l = tid & 1;
            int gr = m0 + r;
            int rowlim = gr + 1024;
            int jbase = kt * 128;
            float* srow = &Ss[r * 132 + l * 64];

            float mx = -1e30f;
            #pragma unroll 8
            for (int j = 0; j < 64; j++) {
                int jg = jbase + l * 64 + j;
                float val = srow[j] * scale;
                if (jg > rowlim || mrow[jg] == 0) val = -1e30f;
                srow[j] = val;
                mx = fmaxf(mx, val);
            }
            mx = fmaxf(mx, __shfl_xor_sync(0xffffffffu, mx, 1));
            float mold = Mi[r];
            float mnew = fmaxf(mold, mx);
            float ls = 0.0f;
            #pragma unroll 8
            for (int j = 0; j < 64; j++) {
                float p = __expf(srow[j] - mnew);
                srow[j] = p;
                ls += p;
            }
            ls += __shfl_xor_sync(0xffffffffu, ls, 1);
            if (mx > mold) {
                float alpha = __expf(mold - mnew);
                float* orow = &Os[r * 128 + l * 64];
                #pragma unroll 8
                for (int j = 0; j < 64; j++) orow[j] *= alpha;
                if (l == 0) { Li[r] = Li[r] * alpha + ls; Mi[r] = mnew; }
            } else {
                if (l == 0) Li[r] += ls;
            }
        }
        __syncthreads();

        #pragma unroll
        for (int i = tid; i < 128 * 32; i += 256) {
            int r = i >> 5, c4 = (i & 31) * 4;
            *(float4*)&Ks[r * 132 + c4] = *(const float4*)&vp[(size_t)(kt * 128 + r) * DD + c4];
        }
        __syncthreads();

        wmma::fragment<wmma::accumulator, 16, 16, 8, float> pv[8];
        #pragma unroll
        for (int n = 0; n < 8; n++) wmma::fill_fragment(pv[n], 0.0f);
        #pragma unroll
        for (int kf = 0; kf < 16; kf++) {
            wmma::fragment<wmma::matrix_a, 16, 16, 8, wmma::precision::tf32, wmma::row_major> ap;
            wmma::load_matrix_sync(ap, &Ss[(w * 16) * 132 + kf * 8], 132);
            #pragma unroll
            for (int t = 0; t < ap.num_elements; t++)
                ap.x[t] = wmma::__float_to_tf32(ap.x[t]);
            #pragma unroll
            for (int n = 0; n < 8; n++) {
                wmma::fragment<wmma::matrix_b, 16, 16, 8, wmma::precision::tf32, wmma::row_major> bv;
                wmma::load_matrix_sync(bv, &Ks[(kf * 8) * 132 + n * 16], 132);
                #pragma unroll
                for (int t = 0; t < bv.num_elements; t++)
                    bv.x[t] = wmma::__float_to_tf32(bv.x[t]);
                wmma::mma_sync(pv[n], ap, bv, pv[n]);
            }
        }
        #pragma unroll
        for (int n = 0; n < 8; n++)
            wmma::store_matrix_sync(&Ss[(w * 16) * 132 + n * 16], pv[n], 132, wmma::mem_row_major);
        int lane = tid & 31;
        #pragma unroll
        for (int i = lane; i < 16 * 128; i += 32) {
            int rr = w * 16 + (i >> 7);
            int cc = i & 127;
            Os[rr * 128 + cc] += Ss[rr * 132 + cc];
        }
    }
    __syncthreads();

    #pragma unroll
    for (int i = tid; i < 128 * 128; i += 256) {
        int r = i >> 7, c = i & 127;
        g_attnout[((size_t)(b * NN + m0 + r)) * DIMM + h * DD + c] = Os[i] / Li[r];
    }
}

extern "C" void kernel_launch(void* const* d_in, const int* in_sizes, int n_in,
                              void* d_out, int out_size) {
    const float* x       = (const float*)d_in[0];
    const float* cache   = (const float*)d_in[1];
    const float* rotary  = (const float*)d_in[2];
    const int*   mask    = (const int*)d_in[3];
    const float* norm_w  = (const float*)d_in[4];
    const float* w_qkv   = (const float*)d_in[5];
    const float* w_out   = (const float*)d_in[6];

    float* out    = (float*)d_out;
    float* kv_out = out + (size_t)ROWS * DIMM;

    float *xn_ptr, *qkv_ptr, *ao_ptr;
    cudaGetSymbolAddress((void**)&xn_ptr, g_xn);
    cudaGetSymbolAddress((void**)&qkv_ptr, g_qkv);
    cudaGetSymbolAddress((void**)&ao_ptr, g_attnout);

    cudaFuncSetAttribute(attn_kernel, cudaFuncAttributeMaxDynamicSharedMemorySize, AT_SMEM_BYTES);
    cudaFuncSetAttribute(gemm_tf32_mp, cudaFuncAttributeMaxDynamicSharedMemorySize, G_SMEM_BYTES);

    rope_table_kernel<<<(JJ * DD) / 256, 256>>>(rotary);
    rmsnorm_kernel<<<ROWS, 256>>>(x, norm_w);

    dim3 grid_qkv(NQKV / 256, ROWS / 128);
    gemm_tf32_mp<<<grid_qkv, 256, G_SMEM_BYTES>>>(xn_ptr, w_qkv, qkv_ptr, ROWS, NQKV, DIMM);

    scatter_rotary_kernel<<<(BB * HH * JJ * DD) / 256, 256>>>(cache, kv_out);

    attn_kernel<<<BB * HH * (NN / 128), 256, AT_SMEM_BYTES>>>(mask);

    dim3 grid_out(DIMM / 256, ROWS / 128);
    gemm_tf32_mp<<<grid_out, 256, G_SMEM_BYTES>>>(ao_ptr, w_out, out, ROWS, DIMM, DIMM);
}

// round 9
// speedup vs baseline: 3.8967x; 2.8550x over previous
#include <cuda_runtime.h>
#include <cuda_fp16.h>
#include <mma.h>
#include <cstdint>

using namespace nvcuda;

#define BB 4
#define NN 1024
#define JJ 2048
#define HH 16
#define DD 128
#define DIMM 2048
#define NQKV 6144
#define ROWS 4096

__device__ __half g_xn[(size_t)ROWS * DIMM];
__device__ float  g_qkv[(size_t)ROWS * NQKV];
__device__ __half g_qrot[(size_t)BB * HH * NN * DD];
__device__ __half g_krot[(size_t)BB * HH * JJ * DD];
__device__ __half g_vfull[(size_t)BB * HH * JJ * DD];
__device__ __half g_attnout[(size_t)ROWS * DIMM];
__device__ __half g_wqkv_h[(size_t)DIMM * NQKV];
__device__ __half g_wout_h[(size_t)DIMM * DIMM];
__device__ float  g_cos[JJ * DD];
__device__ float  g_sin[JJ * DD];

__device__ __forceinline__ void cpa16(void* smem, const void* gmem) {
    unsigned s = (unsigned)__cvta_generic_to_shared(smem);
    asm volatile("cp.async.cg.shared.global [%0], [%1], 16;\n" :: "r"(s), "l"(gmem));
}

// ---------------- small kernels ----------------
__global__ void __launch_bounds__(256) rope_table_kernel(const float* __restrict__ rot) {
    int idx = blockIdx.x * 256 + threadIdx.x;
    float p = rot[idx];
    g_cos[idx] = cosf(p);
    g_sin[idx] = sinf(p);
}

__global__ void __launch_bounds__(256) convert_h_kernel(const float* __restrict__ in,
                                                        __half* __restrict__ out, int n) {
    int idx = (blockIdx.x * 256 + threadIdx.x) * 4;
    if (idx < n) {
        float4 v = *(const float4*)(in + idx);
        __half2 a = __floats2half2_rn(v.x, v.y);
        __half2 b = __floats2half2_rn(v.z, v.w);
        *(__half2*)(out + idx)     = a;
        *(__half2*)(out + idx + 2) = b;
    }
}

__global__ void __launch_bounds__(256) rmsnorm_kernel(const float* __restrict__ x,
                                                      const float* __restrict__ w) {
    int row = blockIdx.x;
    int tid = threadIdx.x;
    const float* xr = x + (size_t)row * DIMM;
    float ss = 0.0f;
    #pragma unroll
    for (int i = tid * 4; i < DIMM; i += 1024) {
        float4 v = *(const float4*)(xr + i);
        ss += v.x * v.x + v.y * v.y + v.z * v.z + v.w * v.w;
    }
    #pragma unroll
    for (int o = 16; o; o >>= 1) ss += __shfl_xor_sync(0xffffffffu, ss, o);
    __shared__ float red[8];
    if ((tid & 31) == 0) red[tid >> 5] = ss;
    __syncthreads();
    float tot = 0.0f;
    #pragma unroll
    for (int i = 0; i < 8; i++) tot += red[i];
    float inv = rsqrtf(tot * (1.0f / (float)DIMM) + 1.1920929e-7f);
    for (int i = tid * 2; i < DIMM; i += 512) {
        float2 v = *(const float2*)(xr + i);
        *(__half2*)&g_xn[(size_t)row * DIMM + i] =
            __floats2half2_rn(v.x * inv * w[i], v.y * inv * w[i + 1]);
    }
}

// ---------------- fp16 GEMM: block 128x256, warp 64x64, KSTEP 32, 3-stage cp.async ----------------
#define GS 3
#define A_LD 40
#define B_LD 264
#define ASZ (128 * A_LD)          // halves
#define BSZ (32 * B_LD)           // halves
#define G_SMEM_BYTES (GS * (ASZ + BSZ) * 2)

__global__ void __launch_bounds__(256, 1) gemm_hp(const __half* __restrict__ A,
                                                  const __half* __restrict__ B,
                                                  float* __restrict__ C,
                                                  int M, int N, int K) {
    extern __shared__ __half hsm[];
    __half* As = hsm;
    __half* Bs = hsm + GS * ASZ;

    int tid = threadIdx.x;
    int n0 = blockIdx.x * 256;
    int m0 = blockIdx.y * 128;
    int w = tid >> 5;
    int wm = w >> 2;   // 0..1
    int wn = w & 3;    // 0..3

    wmma::fragment<wmma::accumulator, 16, 16, 16, float> acc[4][4];
    #pragma unroll
    for (int i = 0; i < 4; i++)
        #pragma unroll
        for (int j = 0; j < 4; j++) wmma::fill_fragment(acc[i][j], 0.0f);

    #define LOAD_STAGE(st, kk)                                                          \
        {                                                                               \
            __half* as_ = As + (st) * ASZ;                                              \
            __half* bs_ = Bs + (st) * BSZ;                                              \
            _Pragma("unroll")                                                           \
            for (int i = 0; i < 2; i++) {                                               \
                int c = tid + 256 * i;                                                  \
                int r = c >> 2, c8 = (c & 3) * 8;                                       \
                cpa16(&as_[r * A_LD + c8], &A[(size_t)(m0 + r) * K + (kk) + c8]);       \
            }                                                                           \
            _Pragma("unroll")                                                           \
            for (int i = 0; i < 4; i++) {                                               \
                int c = tid + 256 * i;                                                  \
                int r = c >> 5, c8 = (c & 31) * 8;                                      \
                cpa16(&bs_[r * B_LD + c8], &B[(size_t)((kk) + r) * N + n0 + c8]);       \
            }                                                                           \
            asm volatile("cp.async.commit_group;\n");                                   \
        }

    LOAD_STAGE(0, 0);
    LOAD_STAGE(1, 32);

    int nk = K >> 5;
    for (int kt = 0; kt < nk; kt++) {
        asm volatile("cp.async.wait_group 1;\n");
        __syncthreads();

        if (kt + 2 < nk) {
            int st = (kt + 2) % GS;
            LOAD_STAGE(st, (kt + 2) << 5);
        }

        const __half* as = As + (kt % GS) * ASZ;
        const __half* bs = Bs + (kt % GS) * BSZ;

        #pragma unroll
        for (int kf = 0; kf < 2; kf++) {
            wmma::fragment<wmma::matrix_a, 16, 16, 16, __half, wmma::row_major> af[4];
            wmma::fragment<wmma::matrix_b, 16, 16, 16, __half, wmma::row_major> bf[4];
            #pragma unroll
            for (int i = 0; i < 4; i++)
                wmma::load_matrix_sync(af[i], &as[(wm * 64 + i * 16) * A_LD + kf * 16], A_LD);
            #pragma unroll
            for (int j = 0; j < 4; j++)
                wmma::load_matrix_sync(bf[j], &bs[(kf * 16) * B_LD + wn * 64 + j * 16], B_LD);
            #pragma unroll
            for (int i = 0; i < 4; i++)
                #pragma unroll
                for (int j = 0; j < 4; j++)
                    wmma::mma_sync(acc[i][j], af[i], bf[j], acc[i][j]);
        }
        __syncthreads();
    }

    #pragma unroll
    for (int i = 0; i < 4; i++)
        #pragma unroll
        for (int j = 0; j < 4; j++)
            wmma::store_matrix_sync(&C[(size_t)(m0 + wm * 64 + i * 16) * N + n0 + wn * 64 + j * 16],
                                    acc[i][j], N, wmma::mem_row_major);
}

// ---------------- scatter + rotary ----------------
__global__ void __launch_bounds__(256) scatter_rotary_kernel(const float* __restrict__ cache,
                                                             float* __restrict__ kv_out) {
    int idx = blockIdx.x * 256 + threadIdx.x;
    int dd = idx & 127;
    int j  = (idx >> 7) & 2047;
    int h  = (idx >> 18) & 15;
    int b  = idx >> 22;

    float c = g_cos[j * DD + dd];
    float s = g_sin[j * DD + dd];
    int pd = (dd < 64) ? dd + 64 : dd - 64;
    float sgn = (dd < 64) ? -1.0f : 1.0f;

    float kvl, kpart, vv;
    if (j < 1024) {
        const float* ckb = cache + (((size_t)(b * 2 + 0) * HH + h) * 1024 + j) * DD;
        const float* cvb = cache + (((size_t)(b * 2 + 1) * HH + h) * 1024 + j) * DD;
        kvl = ckb[dd];
        kpart = ckb[pd];
        vv = cvb[dd];
    } else {
        int rrow = b * NN + (j - 1024);
        const float* qr = g_qkv + (size_t)rrow * NQKV;
        kvl   = qr[2048 + h * DD + dd];
        kpart = qr[2048 + h * DD + pd];
        vv    = qr[4096 + h * DD + dd];
        float ql = qr[h * DD + dd];
        float qp = qr[h * DD + pd];
        g_qrot[(((size_t)(b * HH + h) * NN + (j - 1024)) * DD) + dd] =
            __float2half_rn(ql * c + sgn * qp * s);
    }

    size_t kvidx = ((size_t)(b * HH + h) * JJ + j) * DD + dd;
    g_krot[kvidx]  = __float2half_rn(kvl * c + sgn * kpart * s);
    g_vfull[kvidx] = __float2half_rn(vv);

    kv_out[(((size_t)(b * 2 + 0) * HH + h) * JJ + j) * DD + dd] = kvl;
    kv_out[(((size_t)(b * 2 + 1) * HH + h) * JJ + j) * DD + dd] = vv;
}

// ---------------- flash attention (fp16 wmma) ----------------
// smem: Ks half[128*136] | Ph half[128*136] (Q first, then P) | Ss f32[128*132] | Os f32[128*128] | Mi,Li
#define KS_H (128 * 136)
#define AT_SMEM_BYTES (KS_H * 2 * 2 + (128 * 132 + 128 * 128 + 256) * 4)

__global__ void __launch_bounds__(256) attn_kernel(const int* __restrict__ mask) {
    extern __shared__ char asm_raw[];
    __half* Ks = (__half*)asm_raw;
    __half* Ph = Ks + KS_H;
    float*  Ss = (float*)(Ph + KS_H);
    float*  Os = Ss + 128 * 132;
    float*  Mi = Os + 128 * 128;
    float*  Li = Mi + 128;

    int tid = threadIdx.x;
    int w = tid >> 5;
    int bid = blockIdx.x;
    int b  = bid & 3;
    int h  = (bid >> 2) & 15;
    int qb = 7 - (bid >> 6);
    int m0 = qb * 128;

    const __half* qp = g_qrot + ((size_t)(b * HH + h) * NN + m0) * DD;
    const __half* kp = g_krot + (size_t)(b * HH + h) * JJ * DD;
    const __half* vp = g_vfull + (size_t)(b * HH + h) * JJ * DD;
    const int* mrow = mask + (size_t)b * JJ;

    // load Q into Ph (temp), build per-warp A fragments
    #pragma unroll
    for (int i = tid; i < 128 * 16; i += 256) {
        int r = i >> 4, c8 = (i & 15) * 8;
        *(float4*)&Ph[r * 136 + c8] = *(const float4*)&qp[(size_t)r * DD + c8];
    }
    __syncthreads();

    wmma::fragment<wmma::matrix_a, 16, 16, 16, __half, wmma::row_major> aq[8];
    #pragma unroll
    for (int kf = 0; kf < 8; kf++)
        wmma::load_matrix_sync(aq[kf], &Ph[(w * 16) * 136 + kf * 16], 136);

    #pragma unroll
    for (int i = tid; i < 128 * 128; i += 256) Os[i] = 0.0f;
    if (tid < 128) { Mi[tid] = -1e30f; Li[tid] = 0.0f; }

    int nt = qb + 9;
    const float scale = 0.08838834764831845f;

    for (int kt = 0; kt < nt; kt++) {
        __syncthreads();

        #pragma unroll
        for (int i = tid; i < 128 * 16; i += 256) {
            int r = i >> 4, c8 = (i & 15) * 8;
            *(float4*)&Ks[r * 136 + c8] = *(const float4*)&kp[(size_t)(kt * 128 + r) * DD + c8];
        }
        __syncthreads();

        // S = Q K^T
        wmma::fragment<wmma::accumulator, 16, 16, 16, float> sacc[8];
        #pragma unroll
        for (int n = 0; n < 8; n++) wmma::fill_fragment(sacc[n], 0.0f);
        #pragma unroll
        for (int kf = 0; kf < 8; kf++) {
            #pragma unroll
            for (int n = 0; n < 8; n++) {
                wmma::fragment<wmma::matrix_b, 16, 16, 16, __half, wmma::col_major> bk;
                wmma::load_matrix_sync(bk, &Ks[(n * 16) * 136 + kf * 16], 136);
                wmma::mma_sync(sacc[n], aq[kf], bk, sacc[n]);
            }
        }
        #pragma unroll
        for (int n = 0; n < 8; n++)
            wmma::store_matrix_sync(&Ss[(w * 16) * 132 + n * 16], sacc[n], 132, wmma::mem_row_major);
        __syncthreads();

        // online softmax: 2 threads/row; write P as half into Ph
        {
            int r = tid >> 1;
            int l = tid & 1;
            int gr = m0 + r;
            int rowlim = gr + 1024;
            int jbase = kt * 128;
            float* srow = &Ss[r * 132 + l * 64];
            __half* prow = &Ph[r * 136 + l * 64];

            float mx = -1e30f;
            #pragma unroll 8
            for (int j = 0; j < 64; j++) {
                int jg = jbase + l * 64 + j;
                float val = srow[j] * scale;
                if (jg > rowlim || mrow[jg] == 0) val = -1e30f;
                srow[j] = val;
                mx = fmaxf(mx, val);
            }
            mx = fmaxf(mx, __shfl_xor_sync(0xffffffffu, mx, 1));
            float mold = Mi[r];
            float mnew = fmaxf(mold, mx);
            float ls = 0.0f;
            #pragma unroll 4
            for (int j = 0; j < 64; j += 2) {
                float p0 = __expf(srow[j] - mnew);
                float p1 = __expf(srow[j + 1] - mnew);
                ls += p0 + p1;
                *(__half2*)&prow[j] = __floats2half2_rn(p0, p1);
            }
            ls += __shfl_xor_sync(0xffffffffu, ls, 1);
            if (mx > mold) {
                float alpha = __expf(mold - mnew);
                float* orow = &Os[r * 128 + l * 64];
                #pragma unroll 8
                for (int j = 0; j < 64; j++) orow[j] *= alpha;
                if (l == 0) { Li[r] = Li[r] * alpha + ls; Mi[r] = mnew; }
            } else {
                if (l == 0) Li[r] += ls;
            }
        }
        __syncthreads();

        // load V (overwrites Ks)
        #pragma unroll
        for (int i = tid; i < 128 * 16; i += 256) {
            int r = i >> 4, c8 = (i & 15) * 8;
            *(float4*)&Ks[r * 136 + c8] = *(const float4*)&vp[(size_t)(kt * 128 + r) * DD + c8];
        }
        __syncthreads();

        // PV
        wmma::fragment<wmma::accumulator, 16, 16, 16, float> pv[8];
        #pragma unroll
        for (int n = 0; n < 8; n++) wmma::fill_fragment(pv[n], 0.0f);
        #pragma unroll
        for (int kf = 0; kf < 8; kf++) {
            wmma::fragment<wmma::matrix_a, 16, 16, 16, __half, wmma::row_major> ap;
            wmma::load_matrix_sync(ap, &Ph[(w * 16) * 136 + kf * 16], 136);
            #pragma unroll
            for (int n = 0; n < 8; n++) {
                wmma::fragment<wmma::matrix_b, 16, 16, 16, __half, wmma::row_major> bv;
                wmma::load_matrix_sync(bv, &Ks[(kf * 16) * 136 + n * 16], 136);
                wmma::mma_sync(pv[n], ap, bv, pv[n]);
            }
        }
        #pragma unroll
        for (int n = 0; n < 8; n++)
            wmma::store_matrix_sync(&Ss[(w * 16) * 132 + n * 16], pv[n], 132, wmma::mem_row_major);
        int lane = tid & 31;
        #pragma unroll
        for (int i = lane; i < 16 * 128; i += 32) {
            int rr = w * 16 + (i >> 7);
            int cc = i & 127;
            Os[rr * 128 + cc] += Ss[rr * 132 + cc];
        }
    }
    __syncthreads();

    #pragma unroll
    for (int i = tid; i < 128 * 128; i += 256) {
        int r = i >> 7, c = i & 127;
        g_attnout[((size_t)(b * NN + m0 + r)) * DIMM + h * DD + c] =
            __float2half_rn(Os[i] / Li[r]);
    }
}

// ---------------- launch ----------------
extern "C" void kernel_launch(void* const* d_in, const int* in_sizes, int n_in,
                              void* d_out, int out_size) {
    const float* x       = (const float*)d_in[0];
    const float* cache   = (const float*)d_in[1];
    const float* rotary  = (const float*)d_in[2];
    const int*   mask    = (const int*)d_in[3];
    const float* norm_w  = (const float*)d_in[4];
    const float* w_qkv   = (const float*)d_in[5];
    const float* w_out   = (const float*)d_in[6];

    float* out    = (float*)d_out;
    float* kv_out = out + (size_t)ROWS * DIMM;

    __half *xn_ptr, *wqkv_ptr, *wout_ptr, *ao_ptr;
    float *qkv_ptr;
    cudaGetSymbolAddress((void**)&xn_ptr, g_xn);
    cudaGetSymbolAddress((void**)&qkv_ptr, g_qkv);
    cudaGetSymbolAddress((void**)&ao_ptr, g_attnout);
    cudaGetSymbolAddress((void**)&wqkv_ptr, g_wqkv_h);
    cudaGetSymbolAddress((void**)&wout_ptr, g_wout_h);

    cudaFuncSetAttribute(attn_kernel, cudaFuncAttributeMaxDynamicSharedMemorySize, AT_SMEM_BYTES);
    cudaFuncSetAttribute(gemm_hp, cudaFuncAttributeMaxDynamicSharedMemorySize, G_SMEM_BYTES);

    convert_h_kernel<<<(DIMM * NQKV / 4 + 255) / 256, 256>>>(w_qkv, wqkv_ptr, DIMM * NQKV);
    convert_h_kernel<<<(DIMM * DIMM / 4 + 255) / 256, 256>>>(w_out, wout_ptr, DIMM * DIMM);

    rope_table_kernel<<<(JJ * DD) / 256, 256>>>(rotary);
    rmsnorm_kernel<<<ROWS, 256>>>(x, norm_w);

    gemm_hp<<<dim3(NQKV / 256, ROWS / 128), 256, G_SMEM_BYTES>>>(xn_ptr, wqkv_ptr, qkv_ptr,
                                                                 ROWS, NQKV, DIMM);

    scatter_rotary_kernel<<<(BB * HH * JJ * DD) / 256, 256>>>(cache, kv_out);

    attn_kernel<<<BB * HH * (NN / 128), 256, AT_SMEM_BYTES>>>(mask);

    gemm_hp<<<dim3(DIMM / 256, ROWS / 128), 256, G_SMEM_BYTES>>>(ao_ptr, wout_ptr, out,
                                                                 ROWS, DIMM, DIMM);
}

// round 10
// speedup vs baseline: 5.1787x; 1.3290x over previous
#include <cuda_runtime.h>
#include <cuda_fp16.h>
#include <mma.h>
#include <cstdint>

using namespace nvcuda;

#define BB 4
#define NN 1024
#define JJ 2048
#define HH 16
#define DD 128
#define DIMM 2048
#define NQKV 6144
#define ROWS 4096

__device__ __half g_xn[(size_t)ROWS * DIMM];
__device__ float  g_qkv[(size_t)ROWS * NQKV];
__device__ __half g_qrot[(size_t)BB * HH * NN * DD];
__device__ __half g_krot[(size_t)BB * HH * JJ * DD];
__device__ __half g_vfull[(size_t)BB * HH * JJ * DD];
__device__ __half g_attnout[(size_t)ROWS * DIMM];
__device__ __half g_wqkv_h[(size_t)DIMM * NQKV];
__device__ __half g_wout_h[(size_t)DIMM * DIMM];
__device__ float  g_cos[JJ * DD];
__device__ float  g_sin[JJ * DD];

__device__ __forceinline__ void cpa16(void* smem, const void* gmem) {
    unsigned s = (unsigned)__cvta_generic_to_shared(smem);
    asm volatile("cp.async.cg.shared.global [%0], [%1], 16;\n" :: "r"(s), "l"(gmem));
}

__device__ __forceinline__ void mma16816(float* c, const uint32_t* a, uint32_t b0, uint32_t b1) {
    asm volatile(
        "mma.sync.aligned.m16n8k16.row.col.f32.f16.f16.f32 "
        "{%0,%1,%2,%3}, {%4,%5,%6,%7}, {%8,%9}, {%0,%1,%2,%3};"
        : "+f"(c[0]), "+f"(c[1]), "+f"(c[2]), "+f"(c[3])
        : "r"(a[0]), "r"(a[1]), "r"(a[2]), "r"(a[3]), "r"(b0), "r"(b1));
}

__device__ __forceinline__ uint32_t f2h2(float x, float y) {
    __half2 h = __floats2half2_rn(x, y);
    return *(uint32_t*)&h;
}

// ---------------- small kernels ----------------
__global__ void __launch_bounds__(256) rope_table_kernel(const float* __restrict__ rot) {
    int idx = blockIdx.x * 256 + threadIdx.x;
    float p = rot[idx];
    g_cos[idx] = cosf(p);
    g_sin[idx] = sinf(p);
}

__global__ void __launch_bounds__(256) convert_h_kernel(const float* __restrict__ in,
                                                        __half* __restrict__ out, int n) {
    int idx = (blockIdx.x * 256 + threadIdx.x) * 4;
    if (idx < n) {
        float4 v = *(const float4*)(in + idx);
        *(__half2*)(out + idx)     = __floats2half2_rn(v.x, v.y);
        *(__half2*)(out + idx + 2) = __floats2half2_rn(v.z, v.w);
    }
}

__global__ void __launch_bounds__(256) rmsnorm_kernel(const float* __restrict__ x,
                                                      const float* __restrict__ w) {
    int row = blockIdx.x;
    int tid = threadIdx.x;
    const float* xr = x + (size_t)row * DIMM;
    float ss = 0.0f;
    #pragma unroll
    for (int i = tid * 4; i < DIMM; i += 1024) {
        float4 v = *(const float4*)(xr + i);
        ss += v.x * v.x + v.y * v.y + v.z * v.z + v.w * v.w;
    }
    #pragma unroll
    for (int o = 16; o; o >>= 1) ss += __shfl_xor_sync(0xffffffffu, ss, o);
    __shared__ float red[8];
    if ((tid & 31) == 0) red[tid >> 5] = ss;
    __syncthreads();
    float tot = 0.0f;
    #pragma unroll
    for (int i = 0; i < 8; i++) tot += red[i];
    float inv = rsqrtf(tot * (1.0f / (float)DIMM) + 1.1920929e-7f);
    for (int i = tid * 2; i < DIMM; i += 512) {
        float2 v = *(const float2*)(xr + i);
        *(__half2*)&g_xn[(size_t)row * DIMM + i] =
            __floats2half2_rn(v.x * inv * w[i], v.y * inv * w[i + 1]);
    }
}

// ---------------- fp16 GEMM: block 128x256, warp 64x64, 4-stage cp.async ----------------
#define GS 4
#define A_LD 40
#define B_LD 264
#define ASZ (128 * A_LD)
#define BSZ (32 * B_LD)
#define G_SMEM_BYTES (GS * (ASZ + BSZ) * 2)

__global__ void __launch_bounds__(256, 1) gemm_hp(const __half* __restrict__ A,
                                                  const __half* __restrict__ B,
                                                  float* __restrict__ C,
                                                  int M, int N, int K) {
    extern __shared__ __half hsm[];
    __half* As = hsm;
    __half* Bs = hsm + GS * ASZ;

    int tid = threadIdx.x;
    int n0 = blockIdx.x * 256;
    int m0 = blockIdx.y * 128;
    int w = tid >> 5;
    int wm = w >> 2;
    int wn = w & 3;

    wmma::fragment<wmma::accumulator, 16, 16, 16, float> acc[4][4];
    #pragma unroll
    for (int i = 0; i < 4; i++)
        #pragma unroll
        for (int j = 0; j < 4; j++) wmma::fill_fragment(acc[i][j], 0.0f);

    #define LOAD_STAGE(st, kk)                                                          \
        {                                                                               \
            __half* as_ = As + (st) * ASZ;                                              \
            __half* bs_ = Bs + (st) * BSZ;                                              \
            _Pragma("unroll")                                                           \
            for (int i = 0; i < 2; i++) {                                               \
                int c = tid + 256 * i;                                                  \
                int r = c >> 2, c8 = (c & 3) * 8;                                       \
                cpa16(&as_[r * A_LD + c8], &A[(size_t)(m0 + r) * K + (kk) + c8]);       \
            }                                                                           \
            _Pragma("unroll")                                                           \
            for (int i = 0; i < 4; i++) {                                               \
                int c = tid + 256 * i;                                                  \
                int r = c >> 5, c8 = (c & 31) * 8;                                      \
                cpa16(&bs_[r * B_LD + c8], &B[(size_t)((kk) + r) * N + n0 + c8]);       \
            }                                                                           \
            asm volatile("cp.async.commit_group;\n");                                   \
        }

    LOAD_STAGE(0, 0);
    LOAD_STAGE(1, 32);
    LOAD_STAGE(2, 64);

    int nk = K >> 5;
    for (int kt = 0; kt < nk; kt++) {
        int rem = nk - 1 - kt;
        if (rem >= 2)      asm volatile("cp.async.wait_group 2;\n");
        else if (rem == 1) asm volatile("cp.async.wait_group 1;\n");
        else               asm volatile("cp.async.wait_group 0;\n");
        __syncthreads();

        if (kt + 3 < nk) {
            LOAD_STAGE((kt + 3) & 3, (kt + 3) << 5);
        }

        const __half* as = As + (kt & 3) * ASZ;
        const __half* bs = Bs + (kt & 3) * BSZ;

        #pragma unroll
        for (int kf = 0; kf < 2; kf++) {
            wmma::fragment<wmma::matrix_a, 16, 16, 16, __half, wmma::row_major> af[4];
            wmma::fragment<wmma::matrix_b, 16, 16, 16, __half, wmma::row_major> bf[4];
            #pragma unroll
            for (int i = 0; i < 4; i++)
                wmma::load_matrix_sync(af[i], &as[(wm * 64 + i * 16) * A_LD + kf * 16], A_LD);
            #pragma unroll
            for (int j = 0; j < 4; j++)
                wmma::load_matrix_sync(bf[j], &bs[(kf * 16) * B_LD + wn * 64 + j * 16], B_LD);
            #pragma unroll
            for (int i = 0; i < 4; i++)
                #pragma unroll
                for (int j = 0; j < 4; j++)
                    wmma::mma_sync(acc[i][j], af[i], bf[j], acc[i][j]);
        }
    }

    #pragma unroll
    for (int i = 0; i < 4; i++)
        #pragma unroll
        for (int j = 0; j < 4; j++)
            wmma::store_matrix_sync(&C[(size_t)(m0 + wm * 64 + i * 16) * N + n0 + wn * 64 + j * 16],
                                    acc[i][j], N, wmma::mem_row_major);
}

// ---------------- scatter + rotary ----------------
__global__ void __launch_bounds__(256) scatter_rotary_kernel(const float* __restrict__ cache,
                                                             float* __restrict__ kv_out) {
    int idx = blockIdx.x * 256 + threadIdx.x;
    int dd = idx & 127;
    int j  = (idx >> 7) & 2047;
    int h  = (idx >> 18) & 15;
    int b  = idx >> 22;

    float c = g_cos[j * DD + dd];
    float s = g_sin[j * DD + dd];
    int pd = (dd < 64) ? dd + 64 : dd - 64;
    float sgn = (dd < 64) ? -1.0f : 1.0f;

    float kvl, kpart, vv;
    if (j < 1024) {
        const float* ckb = cache + (((size_t)(b * 2 + 0) * HH + h) * 1024 + j) * DD;
        const float* cvb = cache + (((size_t)(b * 2 + 1) * HH + h) * 1024 + j) * DD;
        kvl = ckb[dd];
        kpart = ckb[pd];
        vv = cvb[dd];
    } else {
        int rrow = b * NN + (j - 1024);
        const float* qr = g_qkv + (size_t)rrow * NQKV;
        kvl   = qr[2048 + h * DD + dd];
        kpart = qr[2048 + h * DD + pd];
        vv    = qr[4096 + h * DD + dd];
        float ql = qr[h * DD + dd];
        float qp = qr[h * DD + pd];
        g_qrot[(((size_t)(b * HH + h) * NN + (j - 1024)) * DD) + dd] =
            __float2half_rn(ql * c + sgn * qp * s);
    }

    size_t kvidx = ((size_t)(b * HH + h) * JJ + j) * DD + dd;
    g_krot[kvidx]  = __float2half_rn(kvl * c + sgn * kpart * s);
    g_vfull[kvidx] = __float2half_rn(vv);

    kv_out[(((size_t)(b * 2 + 0) * HH + h) * JJ + j) * DD + dd] = kvl;
    kv_out[(((size_t)(b * 2 + 1) * HH + h) * JJ + j) * DD + dd] = vv;
}

// ---------------- flash attention: FA2-style, register-resident, mma.sync PTX ----------------
// smem halves: Qs | K0 | V0 | K1 | V1, each 128 x KLD; then 2 x 128 int mask
#define KLD 136
#define TILE_H (128 * KLD)
#define AT_SMEM_BYTES (5 * TILE_H * 2 + 2 * 128 * 4)

__global__ void __launch_bounds__(256, 1) attn_kernel(const int* __restrict__ mask) {
    extern __shared__ char asmem[];
    __half* Qs = (__half*)asmem;
    __half* Kb[2] = { Qs + 1 * TILE_H, Qs + 3 * TILE_H };
    __half* Vb[2] = { Qs + 2 * TILE_H, Qs + 4 * TILE_H };
    int* Ms = (int*)(Qs + 5 * TILE_H);   // [2][128]

    int tid = threadIdx.x;
    int w = tid >> 5;
    int lane = tid & 31;
    int g = lane >> 2;
    int t2 = (lane & 3) * 2;

    int bid = blockIdx.x;
    int b  = bid & 3;
    int h  = (bid >> 2) & 15;
    int qb = 7 - (bid >> 6);
    int m0 = qb * 128;

    const __half* qp = g_qrot + ((size_t)(b * HH + h) * NN + m0) * DD;
    const __half* kp = g_krot + (size_t)(b * HH + h) * JJ * DD;
    const __half* vp = g_vfull + (size_t)(b * HH + h) * JJ * DD;
    const int* mrow = mask + (size_t)b * JJ;

    int nt = qb + 9;

    // Q tile -> smem
    #pragma unroll
    for (int i = tid; i < 128 * 16; i += 256) {
        int r = i >> 4, c8 = (i & 15) * 8;
        *(float4*)&Qs[r * KLD + c8] = *(const float4*)&qp[(size_t)r * DD + c8];
    }
    // mask tile 0
    if (tid < 128) Ms[tid] = mrow[tid];
    // prefetch K0, V0
    #pragma unroll
    for (int i = tid; i < 128 * 16; i += 256) {
        int r = i >> 4, c8 = (i & 15) * 8;
        cpa16(&Kb[0][r * KLD + c8], &kp[(size_t)r * DD + c8]);
    }
    asm volatile("cp.async.commit_group;\n");
    #pragma unroll
    for (int i = tid; i < 128 * 16; i += 256) {
        int r = i >> 4, c8 = (i & 15) * 8;
        cpa16(&Vb[0][r * KLD + c8], &vp[(size_t)r * DD + c8]);
    }
    asm volatile("cp.async.commit_group;\n");
    __syncthreads();

    // Q fragments (persistent)
    uint32_t qa[8][4];
    int qr0 = (w * 16 + g) * KLD;
    int qr1 = (w * 16 + g + 8) * KLD;
    #pragma unroll
    for (int ks = 0; ks < 8; ks++) {
        qa[ks][0] = *(uint32_t*)&Qs[qr0 + ks * 16 + t2];
        qa[ks][1] = *(uint32_t*)&Qs[qr1 + ks * 16 + t2];
        qa[ks][2] = *(uint32_t*)&Qs[qr0 + ks * 16 + t2 + 8];
        qa[ks][3] = *(uint32_t*)&Qs[qr1 + ks * 16 + t2 + 8];
    }

    float oc[16][4];
    #pragma unroll
    for (int n = 0; n < 16; n++)
        #pragma unroll
        for (int i = 0; i < 4; i++) oc[n][i] = 0.0f;

    float m0r = -1e30f, m1r = -1e30f;
    float l0 = 0.0f, l1 = 0.0f;
    int row0 = m0 + w * 16 + g;
    int rowlim0 = row0 + 1024;
    int rowlim1 = rowlim0 + 8;
    const float scale = 0.08838834764831845f;

    for (int kt = 0; kt < nt; kt++) {
        asm volatile("cp.async.wait_group 0;\n");
        __syncthreads();

        // mask tile kt+1
        if (tid < 128 && kt + 1 < nt) Ms[((kt + 1) & 1) * 128 + tid] = mrow[(kt + 1) * 128 + tid];

        // prefetch K,V for kt+1
        if (kt + 1 < nt) {
            int bn = (kt + 1) & 1;
            #pragma unroll
            for (int i = tid; i < 128 * 16; i += 256) {
                int r = i >> 4, c8 = (i & 15) * 8;
                cpa16(&Kb[bn][r * KLD + c8], &kp[(size_t)((kt + 1) * 128 + r) * DD + c8]);
            }
            asm volatile("cp.async.commit_group;\n");
            #pragma unroll
            for (int i = tid; i < 128 * 16; i += 256) {
                int r = i >> 4, c8 = (i & 15) * 8;
                cpa16(&Vb[bn][r * KLD + c8], &vp[(size_t)((kt + 1) * 128 + r) * DD + c8]);
            }
            asm volatile("cp.async.commit_group;\n");
        }

        const __half* Kt = Kb[kt & 1];
        const __half* Vt = Vb[kt & 1];
        const int* Mt = Ms + (kt & 1) * 128;

        // S = Q K^T : 16 n-blocks of 8 keys
        float sc[16][4];
        #pragma unroll
        for (int n = 0; n < 16; n++)
            #pragma unroll
            for (int i = 0; i < 4; i++) sc[n][i] = 0.0f;

        #pragma unroll
        for (int ks = 0; ks < 8; ks++) {
            #pragma unroll
            for (int nb = 0; nb < 16; nb++) {
                uint32_t b0 = *(uint32_t*)&Kt[(nb * 8 + g) * KLD + ks * 16 + t2];
                uint32_t b1 = *(uint32_t*)&Kt[(nb * 8 + g) * KLD + ks * 16 + t2 + 8];
                mma16816(sc[nb], qa[ks], b0, b1);
            }
        }

        // online softmax in registers
        bool lastt = (kt == nt - 1);
        float mx0 = -1e30f, mx1 = -1e30f;
        #pragma unroll
        for (int nb = 0; nb < 16; nb++) {
            int col = kt * 128 + nb * 8 + t2;
            int2 mv = *(const int2*)&Mt[nb * 8 + t2];
            float v0 = sc[nb][0] * scale;
            float v1 = sc[nb][1] * scale;
            float v2 = sc[nb][2] * scale;
            float v3 = sc[nb][3] * scale;
            if (mv.x == 0) { v0 = -1e30f; v2 = -1e30f; }
            if (mv.y == 0) { v1 = -1e30f; v3 = -1e30f; }
            if (lastt) {
                if (col     > rowlim0) v0 = -1e30f;
                if (col + 1 > rowlim0) v1 = -1e30f;
                if (col     > rowlim1) v2 = -1e30f;
                if (col + 1 > rowlim1) v3 = -1e30f;
            }
            sc[nb][0] = v0; sc[nb][1] = v1; sc[nb][2] = v2; sc[nb][3] = v3;
            mx0 = fmaxf(mx0, fmaxf(v0, v1));
            mx1 = fmaxf(mx1, fmaxf(v2, v3));
        }
        mx0 = fmaxf(mx0, __shfl_xor_sync(0xffffffffu, mx0, 1));
        mx0 = fmaxf(mx0, __shfl_xor_sync(0xffffffffu, mx0, 2));
        mx1 = fmaxf(mx1, __shfl_xor_sync(0xffffffffu, mx1, 1));
        mx1 = fmaxf(mx1, __shfl_xor_sync(0xffffffffu, mx1, 2));

        float mn0 = fmaxf(m0r, mx0), mn1 = fmaxf(m1r, mx1);
        float al0 = __expf(m0r - mn0), al1 = __expf(m1r - mn1);
        m0r = mn0; m1r = mn1;

        float s0 = 0.0f, s1 = 0.0f;
        #pragma unroll
        for (int nb = 0; nb < 16; nb++) {
            float p0 = __expf(sc[nb][0] - mn0);
            float p1 = __expf(sc[nb][1] - mn0);
            float p2 = __expf(sc[nb][2] - mn1);
            float p3 = __expf(sc[nb][3] - mn1);
            sc[nb][0] = p0; sc[nb][1] = p1; sc[nb][2] = p2; sc[nb][3] = p3;
            s0 += p0 + p1; s1 += p2 + p3;
        }
        l0 = l0 * al0 + s0;
        l1 = l1 * al1 + s1;
        #pragma unroll
        for (int n = 0; n < 16; n++) {
            oc[n][0] *= al0; oc[n][1] *= al0;
            oc[n][2] *= al1; oc[n][3] *= al1;
        }

        // P fragments + PV
        #pragma unroll
        for (int kk = 0; kk < 8; kk++) {
            uint32_t pa[4];
            pa[0] = f2h2(sc[2 * kk][0],     sc[2 * kk][1]);
            pa[1] = f2h2(sc[2 * kk][2],     sc[2 * kk][3]);
            pa[2] = f2h2(sc[2 * kk + 1][0], sc[2 * kk + 1][1]);
            pa[3] = f2h2(sc[2 * kk + 1][2], sc[2 * kk + 1][3]);
            #pragma unroll
            for (int nd = 0; nd < 16; nd++) {
                int colv = nd * 8 + g;
                __half x0 = Vt[(kk * 16 + t2)     * KLD + colv];
                __half x1 = Vt[(kk * 16 + t2 + 1) * KLD + colv];
                __half x2 = Vt[(kk * 16 + t2 + 8) * KLD + colv];
                __half x3 = Vt[(kk * 16 + t2 + 9) * KLD + colv];
                uint32_t b0 = ((uint32_t)*(uint16_t*)&x1 << 16) | *(uint16_t*)&x0;
                uint32_t b1 = ((uint32_t)*(uint16_t*)&x3 << 16) | *(uint16_t*)&x2;
                mma16816(oc[nd], pa, b0, b1);
            }
        }
    }

    // finalize
    l0 += __shfl_xor_sync(0xffffffffu, l0, 1);
    l0 += __shfl_xor_sync(0xffffffffu, l0, 2);
    l1 += __shfl_xor_sync(0xffffffffu, l1, 1);
    l1 += __shfl_xor_sync(0xffffffffu, l1, 2);
    float inv0 = 1.0f / l0, inv1 = 1.0f / l1;

    __half* out0 = g_attnout + (size_t)(b * NN + row0) * DIMM + h * DD;
    __half* out1 = out0 + (size_t)8 * DIMM;
    #pragma unroll
    for (int nd = 0; nd < 16; nd++) {
        *(uint32_t*)&out0[nd * 8 + t2] = f2h2(oc[nd][0] * inv0, oc[nd][1] * inv0);
        *(uint32_t*)&out1[nd * 8 + t2] = f2h2(oc[nd][2] * inv1, oc[nd][3] * inv1);
    }
}

// ---------------- launch ----------------
extern "C" void kernel_launch(void* const* d_in, const int* in_sizes, int n_in,
                              void* d_out, int out_size) {
    const float* x       = (const float*)d_in[0];
    const float* cache   = (const float*)d_in[1];
    const float* rotary  = (const float*)d_in[2];
    const int*   mask    = (const int*)d_in[3];
    const float* norm_w  = (const float*)d_in[4];
    const float* w_qkv   = (const float*)d_in[5];
    const float* w_out   = (const float*)d_in[6];

    float* out    = (float*)d_out;
    float* kv_out = out + (size_t)ROWS * DIMM;

    __half *xn_ptr, *wqkv_ptr, *wout_ptr, *ao_ptr;
    float *qkv_ptr;
    cudaGetSymbolAddress((void**)&xn_ptr, g_xn);
    cudaGetSymbolAddress((void**)&qkv_ptr, g_qkv);
    cudaGetSymbolAddress((void**)&ao_ptr, g_attnout);
    cudaGetSymbolAddress((void**)&wqkv_ptr, g_wqkv_h);
    cudaGetSymbolAddress((void**)&wout_ptr, g_wout_h);

    cudaFuncSetAttribute(attn_kernel, cudaFuncAttributeMaxDynamicSharedMemorySize, AT_SMEM_BYTES);
    cudaFuncSetAttribute(gemm_hp, cudaFuncAttributeMaxDynamicSharedMemorySize, G_SMEM_BYTES);

    convert_h_kernel<<<(DIMM * NQKV / 4 + 255) / 256, 256>>>(w_qkv, wqkv_ptr, DIMM * NQKV);
    convert_h_kernel<<<(DIMM * DIMM / 4 + 255) / 256, 256>>>(w_out, wout_ptr, DIMM * DIMM);

    rope_table_kernel<<<(JJ * DD) / 256, 256>>>(rotary);
    rmsnorm_kernel<<<ROWS, 256>>>(x, norm_w);

    gemm_hp<<<dim3(NQKV / 256, ROWS / 128), 256, G_SMEM_BYTES>>>(xn_ptr, wqkv_ptr, qkv_ptr,
                                                                 ROWS, NQKV, DIMM);

    scatter_rotary_kernel<<<(BB * HH * JJ * DD) / 256, 256>>>(cache, kv_out);

    attn_kernel<<<BB * HH * (NN / 128), 256, AT_SMEM_BYTES>>>(mask);

    gemm_hp<<<dim3(DIMM / 256, ROWS / 128), 256, G_SMEM_BYTES>>>(ao_ptr, wout_ptr, out,
                                                                 ROWS, DIMM, DIMM);
}

// round 11
// speedup vs baseline: 6.0353x; 1.1654x over previous
#include <cuda_runtime.h>
#include <cuda_fp16.h>
#include <mma.h>
#include <cstdint>

using namespace nvcuda;

#define BB 4
#define NN 1024
#define JJ 2048
#define HH 16
#define DD 128
#define DIMM 2048
#define NQKV 6144
#define ROWS 4096

__device__ __half g_xn[(size_t)ROWS * DIMM];
__device__ float  g_qkv[(size_t)ROWS * NQKV];
__device__ __half g_qrot[(size_t)BB * HH * NN * DD];
__device__ __half g_krot[(size_t)BB * HH * JJ * DD];
__device__ __half g_vfull[(size_t)BB * HH * JJ * DD];
__device__ __half g_attnout[(size_t)ROWS * DIMM];
__device__ __half g_wqkv_h[(size_t)DIMM * NQKV];
__device__ __half g_wout_h[(size_t)DIMM * DIMM];
__device__ float  g_cos[JJ * DD];
__device__ float  g_sin[JJ * DD];

__device__ __forceinline__ void cpa16(void* smem, const void* gmem) {
    unsigned s = (unsigned)__cvta_generic_to_shared(smem);
    asm volatile("cp.async.cg.shared.global [%0], [%1], 16;\n" :: "r"(s), "l"(gmem));
}

__device__ __forceinline__ uint32_t smem_u32(const void* p) {
    uint32_t a;
    asm("{ .reg .u64 t; cvta.to.shared.u64 t, %1; cvt.u32.u64 %0, t; }" : "=r"(a) : "l"(p));
    return a;
}

__device__ __forceinline__ void ldsm4(uint32_t* r, uint32_t a) {
    asm volatile("ldmatrix.sync.aligned.m8n8.x4.shared.b16 {%0,%1,%2,%3}, [%4];"
                 : "=r"(r[0]), "=r"(r[1]), "=r"(r[2]), "=r"(r[3]) : "r"(a));
}
__device__ __forceinline__ void ldsm4t(uint32_t* r, uint32_t a) {
    asm volatile("ldmatrix.sync.aligned.m8n8.x4.trans.shared.b16 {%0,%1,%2,%3}, [%4];"
                 : "=r"(r[0]), "=r"(r[1]), "=r"(r[2]), "=r"(r[3]) : "r"(a));
}

__device__ __forceinline__ void mma16816(float* c, const uint32_t* a, uint32_t b0, uint32_t b1) {
    asm volatile(
        "mma.sync.aligned.m16n8k16.row.col.f32.f16.f16.f32 "
        "{%0,%1,%2,%3}, {%4,%5,%6,%7}, {%8,%9}, {%0,%1,%2,%3};"
        : "+f"(c[0]), "+f"(c[1]), "+f"(c[2]), "+f"(c[3])
        : "r"(a[0]), "r"(a[1]), "r"(a[2]), "r"(a[3]), "r"(b0), "r"(b1));
}

__device__ __forceinline__ uint32_t f2h2(float x, float y) {
    __half2 h = __floats2half2_rn(x, y);
    return *(uint32_t*)&h;
}

// ---------------- small kernels ----------------
__global__ void __launch_bounds__(256) rope_table_kernel(const float* __restrict__ rot) {
    int idx = blockIdx.x * 256 + threadIdx.x;
    float p = rot[idx];
    g_cos[idx] = cosf(p);
    g_sin[idx] = sinf(p);
}

__global__ void __launch_bounds__(256) convert_h_kernel(const float* __restrict__ in,
                                                        __half* __restrict__ out, int n) {
    int idx = (blockIdx.x * 256 + threadIdx.x) * 4;
    if (idx < n) {
        float4 v = *(const float4*)(in + idx);
        *(__half2*)(out + idx)     = __floats2half2_rn(v.x, v.y);
        *(__half2*)(out + idx + 2) = __floats2half2_rn(v.z, v.w);
    }
}

__global__ void __launch_bounds__(256) rmsnorm_kernel(const float* __restrict__ x,
                                                      const float* __restrict__ w) {
    int row = blockIdx.x;
    int tid = threadIdx.x;
    const float* xr = x + (size_t)row * DIMM;
    float ss = 0.0f;
    #pragma unroll
    for (int i = tid * 4; i < DIMM; i += 1024) {
        float4 v = *(const float4*)(xr + i);
        ss += v.x * v.x + v.y * v.y + v.z * v.z + v.w * v.w;
    }
    #pragma unroll
    for (int o = 16; o; o >>= 1) ss += __shfl_xor_sync(0xffffffffu, ss, o);
    __shared__ float red[8];
    if ((tid & 31) == 0) red[tid >> 5] = ss;
    __syncthreads();
    float tot = 0.0f;
    #pragma unroll
    for (int i = 0; i < 8; i++) tot += red[i];
    float inv = rsqrtf(tot * (1.0f / (float)DIMM) + 1.1920929e-7f);
    for (int i = tid * 2; i < DIMM; i += 512) {
        float2 v = *(const float2*)(xr + i);
        *(__half2*)&g_xn[(size_t)row * DIMM + i] =
            __floats2half2_rn(v.x * inv * w[i], v.y * inv * w[i + 1]);
    }
}

// ---------------- fp16 GEMM: block 128x256, warp 64x64, 4-stage cp.async ----------------
#define GS 4
#define A_LD 40
#define B_LD 264
#define ASZ (128 * A_LD)
#define BSZ (32 * B_LD)
#define G_SMEM_BYTES (GS * (ASZ + BSZ) * 2)

__global__ void __launch_bounds__(256, 1) gemm_hp(const __half* __restrict__ A,
                                                  const __half* __restrict__ B,
                                                  float* __restrict__ C,
                                                  int M, int N, int K) {
    extern __shared__ __half hsm[];
    __half* As = hsm;
    __half* Bs = hsm + GS * ASZ;

    int tid = threadIdx.x;
    int n0 = blockIdx.x * 256;
    int m0 = blockIdx.y * 128;
    int w = tid >> 5;
    int wm = w >> 2;
    int wn = w & 3;

    wmma::fragment<wmma::accumulator, 16, 16, 16, float> acc[4][4];
    #pragma unroll
    for (int i = 0; i < 4; i++)
        #pragma unroll
        for (int j = 0; j < 4; j++) wmma::fill_fragment(acc[i][j], 0.0f);

    #define LOAD_STAGE(st, kk)                                                          \
        {                                                                               \
            __half* as_ = As + (st) * ASZ;                                              \
            __half* bs_ = Bs + (st) * BSZ;                                              \
            _Pragma("unroll")                                                           \
            for (int i = 0; i < 2; i++) {                                               \
                int c = tid + 256 * i;                                                  \
                int r = c >> 2, c8 = (c & 3) * 8;                                       \
                cpa16(&as_[r * A_LD + c8], &A[(size_t)(m0 + r) * K + (kk) + c8]);       \
            }                                                                           \
            _Pragma("unroll")                                                           \
            for (int i = 0; i < 4; i++) {                                               \
                int c = tid + 256 * i;                                                  \
                int r = c >> 5, c8 = (c & 31) * 8;                                      \
                cpa16(&bs_[r * B_LD + c8], &B[(size_t)((kk) + r) * N + n0 + c8]);       \
            }                                                                           \
            asm volatile("cp.async.commit_group;\n");                                   \
        }

    LOAD_STAGE(0, 0);
    LOAD_STAGE(1, 32);
    LOAD_STAGE(2, 64);

    int nk = K >> 5;
    for (int kt = 0; kt < nk; kt++) {
        int rem = nk - 1 - kt;
        if (rem >= 2)      asm volatile("cp.async.wait_group 2;\n");
        else if (rem == 1) asm volatile("cp.async.wait_group 1;\n");
        else               asm volatile("cp.async.wait_group 0;\n");
        __syncthreads();

        if (kt + 3 < nk) {
            LOAD_STAGE((kt + 3) & 3, (kt + 3) << 5);
        }

        const __half* as = As + (kt & 3) * ASZ;
        const __half* bs = Bs + (kt & 3) * BSZ;

        #pragma unroll
        for (int kf = 0; kf < 2; kf++) {
            wmma::fragment<wmma::matrix_a, 16, 16, 16, __half, wmma::row_major> af[4];
            wmma::fragment<wmma::matrix_b, 16, 16, 16, __half, wmma::row_major> bf[4];
            #pragma unroll
            for (int i = 0; i < 4; i++)
                wmma::load_matrix_sync(af[i], &as[(wm * 64 + i * 16) * A_LD + kf * 16], A_LD);
            #pragma unroll
            for (int j = 0; j < 4; j++)
                wmma::load_matrix_sync(bf[j], &bs[(kf * 16) * B_LD + wn * 64 + j * 16], B_LD);
            #pragma unroll
            for (int i = 0; i < 4; i++)
                #pragma unroll
                for (int j = 0; j < 4; j++)
                    wmma::mma_sync(acc[i][j], af[i], bf[j], acc[i][j]);
        }
    }

    #pragma unroll
    for (int i = 0; i < 4; i++)
        #pragma unroll
        for (int j = 0; j < 4; j++)
            wmma::store_matrix_sync(&C[(size_t)(m0 + wm * 64 + i * 16) * N + n0 + wn * 64 + j * 16],
                                    acc[i][j], N, wmma::mem_row_major);
}

// ---------------- scatter + rotary (float4 vectorized) ----------------
__global__ void __launch_bounds__(256) scatter_rotary_kernel(const float* __restrict__ cache,
                                                             float* __restrict__ kv_out) {
    int idx = blockIdx.x * 256 + threadIdx.x;    // 2^22 threads
    int d4 = (idx & 31) * 4;
    int j  = (idx >> 5) & 2047;
    int h  = (idx >> 16) & 15;
    int b  = idx >> 20;

    float4 c4 = *(const float4*)&g_cos[j * DD + d4];
    float4 s4 = *(const float4*)&g_sin[j * DD + d4];
    int p4 = (d4 < 64) ? d4 + 64 : d4 - 64;
    float sgn = (d4 < 64) ? -1.0f : 1.0f;

    float4 kv, kpp, vv;
    if (j < 1024) {
        const float* ckb = cache + (((size_t)(b * 2 + 0) * HH + h) * 1024 + j) * DD;
        const float* cvb = cache + (((size_t)(b * 2 + 1) * HH + h) * 1024 + j) * DD;
        kv  = *(const float4*)(ckb + d4);
        kpp = *(const float4*)(ckb + p4);
        vv  = *(const float4*)(cvb + d4);
    } else {
        int rrow = b * NN + (j - 1024);
        const float* qr = g_qkv + (size_t)rrow * NQKV;
        kv  = *(const float4*)(qr + 2048 + h * DD + d4);
        kpp = *(const float4*)(qr + 2048 + h * DD + p4);
        vv  = *(const float4*)(qr + 4096 + h * DD + d4);
        float4 ql = *(const float4*)(qr + h * DD + d4);
        float4 qp = *(const float4*)(qr + h * DD + p4);
        uint2 qh;
        qh.x = f2h2(ql.x * c4.x + sgn * qp.x * s4.x, ql.y * c4.y + sgn * qp.y * s4.y);
        qh.y = f2h2(ql.z * c4.z + sgn * qp.z * s4.z, ql.w * c4.w + sgn * qp.w * s4.w);
        *(uint2*)&g_qrot[(((size_t)(b * HH + h) * NN + (j - 1024)) * DD) + d4] = qh;
    }

    size_t kvidx = ((size_t)(b * HH + h) * JJ + j) * DD + d4;
    uint2 kh, vh;
    kh.x = f2h2(kv.x * c4.x + sgn * kpp.x * s4.x, kv.y * c4.y + sgn * kpp.y * s4.y);
    kh.y = f2h2(kv.z * c4.z + sgn * kpp.z * s4.z, kv.w * c4.w + sgn * kpp.w * s4.w);
    vh.x = f2h2(vv.x, vv.y);
    vh.y = f2h2(vv.z, vv.w);
    *(uint2*)&g_krot[kvidx]  = kh;
    *(uint2*)&g_vfull[kvidx] = vh;

    *(float4*)&kv_out[(((size_t)(b * 2 + 0) * HH + h) * JJ + j) * DD + d4] = kv;
    *(float4*)&kv_out[(((size_t)(b * 2 + 1) * HH + h) * JJ + j) * DD + d4] = vv;
}

// ---------------- flash attention: register-resident, ldmatrix ----------------
#define KLD 136
#define TILE_H (128 * KLD)
#define AT_SMEM_BYTES (5 * TILE_H * 2 + 2 * 128 * 4)

__global__ void __launch_bounds__(256, 1) attn_kernel(const int* __restrict__ mask) {
    extern __shared__ char asmem[];
    __half* Qs = (__half*)asmem;
    __half* Kb[2] = { Qs + 1 * TILE_H, Qs + 3 * TILE_H };
    __half* Vb[2] = { Qs + 2 * TILE_H, Qs + 4 * TILE_H };
    int* Ms = (int*)(Qs + 5 * TILE_H);

    int tid = threadIdx.x;
    int w = tid >> 5;
    int lane = tid & 31;
    int g = lane >> 2;
    int t2 = (lane & 3) * 2;

    int bid = blockIdx.x;
    int b  = bid & 3;
    int h  = (bid >> 2) & 15;
    int qb = 7 - (bid >> 6);
    int m0 = qb * 128;

    const __half* qp = g_qrot + ((size_t)(b * HH + h) * NN + m0) * DD;
    const __half* kp = g_krot + (size_t)(b * HH + h) * JJ * DD;
    const __half* vp = g_vfull + (size_t)(b * HH + h) * JJ * DD;
    const int* mrow = mask + (size_t)b * JJ;

    int nt = qb + 9;

    #pragma unroll
    for (int i = tid; i < 128 * 16; i += 256) {
        int r = i >> 4, c8 = (i & 15) * 8;
        *(float4*)&Qs[r * KLD + c8] = *(const float4*)&qp[(size_t)r * DD + c8];
    }
    if (tid < 128) Ms[tid] = mrow[tid];
    #pragma unroll
    for (int i = tid; i < 128 * 16; i += 256) {
        int r = i >> 4, c8 = (i & 15) * 8;
        cpa16(&Kb[0][r * KLD + c8], &kp[(size_t)r * DD + c8]);
    }
    asm volatile("cp.async.commit_group;\n");
    #pragma unroll
    for (int i = tid; i < 128 * 16; i += 256) {
        int r = i >> 4, c8 = (i & 15) * 8;
        cpa16(&Vb[0][r * KLD + c8], &vp[(size_t)r * DD + c8]);
    }
    asm volatile("cp.async.commit_group;\n");
    __syncthreads();

    // persistent Q fragments
    uint32_t qa[8][4];
    int qr0 = (w * 16 + g) * KLD;
    int qr1 = (w * 16 + g + 8) * KLD;
    #pragma unroll
    for (int ks = 0; ks < 8; ks++) {
        qa[ks][0] = *(uint32_t*)&Qs[qr0 + ks * 16 + t2];
        qa[ks][1] = *(uint32_t*)&Qs[qr1 + ks * 16 + t2];
        qa[ks][2] = *(uint32_t*)&Qs[qr0 + ks * 16 + t2 + 8];
        qa[ks][3] = *(uint32_t*)&Qs[qr1 + ks * 16 + t2 + 8];
    }

    float oc[16][4];
    #pragma unroll
    for (int n = 0; n < 16; n++)
        #pragma unroll
        for (int i = 0; i < 4; i++) oc[n][i] = 0.0f;

    float m0r = -1e30f, m1r = -1e30f;
    float l0 = 0.0f, l1 = 0.0f;
    int row0 = m0 + w * 16 + g;
    int rowlim0 = row0 + 1024;
    int rowlim1 = rowlim0 + 8;
    const float scale = 0.08838834764831845f;

    // per-lane ldmatrix offsets (bytes)
    uint32_t koff = ((lane & 7) * KLD + (lane >> 3) * 8) * 2;
    uint32_t voff = ((((lane >> 3) & 1) * 8 + (lane & 7)) * KLD + (lane >> 4) * 8) * 2;

    for (int kt = 0; kt < nt; kt++) {
        asm volatile("cp.async.wait_group 0;\n");
        __syncthreads();

        if (tid < 128 && kt + 1 < nt) Ms[((kt + 1) & 1) * 128 + tid] = mrow[(kt + 1) * 128 + tid];

        if (kt + 1 < nt) {
            int bn = (kt + 1) & 1;
            #pragma unroll
            for (int i = tid; i < 128 * 16; i += 256) {
                int r = i >> 4, c8 = (i & 15) * 8;
                cpa16(&Kb[bn][r * KLD + c8], &kp[(size_t)((kt + 1) * 128 + r) * DD + c8]);
            }
            asm volatile("cp.async.commit_group;\n");
            #pragma unroll
            for (int i = tid; i < 128 * 16; i += 256) {
                int r = i >> 4, c8 = (i & 15) * 8;
                cpa16(&Vb[bn][r * KLD + c8], &vp[(size_t)((kt + 1) * 128 + r) * DD + c8]);
            }
            asm volatile("cp.async.commit_group;\n");
        }

        const __half* Kt = Kb[kt & 1];
        const __half* Vt = Vb[kt & 1];
        const int* Mt = Ms + (kt & 1) * 128;

        // S = Q K^T via ldmatrix x4 (K fragments)
        float sc[16][4];
        #pragma unroll
        for (int n = 0; n < 16; n++)
            #pragma unroll
            for (int i = 0; i < 4; i++) sc[n][i] = 0.0f;

        uint32_t ktu = smem_u32(Kt) + koff;
        #pragma unroll
        for (int ksp = 0; ksp < 4; ksp++) {
            #pragma unroll
            for (int nb = 0; nb < 16; nb++) {
                uint32_t br[4];
                ldsm4(br, ktu + (uint32_t)(nb * 8 * KLD + ksp * 32) * 2);
                mma16816(sc[nb], qa[2 * ksp],     br[0], br[1]);
                mma16816(sc[nb], qa[2 * ksp + 1], br[2], br[3]);
            }
        }

        // online softmax in registers
        bool lastt = (kt == nt - 1);
        float mx0 = -1e30f, mx1 = -1e30f;
        #pragma unroll
        for (int nb = 0; nb < 16; nb++) {
            int col = kt * 128 + nb * 8 + t2;
            int2 mv = *(const int2*)&Mt[nb * 8 + t2];
            float v0 = sc[nb][0] * scale;
            float v1 = sc[nb][1] * scale;
            float v2 = sc[nb][2] * scale;
            float v3 = sc[nb][3] * scale;
            if (mv.x == 0) { v0 = -1e30f; v2 = -1e30f; }
            if (mv.y == 0) { v1 = -1e30f; v3 = -1e30f; }
            if (lastt) {
                if (col     > rowlim0) v0 = -1e30f;
                if (col + 1 > rowlim0) v1 = -1e30f;
                if (col     > rowlim1) v2 = -1e30f;
                if (col + 1 > rowlim1) v3 = -1e30f;
            }
            sc[nb][0] = v0; sc[nb][1] = v1; sc[nb][2] = v2; sc[nb][3] = v3;
            mx0 = fmaxf(mx0, fmaxf(v0, v1));
            mx1 = fmaxf(mx1, fmaxf(v2, v3));
        }
        mx0 = fmaxf(mx0, __shfl_xor_sync(0xffffffffu, mx0, 1));
        mx0 = fmaxf(mx0, __shfl_xor_sync(0xffffffffu, mx0, 2));
        mx1 = fmaxf(mx1, __shfl_xor_sync(0xffffffffu, mx1, 1));
        mx1 = fmaxf(mx1, __shfl_xor_sync(0xffffffffu, mx1, 2));

        float mn0 = fmaxf(m0r, mx0), mn1 = fmaxf(m1r, mx1);
        float al0 = __expf(m0r - mn0), al1 = __expf(m1r - mn1);
        m0r = mn0; m1r = mn1;

        float s0 = 0.0f, s1 = 0.0f;
        #pragma unroll
        for (int nb = 0; nb < 16; nb++) {
            float p0 = __expf(sc[nb][0] - mn0);
            float p1 = __expf(sc[nb][1] - mn0);
            float p2 = __expf(sc[nb][2] - mn1);
            float p3 = __expf(sc[nb][3] - mn1);
            sc[nb][0] = p0; sc[nb][1] = p1; sc[nb][2] = p2; sc[nb][3] = p3;
            s0 += p0 + p1; s1 += p2 + p3;
        }
        l0 = l0 * al0 + s0;
        l1 = l1 * al1 + s1;
        #pragma unroll
        for (int n = 0; n < 16; n++) {
            oc[n][0] *= al0; oc[n][1] *= al0;
            oc[n][2] *= al1; oc[n][3] *= al1;
        }

        // PV via ldmatrix.trans (V fragments)
        uint32_t vtu = smem_u32(Vt) + voff;
        #pragma unroll
        for (int kk = 0; kk < 8; kk++) {
            uint32_t pa[4];
            pa[0] = f2h2(sc[2 * kk][0],     sc[2 * kk][1]);
            pa[1] = f2h2(sc[2 * kk][2],     sc[2 * kk][3]);
            pa[2] = f2h2(sc[2 * kk + 1][0], sc[2 * kk + 1][1]);
            pa[3] = f2h2(sc[2 * kk + 1][2], sc[2 * kk + 1][3]);
            #pragma unroll
            for (int ndp = 0; ndp < 8; ndp++) {
                uint32_t br[4];
                ldsm4t(br, vtu + (uint32_t)(kk * 16 * KLD + ndp * 16) * 2);
                mma16816(oc[2 * ndp],     pa, br[0], br[1]);
                mma16816(oc[2 * ndp + 1], pa, br[2], br[3]);
            }
        }
    }

    // finalize
    l0 += __shfl_xor_sync(0xffffffffu, l0, 1);
    l0 += __shfl_xor_sync(0xffffffffu, l0, 2);
    l1 += __shfl_xor_sync(0xffffffffu, l1, 1);
    l1 += __shfl_xor_sync(0xffffffffu, l1, 2);
    float inv0 = 1.0f / l0, inv1 = 1.0f / l1;

    __half* out0 = g_attnout + (size_t)(b * NN + row0) * DIMM + h * DD;
    __half* out1 = out0 + (size_t)8 * DIMM;
    #pragma unroll
    for (int nd = 0; nd < 16; nd++) {
        *(uint32_t*)&out0[nd * 8 + t2] = f2h2(oc[nd][0] * inv0, oc[nd][1] * inv0);
        *(uint32_t*)&out1[nd * 8 + t2] = f2h2(oc[nd][2] * inv1, oc[nd][3] * inv1);
    }
}

// ---------------- launch ----------------
extern "C" void kernel_launch(void* const* d_in, const int* in_sizes, int n_in,
                              void* d_out, int out_size) {
    const float* x       = (const float*)d_in[0];
    const float* cache   = (const float*)d_in[1];
    const float* rotary  = (const float*)d_in[2];
    const int*   mask    = (const int*)d_in[3];
    const float* norm_w  = (const float*)d_in[4];
    const float* w_qkv   = (const float*)d_in[5];
    const float* w_out   = (const float*)d_in[6];

    float* out    = (float*)d_out;
    float* kv_out = out + (size_t)ROWS * DIMM;

    __half *xn_ptr, *wqkv_ptr, *wout_ptr, *ao_ptr;
    float *qkv_ptr;
    cudaGetSymbolAddress((void**)&xn_ptr, g_xn);
    cudaGetSymbolAddress((void**)&qkv_ptr, g_qkv);
    cudaGetSymbolAddress((void**)&ao_ptr, g_attnout);
    cudaGetSymbolAddress((void**)&wqkv_ptr, g_wqkv_h);
    cudaGetSymbolAddress((void**)&wout_ptr, g_wout_h);

    cudaFuncSetAttribute(attn_kernel, cudaFuncAttributeMaxDynamicSharedMemorySize, AT_SMEM_BYTES);
    cudaFuncSetAttribute(gemm_hp, cudaFuncAttributeMaxDynamicSharedMemorySize, G_SMEM_BYTES);

    convert_h_kernel<<<(DIMM * NQKV / 4 + 255) / 256, 256>>>(w_qkv, wqkv_ptr, DIMM * NQKV);
    convert_h_kernel<<<(DIMM * DIMM / 4 + 255) / 256, 256>>>(w_out, wout_ptr, DIMM * DIMM);

    rope_table_kernel<<<(JJ * DD) / 256, 256>>>(rotary);
    rmsnorm_kernel<<<ROWS, 256>>>(x, norm_w);

    gemm_hp<<<dim3(NQKV / 256, ROWS / 128), 256, G_SMEM_BYTES>>>(xn_ptr, wqkv_ptr, qkv_ptr,
                                                                 ROWS, NQKV, DIMM);

    scatter_rotary_kernel<<<(BB * HH * JJ * DD / 4) / 256, 256>>>(cache, kv_out);

    attn_kernel<<<BB * HH * (NN / 128), 256, AT_SMEM_BYTES>>>(mask);

    gemm_hp<<<dim3(DIMM / 256, ROWS / 128), 256, G_SMEM_BYTES>>>(ao_ptr, wout_ptr, out,
                                                                 ROWS, DIMM, DIMM);
}

// round 12
// speedup vs baseline: 6.1591x; 1.0205x over previous
#include <cuda_runtime.h>
#include <cuda_fp16.h>
#include <mma.h>
#include <cstdint>

using namespace nvcuda;

#define BB 4
#define NN 1024
#define JJ 2048
#define HH 16
#define DD 128
#define DIMM 2048
#define NQKV 6144
#define ROWS 4096

__device__ __half g_xn[(size_t)ROWS * DIMM];
__device__ float  g_qkv[(size_t)ROWS * NQKV];
__device__ __half g_qrot[(size_t)BB * HH * NN * DD];
__device__ __half g_krot[(size_t)BB * HH * JJ * DD];
__device__ __half g_vfull[(size_t)BB * HH * JJ * DD];
__device__ __half g_attnout[(size_t)ROWS * DIMM];
__device__ __half g_wqkv_h[(size_t)DIMM * NQKV];
__device__ __half g_wout_h[(size_t)DIMM * DIMM];
__device__ float  g_cos[JJ * DD];
__device__ float  g_sin[JJ * DD];

__device__ __forceinline__ void cpa16(void* smem, const void* gmem) {
    unsigned s = (unsigned)__cvta_generic_to_shared(smem);
    asm volatile("cp.async.cg.shared.global [%0], [%1], 16;\n" :: "r"(s), "l"(gmem));
}

__device__ __forceinline__ uint32_t smem_u32(const void* p) {
    uint32_t a;
    asm("{ .reg .u64 t; cvta.to.shared.u64 t, %1; cvt.u32.u64 %0, t; }" : "=r"(a) : "l"(p));
    return a;
}

__device__ __forceinline__ void ldsm4(uint32_t* r, uint32_t a) {
    asm volatile("ldmatrix.sync.aligned.m8n8.x4.shared.b16 {%0,%1,%2,%3}, [%4];"
                 : "=r"(r[0]), "=r"(r[1]), "=r"(r[2]), "=r"(r[3]) : "r"(a));
}
__device__ __forceinline__ void ldsm4t(uint32_t* r, uint32_t a) {
    asm volatile("ldmatrix.sync.aligned.m8n8.x4.trans.shared.b16 {%0,%1,%2,%3}, [%4];"
                 : "=r"(r[0]), "=r"(r[1]), "=r"(r[2]), "=r"(r[3]) : "r"(a));
}

__device__ __forceinline__ void mma16816(float* c, const uint32_t* a, uint32_t b0, uint32_t b1) {
    asm volatile(
        "mma.sync.aligned.m16n8k16.row.col.f32.f16.f16.f32 "
        "{%0,%1,%2,%3}, {%4,%5,%6,%7}, {%8,%9}, {%0,%1,%2,%3};"
        : "+f"(c[0]), "+f"(c[1]), "+f"(c[2]), "+f"(c[3])
        : "r"(a[0]), "r"(a[1]), "r"(a[2]), "r"(a[3]), "r"(b0), "r"(b1));
}

__device__ __forceinline__ uint32_t f2h2(float x, float y) {
    __half2 h = __floats2half2_rn(x, y);
    return *(uint32_t*)&h;
}

// ---------------- small kernels ----------------
__global__ void __launch_bounds__(256) rope_table_kernel(const float* __restrict__ rot) {
    int idx = blockIdx.x * 256 + threadIdx.x;
    float p = rot[idx];
    g_cos[idx] = cosf(p);
    g_sin[idx] = sinf(p);
}

__global__ void __launch_bounds__(256) convert_h_kernel(const float* __restrict__ in,
                                                        __half* __restrict__ out, int n) {
    int idx = (blockIdx.x * 256 + threadIdx.x) * 4;
    if (idx < n) {
        float4 v = *(const float4*)(in + idx);
        *(__half2*)(out + idx)     = __floats2half2_rn(v.x, v.y);
        *(__half2*)(out + idx + 2) = __floats2half2_rn(v.z, v.w);
    }
}

__global__ void __launch_bounds__(256) rmsnorm_kernel(const float* __restrict__ x,
                                                      const float* __restrict__ w) {
    int row = blockIdx.x;
    int tid = threadIdx.x;
    const float* xr = x + (size_t)row * DIMM;
    float ss = 0.0f;
    #pragma unroll
    for (int i = tid * 4; i < DIMM; i += 1024) {
        float4 v = *(const float4*)(xr + i);
        ss += v.x * v.x + v.y * v.y + v.z * v.z + v.w * v.w;
    }
    #pragma unroll
    for (int o = 16; o; o >>= 1) ss += __shfl_xor_sync(0xffffffffu, ss, o);
    __shared__ float red[8];
    if ((tid & 31) == 0) red[tid >> 5] = ss;
    __syncthreads();
    float tot = 0.0f;
    #pragma unroll
    for (int i = 0; i < 8; i++) tot += red[i];
    float inv = rsqrtf(tot * (1.0f / (float)DIMM) + 1.1920929e-7f);
    for (int i = tid * 2; i < DIMM; i += 512) {
        float2 v = *(const float2*)(xr + i);
        *(__half2*)&g_xn[(size_t)row * DIMM + i] =
            __floats2half2_rn(v.x * inv * w[i], v.y * inv * w[i + 1]);
    }
}

// ---------------- fp16 GEMM v1: block 128x256, warp 64x64, 4-stage (out-proj) ----------------
#define GS 4
#define A_LD 40
#define B_LD 264
#define ASZ (128 * A_LD)
#define BSZ (32 * B_LD)
#define G_SMEM_BYTES (GS * (ASZ + BSZ) * 2)

__global__ void __launch_bounds__(256, 1) gemm_hp(const __half* __restrict__ A,
                                                  const __half* __restrict__ B,
                                                  float* __restrict__ C,
                                                  int M, int N, int K) {
    extern __shared__ __half hsm[];
    __half* As = hsm;
    __half* Bs = hsm + GS * ASZ;

    int tid = threadIdx.x;
    int n0 = blockIdx.x * 256;
    int m0 = blockIdx.y * 128;
    int w = tid >> 5;
    int wm = w >> 2;
    int wn = w & 3;

    wmma::fragment<wmma::accumulator, 16, 16, 16, float> acc[4][4];
    #pragma unroll
    for (int i = 0; i < 4; i++)
        #pragma unroll
        for (int j = 0; j < 4; j++) wmma::fill_fragment(acc[i][j], 0.0f);

    #define LOAD_STAGE(st, kk)                                                          \
        {                                                                               \
            __half* as_ = As + (st) * ASZ;                                              \
            __half* bs_ = Bs + (st) * BSZ;                                              \
            _Pragma("unroll")                                                           \
            for (int i = 0; i < 2; i++) {                                               \
                int c = tid + 256 * i;                                                  \
                int r = c >> 2, c8 = (c & 3) * 8;                                       \
                cpa16(&as_[r * A_LD + c8], &A[(size_t)(m0 + r) * K + (kk) + c8]);       \
            }                                                                           \
            _Pragma("unroll")                                                           \
            for (int i = 0; i < 4; i++) {                                               \
                int c = tid + 256 * i;                                                  \
                int r = c >> 5, c8 = (c & 31) * 8;                                      \
                cpa16(&bs_[r * B_LD + c8], &B[(size_t)((kk) + r) * N + n0 + c8]);       \
            }                                                                           \
            asm volatile("cp.async.commit_group;\n");                                   \
        }

    LOAD_STAGE(0, 0);
    LOAD_STAGE(1, 32);
    LOAD_STAGE(2, 64);

    int nk = K >> 5;
    for (int kt = 0; kt < nk; kt++) {
        int rem = nk - 1 - kt;
        if (rem >= 2)      asm volatile("cp.async.wait_group 2;\n");
        else if (rem == 1) asm volatile("cp.async.wait_group 1;\n");
        else               asm volatile("cp.async.wait_group 0;\n");
        __syncthreads();

        if (kt + 3 < nk) {
            LOAD_STAGE((kt + 3) & 3, (kt + 3) << 5);
        }

        const __half* as = As + (kt & 3) * ASZ;
        const __half* bs = Bs + (kt & 3) * BSZ;

        #pragma unroll
        for (int kf = 0; kf < 2; kf++) {
            wmma::fragment<wmma::matrix_a, 16, 16, 16, __half, wmma::row_major> af[4];
            wmma::fragment<wmma::matrix_b, 16, 16, 16, __half, wmma::row_major> bf[4];
            #pragma unroll
            for (int i = 0; i < 4; i++)
                wmma::load_matrix_sync(af[i], &as[(wm * 64 + i * 16) * A_LD + kf * 16], A_LD);
            #pragma unroll
            for (int j = 0; j < 4; j++)
                wmma::load_matrix_sync(bf[j], &bs[(kf * 16) * B_LD + wn * 64 + j * 16], B_LD);
            #pragma unroll
            for (int i = 0; i < 4; i++)
                #pragma unroll
                for (int j = 0; j < 4; j++)
                    wmma::mma_sync(acc[i][j], af[i], bf[j], acc[i][j]);
        }
    }

    #pragma unroll
    for (int i = 0; i < 4; i++)
        #pragma unroll
        for (int j = 0; j < 4; j++)
            wmma::store_matrix_sync(&C[(size_t)(m0 + wm * 64 + i * 16) * N + n0 + wn * 64 + j * 16],
                                    acc[i][j], N, wmma::mem_row_major);
    #undef LOAD_STAGE
}

// ---------------- fp16 GEMM v2: block 128x192, warp 64x48, 4-stage (QKV; better wave fit) ----------------
#define A_LD2 40
#define B_LD2 200
#define ASZ2 (128 * A_LD2)
#define BSZ2 (32 * B_LD2)
#define G2_SMEM_BYTES (GS * (ASZ2 + BSZ2) * 2)

__global__ void __launch_bounds__(256, 1) gemm_hp192(const __half* __restrict__ A,
                                                     const __half* __restrict__ B,
                                                     float* __restrict__ C,
                                                     int M, int N, int K) {
    extern __shared__ __half hsm[];
    __half* As = hsm;
    __half* Bs = hsm + GS * ASZ2;

    int tid = threadIdx.x;
    int n0 = blockIdx.x * 192;
    int m0 = blockIdx.y * 128;
    int w = tid >> 5;
    int wm = w >> 2;    // 0..1 : 64 rows
    int wn = w & 3;     // 0..3 : 48 cols

    wmma::fragment<wmma::accumulator, 16, 16, 16, float> acc[4][3];
    #pragma unroll
    for (int i = 0; i < 4; i++)
        #pragma unroll
        for (int j = 0; j < 3; j++) wmma::fill_fragment(acc[i][j], 0.0f);

    #define LOAD_STAGE2(st, kk)                                                         \
        {                                                                               \
            __half* as_ = As + (st) * ASZ2;                                             \
            __half* bs_ = Bs + (st) * BSZ2;                                             \
            _Pragma("unroll")                                                           \
            for (int i = 0; i < 2; i++) {                                               \
                int c = tid + 256 * i;                                                  \
                int r = c >> 2, c8 = (c & 3) * 8;                                       \
                cpa16(&as_[r * A_LD2 + c8], &A[(size_t)(m0 + r) * K + (kk) + c8]);      \
            }                                                                           \
            _Pragma("unroll")                                                           \
            for (int i = 0; i < 3; i++) {                                               \
                int c = tid + 256 * i;                                                  \
                int r = c / 24, cc = (c % 24) * 8;                                      \
                cpa16(&bs_[r * B_LD2 + cc], &B[(size_t)((kk) + r) * N + n0 + cc]);      \
            }                                                                           \
            asm volatile("cp.async.commit_group;\n");                                   \
        }

    LOAD_STAGE2(0, 0);
    LOAD_STAGE2(1, 32);
    LOAD_STAGE2(2, 64);

    int nk = K >> 5;
    for (int kt = 0; kt < nk; kt++) {
        int rem = nk - 1 - kt;
        if (rem >= 2)      asm volatile("cp.async.wait_group 2;\n");
        else if (rem == 1) asm volatile("cp.async.wait_group 1;\n");
        else               asm volatile("cp.async.wait_group 0;\n");
        __syncthreads();

        if (kt + 3 < nk) {
            LOAD_STAGE2((kt + 3) & 3, (kt + 3) << 5);
        }

        const __half* as = As + (kt & 3) * ASZ2;
        const __half* bs = Bs + (kt & 3) * BSZ2;

        #pragma unroll
        for (int kf = 0; kf < 2; kf++) {
            wmma::fragment<wmma::matrix_a, 16, 16, 16, __half, wmma::row_major> af[4];
            wmma::fragment<wmma::matrix_b, 16, 16, 16, __half, wmma::row_major> bf[3];
            #pragma unroll
            for (int i = 0; i < 4; i++)
                wmma::load_matrix_sync(af[i], &as[(wm * 64 + i * 16) * A_LD2 + kf * 16], A_LD2);
            #pragma unroll
            for (int j = 0; j < 3; j++)
                wmma::load_matrix_sync(bf[j], &bs[(kf * 16) * B_LD2 + wn * 48 + j * 16], B_LD2);
            #pragma unroll
            for (int i = 0; i < 4; i++)
                #pragma unroll
                for (int j = 0; j < 3; j++)
                    wmma::mma_sync(acc[i][j], af[i], bf[j], acc[i][j]);
        }
    }

    #pragma unroll
    for (int i = 0; i < 4; i++)
        #pragma unroll
        for (int j = 0; j < 3; j++)
            wmma::store_matrix_sync(&C[(size_t)(m0 + wm * 64 + i * 16) * N + n0 + wn * 48 + j * 16],
                                    acc[i][j], N, wmma::mem_row_major);
    #undef LOAD_STAGE2
}

// ---------------- scatter + rotary: one thread handles the (d, d+64) pair ----------------
__global__ void __launch_bounds__(256) scatter_rotary_kernel(const float* __restrict__ cache,
                                                             float* __restrict__ kv_out) {
    int idx = blockIdx.x * 256 + threadIdx.x;    // 2^21 threads
    int d4 = (idx & 15) * 4;                     // 0..60
    int j  = (idx >> 4) & 2047;
    int h  = (idx >> 15) & 15;
    int b  = idx >> 19;

    float4 cl = *(const float4*)&g_cos[j * DD + d4];
    float4 ch = *(const float4*)&g_cos[j * DD + d4 + 64];
    float4 sl = *(const float4*)&g_sin[j * DD + d4];
    float4 sh = *(const float4*)&g_sin[j * DD + d4 + 64];

    float4 kl, kh, vl, vh;
    if (j < 1024) {
        const float* ckb = cache + (((size_t)(b * 2 + 0) * HH + h) * 1024 + j) * DD;
        const float* cvb = cache + (((size_t)(b * 2 + 1) * HH + h) * 1024 + j) * DD;
        kl = *(const float4*)(ckb + d4);
        kh = *(const float4*)(ckb + d4 + 64);
        vl = *(const float4*)(cvb + d4);
        vh = *(const float4*)(cvb + d4 + 64);
    } else {
        int rrow = b * NN + (j - 1024);
        const float* qr = g_qkv + (size_t)rrow * NQKV;
        kl = *(const float4*)(qr + 2048 + h * DD + d4);
        kh = *(const float4*)(qr + 2048 + h * DD + d4 + 64);
        vl = *(const float4*)(qr + 4096 + h * DD + d4);
        vh = *(const float4*)(qr + 4096 + h * DD + d4 + 64);
        float4 ql = *(const float4*)(qr + h * DD + d4);
        float4 qh = *(const float4*)(qr + h * DD + d4 + 64);
        size_t qidx = (((size_t)(b * HH + h) * NN + (j - 1024)) * DD) + d4;
        uint2 qlo, qhi;
        qlo.x = f2h2(ql.x * cl.x - qh.x * sl.x, ql.y * cl.y - qh.y * sl.y);
        qlo.y = f2h2(ql.z * cl.z - qh.z * sl.z, ql.w * cl.w - qh.w * sl.w);
        qhi.x = f2h2(qh.x * ch.x + ql.x * sh.x, qh.y * ch.y + ql.y * sh.y);
        qhi.y = f2h2(qh.z * ch.z + ql.z * sh.z, qh.w * ch.w + ql.w * sh.w);
        *(uint2*)&g_qrot[qidx]      = qlo;
        *(uint2*)&g_qrot[qidx + 64] = qhi;
    }

    size_t kvidx = ((size_t)(b * HH + h) * JJ + j) * DD + d4;
    uint2 klo, khi, vlo, vhi;
    klo.x = f2h2(kl.x * cl.x - kh.x * sl.x, kl.y * cl.y - kh.y * sl.y);
    klo.y = f2h2(kl.z * cl.z - kh.z * sl.z, kl.w * cl.w - kh.w * sl.w);
    khi.x = f2h2(kh.x * ch.x + kl.x * sh.x, kh.y * ch.y + kl.y * sh.y);
    khi.y = f2h2(kh.z * ch.z + kl.z * sh.z, kh.w * ch.w + kl.w * sh.w);
    vlo.x = f2h2(vl.x, vl.y);  vlo.y = f2h2(vl.z, vl.w);
    vhi.x = f2h2(vh.x, vh.y);  vhi.y = f2h2(vh.z, vh.w);
    *(uint2*)&g_krot[kvidx]       = klo;
    *(uint2*)&g_krot[kvidx + 64]  = khi;
    *(uint2*)&g_vfull[kvidx]      = vlo;
    *(uint2*)&g_vfull[kvidx + 64] = vhi;

    float* ko = &kv_out[(((size_t)(b * 2 + 0) * HH + h) * JJ + j) * DD + d4];
    float* vo = &kv_out[(((size_t)(b * 2 + 1) * HH + h) * JJ + j) * DD + d4];
    *(float4*)(ko)      = kl;
    *(float4*)(ko + 64) = kh;
    *(float4*)(vo)      = vl;
    *(float4*)(vo + 64) = vh;
}

// ---------------- flash attention: register-resident, ldmatrix ----------------
#define KLD 136
#define TILE_H (128 * KLD)
#define AT_SMEM_BYTES (5 * TILE_H * 2 + 2 * 128 * 4)

__global__ void __launch_bounds__(256, 1) attn_kernel(const int* __restrict__ mask) {
    extern __shared__ char asmem[];
    __half* Qs = (__half*)asmem;
    __half* Kb[2] = { Qs + 1 * TILE_H, Qs + 3 * TILE_H };
    __half* Vb[2] = { Qs + 2 * TILE_H, Qs + 4 * TILE_H };
    int* Ms = (int*)(Qs + 5 * TILE_H);

    int tid = threadIdx.x;
    int w = tid >> 5;
    int lane = tid & 31;
    int g = lane >> 2;
    int t2 = (lane & 3) * 2;

    int bid = blockIdx.x;
    int b  = bid & 3;
    int h  = (bid >> 2) & 15;
    int qb = 7 - (bid >> 6);
    int m0 = qb * 128;

    const __half* qp = g_qrot + ((size_t)(b * HH + h) * NN + m0) * DD;
    const __half* kp = g_krot + (size_t)(b * HH + h) * JJ * DD;
    const __half* vp = g_vfull + (size_t)(b * HH + h) * JJ * DD;
    const int* mrow = mask + (size_t)b * JJ;

    int nt = qb + 9;

    #pragma unroll
    for (int i = tid; i < 128 * 16; i += 256) {
        int r = i >> 4, c8 = (i & 15) * 8;
        *(float4*)&Qs[r * KLD + c8] = *(const float4*)&qp[(size_t)r * DD + c8];
    }
    if (tid < 128) Ms[tid] = mrow[tid];
    #pragma unroll
    for (int i = tid; i < 128 * 16; i += 256) {
        int r = i >> 4, c8 = (i & 15) * 8;
        cpa16(&Kb[0][r * KLD + c8], &kp[(size_t)r * DD + c8]);
    }
    asm volatile("cp.async.commit_group;\n");
    #pragma unroll
    for (int i = tid; i < 128 * 16; i += 256) {
        int r = i >> 4, c8 = (i & 15) * 8;
        cpa16(&Vb[0][r * KLD + c8], &vp[(size_t)r * DD + c8]);
    }
    asm volatile("cp.async.commit_group;\n");
    __syncthreads();

    uint32_t qa[8][4];
    int qr0 = (w * 16 + g) * KLD;
    int qr1 = (w * 16 + g + 8) * KLD;
    #pragma unroll
    for (int ks = 0; ks < 8; ks++) {
        qa[ks][0] = *(uint32_t*)&Qs[qr0 + ks * 16 + t2];
        qa[ks][1] = *(uint32_t*)&Qs[qr1 + ks * 16 + t2];
        qa[ks][2] = *(uint32_t*)&Qs[qr0 + ks * 16 + t2 + 8];
        qa[ks][3] = *(uint32_t*)&Qs[qr1 + ks * 16 + t2 + 8];
    }

    float oc[16][4];
    #pragma unroll
    for (int n = 0; n < 16; n++)
        #pragma unroll
        for (int i = 0; i < 4; i++) oc[n][i] = 0.0f;

    float m0r = -1e30f, m1r = -1e30f;
    float l0 = 0.0f, l1 = 0.0f;
    int row0 = m0 + w * 16 + g;
    int rowlim0 = row0 + 1024;
    int rowlim1 = rowlim0 + 8;
    const float scale = 0.08838834764831845f;

    uint32_t koff = ((lane & 7) * KLD + (lane >> 3) * 8) * 2;
    uint32_t voff = ((((lane >> 3) & 1) * 8 + (lane & 7)) * KLD + (lane >> 4) * 8) * 2;

    for (int kt = 0; kt < nt; kt++) {
        asm volatile("cp.async.wait_group 0;\n");
        __syncthreads();

        if (tid < 128 && kt + 1 < nt) Ms[((kt + 1) & 1) * 128 + tid] = mrow[(kt + 1) * 128 + tid];

        if (kt + 1 < nt) {
            int bn = (kt + 1) & 1;
            #pragma unroll
            for (int i = tid; i < 128 * 16; i += 256) {
                int r = i >> 4, c8 = (i & 15) * 8;
                cpa16(&Kb[bn][r * KLD + c8], &kp[(size_t)((kt + 1) * 128 + r) * DD + c8]);
            }
            asm volatile("cp.async.commit_group;\n");
            #pragma unroll
            for (int i = tid; i < 128 * 16; i += 256) {
                int r = i >> 4, c8 = (i & 15) * 8;
                cpa16(&Vb[bn][r * KLD + c8], &vp[(size_t)((kt + 1) * 128 + r) * DD + c8]);
            }
            asm volatile("cp.async.commit_group;\n");
        }

        const __half* Kt = Kb[kt & 1];
        const __half* Vt = Vb[kt & 1];
        const int* Mt = Ms + (kt & 1) * 128;

        float sc[16][4];
        #pragma unroll
        for (int n = 0; n < 16; n++)
            #pragma unroll
            for (int i = 0; i < 4; i++) sc[n][i] = 0.0f;

        uint32_t ktu = smem_u32(Kt) + koff;
        #pragma unroll
        for (int ksp = 0; ksp < 4; ksp++) {
            #pragma unroll
            for (int nb = 0; nb < 16; nb++) {
                uint32_t br[4];
                ldsm4(br, ktu + (uint32_t)(nb * 8 * KLD + ksp * 32) * 2);
                mma16816(sc[nb], qa[2 * ksp],     br[0], br[1]);
                mma16816(sc[nb], qa[2 * ksp + 1], br[2], br[3]);
            }
        }

        bool lastt = (kt == nt - 1);
        float mx0 = -1e30f, mx1 = -1e30f;
        #pragma unroll
        for (int nb = 0; nb < 16; nb++) {
            int col = kt * 128 + nb * 8 + t2;
            int2 mv = *(const int2*)&Mt[nb * 8 + t2];
            float v0 = sc[nb][0] * scale;
            float v1 = sc[nb][1] * scale;
            float v2 = sc[nb][2] * scale;
            float v3 = sc[nb][3] * scale;
            if (mv.x == 0) { v0 = -1e30f; v2 = -1e30f; }
            if (mv.y == 0) { v1 = -1e30f; v3 = -1e30f; }
            if (lastt) {
                if (col     > rowlim0) v0 = -1e30f;
                if (col + 1 > rowlim0) v1 = -1e30f;
                if (col     > rowlim1) v2 = -1e30f;
                if (col + 1 > rowlim1) v3 = -1e30f;
            }
            sc[nb][0] = v0; sc[nb][1] = v1; sc[nb][2] = v2; sc[nb][3] = v3;
            mx0 = fmaxf(mx0, fmaxf(v0, v1));
            mx1 = fmaxf(mx1, fmaxf(v2, v3));
        }
        mx0 = fmaxf(mx0, __shfl_xor_sync(0xffffffffu, mx0, 1));
        mx0 = fmaxf(mx0, __shfl_xor_sync(0xffffffffu, mx0, 2));
        mx1 = fmaxf(mx1, __shfl_xor_sync(0xffffffffu, mx1, 1));
        mx1 = fmaxf(mx1, __shfl_xor_sync(0xffffffffu, mx1, 2));

        float mn0 = fmaxf(m0r, mx0), mn1 = fmaxf(m1r, mx1);
        float al0 = __expf(m0r - mn0), al1 = __expf(m1r - mn1);
        m0r = mn0; m1r = mn1;

        float s0 = 0.0f, s1 = 0.0f;
        #pragma unroll
        for (int nb = 0; nb < 16; nb++) {
            float p0 = __expf(sc[nb][0] - mn0);
            float p1 = __expf(sc[nb][1] - mn0);
            float p2 = __expf(sc[nb][2] - mn1);
            float p3 = __expf(sc[nb][3] - mn1);
            sc[nb][0] = p0; sc[nb][1] = p1; sc[nb][2] = p2; sc[nb][3] = p3;
            s0 += p0 + p1; s1 += p2 + p3;
        }
        l0 = l0 * al0 + s0;
        l1 = l1 * al1 + s1;
        #pragma unroll
        for (int n = 0; n < 16; n++) {
            oc[n][0] *= al0; oc[n][1] *= al0;
            oc[n][2] *= al1; oc[n][3] *= al1;
        }

        uint32_t vtu = smem_u32(Vt) + voff;
        #pragma unroll
        for (int kk = 0; kk < 8; kk++) {
            uint32_t pa[4];
            pa[0] = f2h2(sc[2 * kk][0],     sc[2 * kk][1]);
            pa[1] = f2h2(sc[2 * kk][2],     sc[2 * kk][3]);
            pa[2] = f2h2(sc[2 * kk + 1][0], sc[2 * kk + 1][1]);
            pa[3] = f2h2(sc[2 * kk + 1][2], sc[2 * kk + 1][3]);
            #pragma unroll
            for (int ndp = 0; ndp < 8; ndp++) {
                uint32_t br[4];
                ldsm4t(br, vtu + (uint32_t)(kk * 16 * KLD + ndp * 16) * 2);
                mma16816(oc[2 * ndp],     pa, br[0], br[1]);
                mma16816(oc[2 * ndp + 1], pa, br[2], br[3]);
            }
        }
    }

    l0 += __shfl_xor_sync(0xffffffffu, l0, 1);
    l0 += __shfl_xor_sync(0xffffffffu, l0, 2);
    l1 += __shfl_xor_sync(0xffffffffu, l1, 1);
    l1 += __shfl_xor_sync(0xffffffffu, l1, 2);
    float inv0 = 1.0f / l0, inv1 = 1.0f / l1;

    __half* out0 = g_attnout + (size_t)(b * NN + row0) * DIMM + h * DD;
    __half* out1 = out0 + (size_t)8 * DIMM;
    #pragma unroll
    for (int nd = 0; nd < 16; nd++) {
        *(uint32_t*)&out0[nd * 8 + t2] = f2h2(oc[nd][0] * inv0, oc[nd][1] * inv0);
        *(uint32_t*)&out1[nd * 8 + t2] = f2h2(oc[nd][2] * inv1, oc[nd][3] * inv1);
    }
}

// ---------------- launch ----------------
extern "C" void kernel_launch(void* const* d_in, const int* in_sizes, int n_in,
                              void* d_out, int out_size) {
    const float* x       = (const float*)d_in[0];
    const float* cache   = (const float*)d_in[1];
    const float* rotary  = (const float*)d_in[2];
    const int*   mask    = (const int*)d_in[3];
    const float* norm_w  = (const float*)d_in[4];
    const float* w_qkv   = (const float*)d_in[5];
    const float* w_out   = (const float*)d_in[6];

    float* out    = (float*)d_out;
    float* kv_out = out + (size_t)ROWS * DIMM;

    __half *xn_ptr, *wqkv_ptr, *wout_ptr, *ao_ptr;
    float *qkv_ptr;
    cudaGetSymbolAddress((void**)&xn_ptr, g_xn);
    cudaGetSymbolAddress((void**)&qkv_ptr, g_qkv);
    cudaGetSymbolAddress((void**)&ao_ptr, g_attnout);
    cudaGetSymbolAddress((void**)&wqkv_ptr, g_wqkv_h);
    cudaGetSymbolAddress((void**)&wout_ptr, g_wout_h);

    cudaFuncSetAttribute(attn_kernel, cudaFuncAttributeMaxDynamicSharedMemorySize, AT_SMEM_BYTES);
    cudaFuncSetAttribute(gemm_hp, cudaFuncAttributeMaxDynamicSharedMemorySize, G_SMEM_BYTES);
    cudaFuncSetAttribute(gemm_hp192, cudaFuncAttributeMaxDynamicSharedMemorySize, G2_SMEM_BYTES);

    convert_h_kernel<<<(DIMM * NQKV / 4 + 255) / 256, 256>>>(w_qkv, wqkv_ptr, DIMM * NQKV);
    convert_h_kernel<<<(DIMM * DIMM / 4 + 255) / 256, 256>>>(w_out, wout_ptr, DIMM * DIMM);

    rope_table_kernel<<<(JJ * DD) / 256, 256>>>(rotary);
    rmsnorm_kernel<<<ROWS, 256>>>(x, norm_w);

    gemm_hp192<<<dim3(NQKV / 192, ROWS / 128), 256, G2_SMEM_BYTES>>>(xn_ptr, wqkv_ptr, qkv_ptr,
                                                                     ROWS, NQKV, DIMM);

    scatter_rotary_kernel<<<(BB * HH * JJ * 16) / 256, 256>>>(cache, kv_out);

    attn_kernel<<<BB * HH * (NN / 128), 256, AT_SMEM_BYTES>>>(mask);

    gemm_hp<<<dim3(DIMM / 256, ROWS / 128), 256, G_SMEM_BYTES>>>(ao_ptr, wout_ptr, out,
                                                                 ROWS, DIMM, DIMM);
}

// round 13
// speedup vs baseline: 6.2971x; 1.0224x over previous
#include <cuda_runtime.h>
#include <cuda_fp16.h>
#include <mma.h>
#include <cstdint>

using namespace nvcuda;

#define BB 4
#define NN 1024
#define JJ 2048
#define HH 16
#define DD 128
#define DIMM 2048
#define NQKV 6144
#define ROWS 4096

__device__ __half g_xn[(size_t)ROWS * DIMM];
__device__ __half g_qkv_h[(size_t)ROWS * NQKV];
__device__ __half g_qrot[(size_t)BB * HH * NN * DD];
__device__ __half g_krot[(size_t)BB * HH * JJ * DD];
__device__ __half g_vfull[(size_t)BB * HH * JJ * DD];
__device__ __half g_attnout[(size_t)ROWS * DIMM];
__device__ __half g_wqkv_h[(size_t)DIMM * NQKV];
__device__ __half g_wout_h[(size_t)DIMM * DIMM];
__device__ float  g_cos[JJ * DD];
__device__ float  g_sin[JJ * DD];

__device__ __forceinline__ void cpa16(void* smem, const void* gmem) {
    unsigned s = (unsigned)__cvta_generic_to_shared(smem);
    asm volatile("cp.async.cg.shared.global [%0], [%1], 16;\n" :: "r"(s), "l"(gmem));
}

__device__ __forceinline__ uint32_t smem_u32(const void* p) {
    uint32_t a;
    asm("{ .reg .u64 t; cvta.to.shared.u64 t, %1; cvt.u32.u64 %0, t; }" : "=r"(a) : "l"(p));
    return a;
}

__device__ __forceinline__ void ldsm4(uint32_t* r, uint32_t a) {
    asm volatile("ldmatrix.sync.aligned.m8n8.x4.shared.b16 {%0,%1,%2,%3}, [%4];"
                 : "=r"(r[0]), "=r"(r[1]), "=r"(r[2]), "=r"(r[3]) : "r"(a));
}
__device__ __forceinline__ void ldsm4t(uint32_t* r, uint32_t a) {
    asm volatile("ldmatrix.sync.aligned.m8n8.x4.trans.shared.b16 {%0,%1,%2,%3}, [%4];"
                 : "=r"(r[0]), "=r"(r[1]), "=r"(r[2]), "=r"(r[3]) : "r"(a));
}

__device__ __forceinline__ void mma16816(float* c, const uint32_t* a, uint32_t b0, uint32_t b1) {
    asm volatile(
        "mma.sync.aligned.m16n8k16.row.col.f32.f16.f16.f32 "
        "{%0,%1,%2,%3}, {%4,%5,%6,%7}, {%8,%9}, {%0,%1,%2,%3};"
        : "+f"(c[0]), "+f"(c[1]), "+f"(c[2]), "+f"(c[3])
        : "r"(a[0]), "r"(a[1]), "r"(a[2]), "r"(a[3]), "r"(b0), "r"(b1));
}

__device__ __forceinline__ uint32_t f2h2(float x, float y) {
    __half2 h = __floats2half2_rn(x, y);
    return *(uint32_t*)&h;
}

__device__ __forceinline__ float4 ld_half4(const __half* p) {
    uint2 u = *(const uint2*)p;
    __half2 a = *(__half2*)&u.x, b = *(__half2*)&u.y;
    float2 fa = __half22float2(a), fb = __half22float2(b);
    return make_float4(fa.x, fa.y, fb.x, fb.y);
}

// ---------------- merged prep: convert wqkv, convert wout, rope table ----------------
#define PREP_WQKV_BLKS 12288   // 2048*6144/4/256
#define PREP_WOUT_BLKS 4096    // 2048*2048/4/256
#define PREP_ROPE_BLKS 256     // 2048*128/4/256
#define PREP_BLKS (PREP_WQKV_BLKS + PREP_WOUT_BLKS + PREP_ROPE_BLKS)

__global__ void __launch_bounds__(256) prep_kernel(const float* __restrict__ rot,
                                                   const float* __restrict__ wqkv,
                                                   const float* __restrict__ wout) {
    int bid = blockIdx.x;
    if (bid < PREP_WQKV_BLKS) {
        int idx = (bid * 256 + threadIdx.x) * 4;
        float4 v = *(const float4*)(wqkv + idx);
        *(__half2*)(g_wqkv_h + idx)     = __floats2half2_rn(v.x, v.y);
        *(__half2*)(g_wqkv_h + idx + 2) = __floats2half2_rn(v.z, v.w);
    } else if (bid < PREP_WQKV_BLKS + PREP_WOUT_BLKS) {
        int idx = ((bid - PREP_WQKV_BLKS) * 256 + threadIdx.x) * 4;
        float4 v = *(const float4*)(wout + idx);
        *(__half2*)(g_wout_h + idx)     = __floats2half2_rn(v.x, v.y);
        *(__half2*)(g_wout_h + idx + 2) = __floats2half2_rn(v.z, v.w);
    } else {
        int idx = ((bid - PREP_WQKV_BLKS - PREP_WOUT_BLKS) * 256 + threadIdx.x) * 4;
        float4 p = *(const float4*)(rot + idx);
        *(float4*)&g_cos[idx] = make_float4(cosf(p.x), cosf(p.y), cosf(p.z), cosf(p.w));
        *(float4*)&g_sin[idx] = make_float4(sinf(p.x), sinf(p.y), sinf(p.z), sinf(p.w));
    }
}

// ---------------- rmsnorm: register-resident single pass ----------------
__global__ void __launch_bounds__(256) rmsnorm_kernel(const float* __restrict__ x,
                                                      const float* __restrict__ w) {
    int row = blockIdx.x;
    int tid = threadIdx.x;
    const float4* xr = (const float4*)(x + (size_t)row * DIMM);
    float4 a = xr[tid];
    float4 b = xr[tid + 256];
    float ss = a.x * a.x + a.y * a.y + a.z * a.z + a.w * a.w
             + b.x * b.x + b.y * b.y + b.z * b.z + b.w * b.w;
    #pragma unroll
    for (int o = 16; o; o >>= 1) ss += __shfl_xor_sync(0xffffffffu, ss, o);
    __shared__ float red[8];
    if ((tid & 31) == 0) red[tid >> 5] = ss;
    __syncthreads();
    float tot = red[0] + red[1] + red[2] + red[3] + red[4] + red[5] + red[6] + red[7];
    float inv = rsqrtf(tot * (1.0f / (float)DIMM) + 1.1920929e-7f);

    const float4* wr = (const float4*)w;
    float4 wa = wr[tid];
    float4 wb = wr[tid + 256];
    uint2 o0, o1;
    o0.x = f2h2(a.x * inv * wa.x, a.y * inv * wa.y);
    o0.y = f2h2(a.z * inv * wa.z, a.w * inv * wa.w);
    o1.x = f2h2(b.x * inv * wb.x, b.y * inv * wb.y);
    o1.y = f2h2(b.z * inv * wb.z, b.w * inv * wb.w);
    *(uint2*)&g_xn[(size_t)row * DIMM + tid * 4]        = o0;
    *(uint2*)&g_xn[(size_t)row * DIMM + 1024 + tid * 4] = o1;
}

// ---------------- fp16 GEMM v1: block 128x256, warp 64x64, 4-stage (out-proj, fp32 out) ----------------
#define GS 4
#define A_LD 40
#define B_LD 264
#define ASZ (128 * A_LD)
#define BSZ (32 * B_LD)
#define G_SMEM_BYTES (GS * (ASZ + BSZ) * 2)

__global__ void __launch_bounds__(256, 1) gemm_hp(const __half* __restrict__ A,
                                                  const __half* __restrict__ B,
                                                  float* __restrict__ C,
                                                  int M, int N, int K) {
    extern __shared__ __half hsm[];
    __half* As = hsm;
    __half* Bs = hsm + GS * ASZ;

    int tid = threadIdx.x;
    int n0 = blockIdx.x * 256;
    int m0 = blockIdx.y * 128;
    int w = tid >> 5;
    int wm = w >> 2;
    int wn = w & 3;

    wmma::fragment<wmma::accumulator, 16, 16, 16, float> acc[4][4];
    #pragma unroll
    for (int i = 0; i < 4; i++)
        #pragma unroll
        for (int j = 0; j < 4; j++) wmma::fill_fragment(acc[i][j], 0.0f);

    #define LOAD_STAGE(st, kk)                                                          \
        {                                                                               \
            __half* as_ = As + (st) * ASZ;                                              \
            __half* bs_ = Bs + (st) * BSZ;                                              \
            _Pragma("unroll")                                                           \
            for (int i = 0; i < 2; i++) {                                               \
                int c = tid + 256 * i;                                                  \
                int r = c >> 2, c8 = (c & 3) * 8;                                       \
                cpa16(&as_[r * A_LD + c8], &A[(size_t)(m0 + r) * K + (kk) + c8]);       \
            }                                                                           \
            _Pragma("unroll")                                                           \
            for (int i = 0; i < 4; i++) {                                               \
                int c = tid + 256 * i;                                                  \
                int r = c >> 5, c8 = (c & 31) * 8;                                      \
                cpa16(&bs_[r * B_LD + c8], &B[(size_t)((kk) + r) * N + n0 + c8]);       \
            }                                                                           \
            asm volatile("cp.async.commit_group;\n");                                   \
        }

    LOAD_STAGE(0, 0);
    LOAD_STAGE(1, 32);
    LOAD_STAGE(2, 64);

    int nk = K >> 5;
    for (int kt = 0; kt < nk; kt++) {
        int rem = nk - 1 - kt;
        if (rem >= 2)      asm volatile("cp.async.wait_group 2;\n");
        else if (rem == 1) asm volatile("cp.async.wait_group 1;\n");
        else               asm volatile("cp.async.wait_group 0;\n");
        __syncthreads();

        if (kt + 3 < nk) {
            LOAD_STAGE((kt + 3) & 3, (kt + 3) << 5);
        }

        const __half* as = As + (kt & 3) * ASZ;
        const __half* bs = Bs + (kt & 3) * BSZ;

        #pragma unroll
        for (int kf = 0; kf < 2; kf++) {
            wmma::fragment<wmma::matrix_a, 16, 16, 16, __half, wmma::row_major> af[4];
            wmma::fragment<wmma::matrix_b, 16, 16, 16, __half, wmma::row_major> bf[4];
            #pragma unroll
            for (int i = 0; i < 4; i++)
                wmma::load_matrix_sync(af[i], &as[(wm * 64 + i * 16) * A_LD + kf * 16], A_LD);
            #pragma unroll
            for (int j = 0; j < 4; j++)
                wmma::load_matrix_sync(bf[j], &bs[(kf * 16) * B_LD + wn * 64 + j * 16], B_LD);
            #pragma unroll
            for (int i = 0; i < 4; i++)
                #pragma unroll
                for (int j = 0; j < 4; j++)
                    wmma::mma_sync(acc[i][j], af[i], bf[j], acc[i][j]);
        }
    }

    #pragma unroll
    for (int i = 0; i < 4; i++)
        #pragma unroll
        for (int j = 0; j < 4; j++)
            wmma::store_matrix_sync(&C[(size_t)(m0 + wm * 64 + i * 16) * N + n0 + wn * 64 + j * 16],
                                    acc[i][j], N, wmma::mem_row_major);
    #undef LOAD_STAGE
}

// ---------------- fp16 GEMM v2: block 128x192, warp 64x48, 4-stage (QKV; half output) ----------------
#define A_LD2 40
#define B_LD2 200
#define ASZ2 (128 * A_LD2)
#define BSZ2 (32 * B_LD2)
#define G2_SMEM_BYTES (GS * (ASZ2 + BSZ2) * 2)

__global__ void __launch_bounds__(256, 1) gemm_hp192(const __half* __restrict__ A,
                                                     const __half* __restrict__ B,
                                                     __half* __restrict__ C,
                                                     int M, int N, int K) {
    extern __shared__ __half hsm[];
    __half* As = hsm;
    __half* Bs = hsm + GS * ASZ2;

    int tid = threadIdx.x;
    int lane = tid & 31;
    int n0 = blockIdx.x * 192;
    int m0 = blockIdx.y * 128;
    int w = tid >> 5;
    int wm = w >> 2;    // 0..1 : 64 rows
    int wn = w & 3;     // 0..3 : 48 cols

    wmma::fragment<wmma::accumulator, 16, 16, 16, float> acc[4][3];
    #pragma unroll
    for (int i = 0; i < 4; i++)
        #pragma unroll
        for (int j = 0; j < 3; j++) wmma::fill_fragment(acc[i][j], 0.0f);

    #define LOAD_STAGE2(st, kk)                                                         \
        {                                                                               \
            __half* as_ = As + (st) * ASZ2;                                             \
            __half* bs_ = Bs + (st) * BSZ2;                                             \
            _Pragma("unroll")                                                           \
            for (int i = 0; i < 2; i++) {                                               \
                int c = tid + 256 * i;                                                  \
                int r = c >> 2, c8 = (c & 3) * 8;                                       \
                cpa16(&as_[r * A_LD2 + c8], &A[(size_t)(m0 + r) * K + (kk) + c8]);      \
            }                                                                           \
            _Pragma("unroll")                                                           \
            for (int i = 0; i < 3; i++) {                                               \
                int c = tid + 256 * i;                                                  \
                int r = c / 24, cc = (c % 24) * 8;                                      \
                cpa16(&bs_[r * B_LD2 + cc], &B[(size_t)((kk) + r) * N + n0 + cc]);      \
            }                                                                           \
            asm volatile("cp.async.commit_group;\n");                                   \
        }

    LOAD_STAGE2(0, 0);
    LOAD_STAGE2(1, 32);
    LOAD_STAGE2(2, 64);

    int nk = K >> 5;
    for (int kt = 0; kt < nk; kt++) {
        int rem = nk - 1 - kt;
        if (rem >= 2)      asm volatile("cp.async.wait_group 2;\n");
        else if (rem == 1) asm volatile("cp.async.wait_group 1;\n");
        else               asm volatile("cp.async.wait_group 0;\n");
        __syncthreads();

        if (kt + 3 < nk) {
            LOAD_STAGE2((kt + 3) & 3, (kt + 3) << 5);
        }

        const __half* as = As + (kt & 3) * ASZ2;
        const __half* bs = Bs + (kt & 3) * BSZ2;

        #pragma unroll
        for (int kf = 0; kf < 2; kf++) {
            wmma::fragment<wmma::matrix_a, 16, 16, 16, __half, wmma::row_major> af[4];
            wmma::fragment<wmma::matrix_b, 16, 16, 16, __half, wmma::row_major> bf[3];
            #pragma unroll
            for (int i = 0; i < 4; i++)
                wmma::load_matrix_sync(af[i], &as[(wm * 64 + i * 16) * A_LD2 + kf * 16], A_LD2);
            #pragma unroll
            for (int j = 0; j < 3; j++)
                wmma::load_matrix_sync(bf[j], &bs[(kf * 16) * B_LD2 + wn * 48 + j * 16], B_LD2);
            #pragma unroll
            for (int i = 0; i < 4; i++)
                #pragma unroll
                for (int j = 0; j < 3; j++)
                    wmma::mma_sync(acc[i][j], af[i], bf[j], acc[i][j]);
        }
    }

    // epilogue: per-warp smem staging, convert fp32 -> half, vectorized store
    __syncthreads();   // all warps done reading stage buffers
    float* stage = (float*)hsm + w * (16 * 52);
    #pragma unroll
    for (int i = 0; i < 4; i++) {
        #pragma unroll
        for (int j = 0; j < 3; j++)
            wmma::store_matrix_sync(stage + j * 16, acc[i][j], 52, wmma::mem_row_major);
        __syncwarp();
        int rbase = m0 + wm * 64 + i * 16;
        #pragma unroll
        for (int e = 0; e < 12; e++) {
            int idx = lane + e * 32;            // 0..383 = 16 rows x 24 half2
            int r = idx / 24, c2 = (idx % 24) * 2;
            float x0 = stage[r * 52 + c2];
            float x1 = stage[r * 52 + c2 + 1];
            *(uint32_t*)&C[(size_t)(rbase + r) * N + n0 + wn * 48 + c2] = f2h2(x0, x1);
        }
        __syncwarp();
    }
    #undef LOAD_STAGE2
}

// ---------------- scatter + rotary: half qkv input, (d, d+64) pair per thread ----------------
__global__ void __launch_bounds__(256) scatter_rotary_kernel(const float* __restrict__ cache,
                                                             float* __restrict__ kv_out) {
    int idx = blockIdx.x * 256 + threadIdx.x;    // 2^21 threads
    int d4 = (idx & 15) * 4;                     // 0..60
    int j  = (idx >> 4) & 2047;
    int h  = (idx >> 15) & 15;
    int b  = idx >> 19;

    float4 cl = *(const float4*)&g_cos[j * DD + d4];
    float4 ch = *(const float4*)&g_cos[j * DD + d4 + 64];
    float4 sl = *(const float4*)&g_sin[j * DD + d4];
    float4 sh = *(const float4*)&g_sin[j * DD + d4 + 64];

    float4 kl, kh, vl, vh;
    if (j < 1024) {
        const float* ckb = cache + (((size_t)(b * 2 + 0) * HH + h) * 1024 + j) * DD;
        const float* cvb = cache + (((size_t)(b * 2 + 1) * HH + h) * 1024 + j) * DD;
        kl = *(const float4*)(ckb + d4);
        kh = *(const float4*)(ckb + d4 + 64);
        vl = *(const float4*)(cvb + d4);
        vh = *(const float4*)(cvb + d4 + 64);
    } else {
        int rrow = b * NN + (j - 1024);
        const __half* qr = g_qkv_h + (size_t)rrow * NQKV;
        kl = ld_half4(qr + 2048 + h * DD + d4);
        kh = ld_half4(qr + 2048 + h * DD + d4 + 64);
        vl = ld_half4(qr + 4096 + h * DD + d4);
        vh = ld_half4(qr + 4096 + h * DD + d4 + 64);
        float4 ql = ld_half4(qr + h * DD + d4);
        float4 qh = ld_half4(qr + h * DD + d4 + 64);
        size_t qidx = (((size_t)(b * HH + h) * NN + (j - 1024)) * DD) + d4;
        uint2 qlo, qhi;
        qlo.x = f2h2(ql.x * cl.x - qh.x * sl.x, ql.y * cl.y - qh.y * sl.y);
        qlo.y = f2h2(ql.z * cl.z - qh.z * sl.z, ql.w * cl.w - qh.w * sl.w);
        qhi.x = f2h2(qh.x * ch.x + ql.x * sh.x, qh.y * ch.y + ql.y * sh.y);
        qhi.y = f2h2(qh.z * ch.z + ql.z * sh.z, qh.w * ch.w + ql.w * sh.w);
        *(uint2*)&g_qrot[qidx]      = qlo;
        *(uint2*)&g_qrot[qidx + 64] = qhi;
    }

    size_t kvidx = ((size_t)(b * HH + h) * JJ + j) * DD + d4;
    uint2 klo, khi, vlo, vhi;
    klo.x = f2h2(kl.x * cl.x - kh.x * sl.x, kl.y * cl.y - kh.y * sl.y);
    klo.y = f2h2(kl.z * cl.z - kh.z * sl.z, kl.w * cl.w - kh.w * sl.w);
    khi.x = f2h2(kh.x * ch.x + kl.x * sh.x, kh.y * ch.y + kl.y * sh.y);
    khi.y = f2h2(kh.z * ch.z + kl.z * sh.z, kh.w * ch.w + kl.w * sh.w);
    vlo.x = f2h2(vl.x, vl.y);  vlo.y = f2h2(vl.z, vl.w);
    vhi.x = f2h2(vh.x, vh.y);  vhi.y = f2h2(vh.z, vh.w);
    *(uint2*)&g_krot[kvidx]       = klo;
    *(uint2*)&g_krot[kvidx + 64]  = khi;
    *(uint2*)&g_vfull[kvidx]      = vlo;
    *(uint2*)&g_vfull[kvidx + 64] = vhi;

    float* ko = &kv_out[(((size_t)(b * 2 + 0) * HH + h) * JJ + j) * DD + d4];
    float* vo = &kv_out[(((size_t)(b * 2 + 1) * HH + h) * JJ + j) * DD + d4];
    *(float4*)(ko)      = kl;
    *(float4*)(ko + 64) = kh;
    *(float4*)(vo)      = vl;
    *(float4*)(vo + 64) = vh;
}

// ---------------- flash attention: register-resident, ldmatrix ----------------
#define KLD 136
#define TILE_H (128 * KLD)
#define AT_SMEM_BYTES (5 * TILE_H * 2 + 2 * 128 * 4)

__global__ void __launch_bounds__(256, 1) attn_kernel(const int* __restrict__ mask) {
    extern __shared__ char asmem[];
    __half* Qs = (__half*)asmem;
    __half* Kb[2] = { Qs + 1 * TILE_H, Qs + 3 * TILE_H };
    __half* Vb[2] = { Qs + 2 * TILE_H, Qs + 4 * TILE_H };
    int* Ms = (int*)(Qs + 5 * TILE_H);

    int tid = threadIdx.x;
    int w = tid >> 5;
    int lane = tid & 31;
    int g = lane >> 2;
    int t2 = (lane & 3) * 2;

    int bid = blockIdx.x;
    int b  = bid & 3;
    int h  = (bid >> 2) & 15;
    int qb = 7 - (bid >> 6);
    int m0 = qb * 128;

    const __half* qp = g_qrot + ((size_t)(b * HH + h) * NN + m0) * DD;
    const __half* kp = g_krot + (size_t)(b * HH + h) * JJ * DD;
    const __half* vp = g_vfull + (size_t)(b * HH + h) * JJ * DD;
    const int* mrow = mask + (size_t)b * JJ;

    int nt = qb + 9;

    #pragma unroll
    for (int i = tid; i < 128 * 16; i += 256) {
        int r = i >> 4, c8 = (i & 15) * 8;
        *(float4*)&Qs[r * KLD + c8] = *(const float4*)&qp[(size_t)r * DD + c8];
    }
    if (tid < 128) Ms[tid] = mrow[tid];
    #pragma unroll
    for (int i = tid; i < 128 * 16; i += 256) {
        int r = i >> 4, c8 = (i & 15) * 8;
        cpa16(&Kb[0][r * KLD + c8], &kp[(size_t)r * DD + c8]);
    }
    asm volatile("cp.async.commit_group;\n");
    #pragma unroll
    for (int i = tid; i < 128 * 16; i += 256) {
        int r = i >> 4, c8 = (i & 15) * 8;
        cpa16(&Vb[0][r * KLD + c8], &vp[(size_t)r * DD + c8]);
    }
    asm volatile("cp.async.commit_group;\n");
    __syncthreads();

    uint32_t qa[8][4];
    int qr0 = (w * 16 + g) * KLD;
    int qr1 = (w * 16 + g + 8) * KLD;
    #pragma unroll
    for (int ks = 0; ks < 8; ks++) {
        qa[ks][0] = *(uint32_t*)&Qs[qr0 + ks * 16 + t2];
        qa[ks][1] = *(uint32_t*)&Qs[qr1 + ks * 16 + t2];
        qa[ks][2] = *(uint32_t*)&Qs[qr0 + ks * 16 + t2 + 8];
        qa[ks][3] = *(uint32_t*)&Qs[qr1 + ks * 16 + t2 + 8];
    }

    float oc[16][4];
    #pragma unroll
    for (int n = 0; n < 16; n++)
        #pragma unroll
        for (int i = 0; i < 4; i++) oc[n][i] = 0.0f;

    float m0r = -1e30f, m1r = -1e30f;
    float l0 = 0.0f, l1 = 0.0f;
    int row0 = m0 + w * 16 + g;
    int rowlim0 = row0 + 1024;
    int rowlim1 = rowlim0 + 8;
    const float scale = 0.08838834764831845f;

    uint32_t koff = ((lane & 7) * KLD + (lane >> 3) * 8) * 2;
    uint32_t voff = ((((lane >> 3) & 1) * 8 + (lane & 7)) * KLD + (lane >> 4) * 8) * 2;

    for (int kt = 0; kt < nt; kt++) {
        asm volatile("cp.async.wait_group 0;\n");
        __syncthreads();

        if (tid < 128 && kt + 1 < nt) Ms[((kt + 1) & 1) * 128 + tid] = mrow[(kt + 1) * 128 + tid];

        if (kt + 1 < nt) {
            int bn = (kt + 1) & 1;
            #pragma unroll
            for (int i = tid; i < 128 * 16; i += 256) {
                int r = i >> 4, c8 = (i & 15) * 8;
                cpa16(&Kb[bn][r * KLD + c8], &kp[(size_t)((kt + 1) * 128 + r) * DD + c8]);
            }
            asm volatile("cp.async.commit_group;\n");
            #pragma unroll
            for (int i = tid; i < 128 * 16; i += 256) {
                int r = i >> 4, c8 = (i & 15) * 8;
                cpa16(&Vb[bn][r * KLD + c8], &vp[(size_t)((kt + 1) * 128 + r) * DD + c8]);
            }
            asm volatile("cp.async.commit_group;\n");
        }

        const __half* Kt = Kb[kt & 1];
        const __half* Vt = Vb[kt & 1];
        const int* Mt = Ms + (kt & 1) * 128;

        float sc[16][4];
        #pragma unroll
        for (int n = 0; n < 16; n++)
            #pragma unroll
            for (int i = 0; i < 4; i++) sc[n][i] = 0.0f;

        uint32_t ktu = smem_u32(Kt) + koff;
        #pragma unroll
        for (int ksp = 0; ksp < 4; ksp++) {
            #pragma unroll
            for (int nb = 0; nb < 16; nb++) {
                uint32_t br[4];
                ldsm4(br, ktu + (uint32_t)(nb * 8 * KLD + ksp * 32) * 2);
                mma16816(sc[nb], qa[2 * ksp],     br[0], br[1]);
                mma16816(sc[nb], qa[2 * ksp + 1], br[2], br[3]);
            }
        }

        bool lastt = (kt == nt - 1);
        float mx0 = -1e30f, mx1 = -1e30f;
        #pragma unroll
        for (int nb = 0; nb < 16; nb++) {
            int col = kt * 128 + nb * 8 + t2;
            int2 mv = *(const int2*)&Mt[nb * 8 + t2];
            float v0 = sc[nb][0] * scale;
            float v1 = sc[nb][1] * scale;
            float v2 = sc[nb][2] * scale;
            float v3 = sc[nb][3] * scale;
            if (mv.x == 0) { v0 = -1e30f; v2 = -1e30f; }
            if (mv.y == 0) { v1 = -1e30f; v3 = -1e30f; }
            if (lastt) {
                if (col     > rowlim0) v0 = -1e30f;
                if (col + 1 > rowlim0) v1 = -1e30f;
                if (col     > rowlim1) v2 = -1e30f;
                if (col + 1 > rowlim1) v3 = -1e30f;
            }
            sc[nb][0] = v0; sc[nb][1] = v1; sc[nb][2] = v2; sc[nb][3] = v3;
            mx0 = fmaxf(mx0, fmaxf(v0, v1));
            mx1 = fmaxf(mx1, fmaxf(v2, v3));
        }
        mx0 = fmaxf(mx0, __shfl_xor_sync(0xffffffffu, mx0, 1));
        mx0 = fmaxf(mx0, __shfl_xor_sync(0xffffffffu, mx0, 2));
        mx1 = fmaxf(mx1, __shfl_xor_sync(0xffffffffu, mx1, 1));
        mx1 = fmaxf(mx1, __shfl_xor_sync(0xffffffffu, mx1, 2));

        float mn0 = fmaxf(m0r, mx0), mn1 = fmaxf(m1r, mx1);
        float al0 = __expf(m0r - mn0), al1 = __expf(m1r - mn1);
        m0r = mn0; m1r = mn1;

        float s0 = 0.0f, s1 = 0.0f;
        #pragma unroll
        for (int nb = 0; nb < 16; nb++) {
            float p0 = __expf(sc[nb][0] - mn0);
            float p1 = __expf(sc[nb][1] - mn0);
            float p2 = __expf(sc[nb][2] - mn1);
            float p3 = __expf(sc[nb][3] - mn1);
            sc[nb][0] = p0; sc[nb][1] = p1; sc[nb][2] = p2; sc[nb][3] = p3;
            s0 += p0 + p1; s1 += p2 + p3;
        }
        l0 = l0 * al0 + s0;
        l1 = l1 * al1 + s1;
        #pragma unroll
        for (int n = 0; n < 16; n++) {
            oc[n][0] *= al0; oc[n][1] *= al0;
            oc[n][2] *= al1; oc[n][3] *= al1;
        }

        uint32_t vtu = smem_u32(Vt) + voff;
        #pragma unroll
        for (int kk = 0; kk < 8; kk++) {
            uint32_t pa[4];
            pa[0] = f2h2(sc[2 * kk][0],     sc[2 * kk][1]);
            pa[1] = f2h2(sc[2 * kk][2],     sc[2 * kk][3]);
            pa[2] = f2h2(sc[2 * kk + 1][0], sc[2 * kk + 1][1]);
            pa[3] = f2h2(sc[2 * kk + 1][2], sc[2 * kk + 1][3]);
            #pragma unroll
            for (int ndp = 0; ndp < 8; ndp++) {
                uint32_t br[4];
                ldsm4t(br, vtu + (uint32_t)(kk * 16 * KLD + ndp * 16) * 2);
                mma16816(oc[2 * ndp],     pa, br[0], br[1]);
                mma16816(oc[2 * ndp + 1], pa, br[2], br[3]);
            }
        }
    }

    l0 += __shfl_xor_sync(0xffffffffu, l0, 1);
    l0 += __shfl_xor_sync(0xffffffffu, l0, 2);
    l1 += __shfl_xor_sync(0xffffffffu, l1, 1);
    l1 += __shfl_xor_sync(0xffffffffu, l1, 2);
    float inv0 = 1.0f / l0, inv1 = 1.0f / l1;

    __half* out0 = g_attnout + (size_t)(b * NN + row0) * DIMM + h * DD;
    __half* out1 = out0 + (size_t)8 * DIMM;
    #pragma unroll
    for (int nd = 0; nd < 16; nd++) {
        *(uint32_t*)&out0[nd * 8 + t2] = f2h2(oc[nd][0] * inv0, oc[nd][1] * inv0);
        *(uint32_t*)&out1[nd * 8 + t2] = f2h2(oc[nd][2] * inv1, oc[nd][3] * inv1);
    }
}

// ---------------- launch ----------------
extern "C" void kernel_launch(void* const* d_in, const int* in_sizes, int n_in,
                              void* d_out, int out_size) {
    const float* x       = (const float*)d_in[0];
    const float* cache   = (const float*)d_in[1];
    const float* rotary  = (const float*)d_in[2];
    const int*   mask    = (const int*)d_in[3];
    const float* norm_w  = (const float*)d_in[4];
    const float* w_qkv   = (const float*)d_in[5];
    const float* w_out   = (const float*)d_in[6];

    float* out    = (float*)d_out;
    float* kv_out = out + (size_t)ROWS * DIMM;

    __half *xn_ptr, *wqkv_ptr, *wout_ptr, *ao_ptr, *qkvh_ptr;
    cudaGetSymbolAddress((void**)&xn_ptr, g_xn);
    cudaGetSymbolAddress((void**)&qkvh_ptr, g_qkv_h);
    cudaGetSymbolAddress((void**)&ao_ptr, g_attnout);
    cudaGetSymbolAddress((void**)&wqkv_ptr, g_wqkv_h);
    cudaGetSymbolAddress((void**)&wout_ptr, g_wout_h);

    cudaFuncSetAttribute(attn_kernel, cudaFuncAttributeMaxDynamicSharedMemorySize, AT_SMEM_BYTES);
    cudaFuncSetAttribute(gemm_hp, cudaFuncAttributeMaxDynamicSharedMemorySize, G_SMEM_BYTES);
    cudaFuncSetAttribute(gemm_hp192, cudaFuncAttributeMaxDynamicSharedMemorySize, G2_SMEM_BYTES);

    prep_kernel<<<PREP_BLKS, 256>>>(rotary, w_qkv, w_out);

    rmsnorm_kernel<<<ROWS, 256>>>(x, norm_w);

    gemm_hp192<<<dim3(NQKV / 192, ROWS / 128), 256, G2_SMEM_BYTES>>>(xn_ptr, wqkv_ptr, qkvh_ptr,
                                                                     ROWS, NQKV, DIMM);

    scatter_rotary_kernel<<<(BB * HH * JJ * 16) / 256, 256>>>(cache, kv_out);

    attn_kernel<<<BB * HH * (NN / 128), 256, AT_SMEM_BYTES>>>(mask);

    gemm_hp<<<dim3(DIMM / 256, ROWS / 128), 256, G_SMEM_BYTES>>>(ao_ptr, wout_ptr, out,
                                                                 ROWS, DIMM, DIMM);
}

// round 14
// speedup vs baseline: 6.6761x; 1.0602x over previous
#include <cuda_runtime.h>
#include <cuda_fp16.h>
#include <mma.h>
#include <cstdint>

using namespace nvcuda;

#define BB 4
#define NN 1024
#define JJ 2048
#define HH 16
#define DD 128
#define DIMM 2048
#define NQKV 6144
#define ROWS 4096

__device__ __half g_xn[(size_t)ROWS * DIMM];
__device__ __half g_qkv_h[(size_t)ROWS * NQKV];
__device__ __half g_qrot[(size_t)BB * HH * NN * DD];
__device__ __half g_krot[(size_t)BB * HH * JJ * DD];
__device__ __half g_vfull[(size_t)BB * HH * JJ * DD];
__device__ __half g_attnout[(size_t)ROWS * DIMM];
__device__ __half g_wqkv_h[(size_t)DIMM * NQKV];
__device__ __half g_wout_h[(size_t)DIMM * DIMM];
__device__ float  g_cos[JJ * DD];
__device__ float  g_sin[JJ * DD];

__device__ __forceinline__ void cpa16(void* smem, const void* gmem) {
    unsigned s = (unsigned)__cvta_generic_to_shared(smem);
    asm volatile("cp.async.cg.shared.global [%0], [%1], 16;\n" :: "r"(s), "l"(gmem));
}

__device__ __forceinline__ uint32_t smem_u32(const void* p) {
    uint32_t a;
    asm("{ .reg .u64 t; cvta.to.shared.u64 t, %1; cvt.u32.u64 %0, t; }" : "=r"(a) : "l"(p));
    return a;
}

__device__ __forceinline__ void ldsm4(uint32_t* r, uint32_t a) {
    asm volatile("ldmatrix.sync.aligned.m8n8.x4.shared.b16 {%0,%1,%2,%3}, [%4];"
                 : "=r"(r[0]), "=r"(r[1]), "=r"(r[2]), "=r"(r[3]) : "r"(a));
}
__device__ __forceinline__ void ldsm4t(uint32_t* r, uint32_t a) {
    asm volatile("ldmatrix.sync.aligned.m8n8.x4.trans.shared.b16 {%0,%1,%2,%3}, [%4];"
                 : "=r"(r[0]), "=r"(r[1]), "=r"(r[2]), "=r"(r[3]) : "r"(a));
}

__device__ __forceinline__ void mma16816(float* c, const uint32_t* a, uint32_t b0, uint32_t b1) {
    asm volatile(
        "mma.sync.aligned.m16n8k16.row.col.f32.f16.f16.f32 "
        "{%0,%1,%2,%3}, {%4,%5,%6,%7}, {%8,%9}, {%0,%1,%2,%3};"
        : "+f"(c[0]), "+f"(c[1]), "+f"(c[2]), "+f"(c[3])
        : "r"(a[0]), "r"(a[1]), "r"(a[2]), "r"(a[3]), "r"(b0), "r"(b1));
}

__device__ __forceinline__ uint32_t f2h2(float x, float y) {
    __half2 h = __floats2half2_rn(x, y);
    return *(uint32_t*)&h;
}

__device__ __forceinline__ float4 ld_half4(const __half* p) {
    uint2 u = *(const uint2*)p;
    __half2 a = *(__half2*)&u.x, b = *(__half2*)&u.y;
    float2 fa = __half22float2(a), fb = __half22float2(b);
    return make_float4(fa.x, fa.y, fb.x, fb.y);
}

// ---------------- merged prep: weight converts + rope table + rmsnorm ----------------
#define PREP_WQKV_BLKS 12288   // 2048*6144/4/256
#define PREP_WOUT_BLKS 4096    // 2048*2048/4/256
#define PREP_ROPE_BLKS 256     // 2048*128/4/256
#define PREP_CONV_BLKS (PREP_WQKV_BLKS + PREP_WOUT_BLKS + PREP_ROPE_BLKS)
#define PREP_BLKS (PREP_CONV_BLKS + ROWS)

__global__ void __launch_bounds__(256) prep_kernel(const float* __restrict__ rot,
                                                   const float* __restrict__ wqkv,
                                                   const float* __restrict__ wout,
                                                   const float* __restrict__ x,
                                                   const float* __restrict__ w) {
    int bid = blockIdx.x;
    int tid = threadIdx.x;
    if (bid < PREP_WQKV_BLKS) {
        int idx = (bid * 256 + tid) * 4;
        float4 v = *(const float4*)(wqkv + idx);
        *(__half2*)(g_wqkv_h + idx)     = __floats2half2_rn(v.x, v.y);
        *(__half2*)(g_wqkv_h + idx + 2) = __floats2half2_rn(v.z, v.w);
    } else if (bid < PREP_WQKV_BLKS + PREP_WOUT_BLKS) {
        int idx = ((bid - PREP_WQKV_BLKS) * 256 + tid) * 4;
        float4 v = *(const float4*)(wout + idx);
        *(__half2*)(g_wout_h + idx)     = __floats2half2_rn(v.x, v.y);
        *(__half2*)(g_wout_h + idx + 2) = __floats2half2_rn(v.z, v.w);
    } else if (bid < PREP_CONV_BLKS) {
        int idx = ((bid - PREP_WQKV_BLKS - PREP_WOUT_BLKS) * 256 + tid) * 4;
        float4 p = *(const float4*)(rot + idx);
        *(float4*)&g_cos[idx] = make_float4(cosf(p.x), cosf(p.y), cosf(p.z), cosf(p.w));
        *(float4*)&g_sin[idx] = make_float4(sinf(p.x), sinf(p.y), sinf(p.z), sinf(p.w));
    } else {
        // rmsnorm: one row per block
        int row = bid - PREP_CONV_BLKS;
        const float4* xr = (const float4*)(x + (size_t)row * DIMM);
        float4 a = xr[tid];
        float4 b = xr[tid + 256];
        float ss = a.x * a.x + a.y * a.y + a.z * a.z + a.w * a.w
                 + b.x * b.x + b.y * b.y + b.z * b.z + b.w * b.w;
        #pragma unroll
        for (int o = 16; o; o >>= 1) ss += __shfl_xor_sync(0xffffffffu, ss, o);
        __shared__ float red[8];
        if ((tid & 31) == 0) red[tid >> 5] = ss;
        __syncthreads();
        float tot = red[0] + red[1] + red[2] + red[3] + red[4] + red[5] + red[6] + red[7];
        float inv = rsqrtf(tot * (1.0f / (float)DIMM) + 1.1920929e-7f);

        const float4* wr = (const float4*)w;
        float4 wa = wr[tid];
        float4 wb = wr[tid + 256];
        uint2 o0, o1;
        o0.x = f2h2(a.x * inv * wa.x, a.y * inv * wa.y);
        o0.y = f2h2(a.z * inv * wa.z, a.w * inv * wa.w);
        o1.x = f2h2(b.x * inv * wb.x, b.y * inv * wb.y);
        o1.y = f2h2(b.z * inv * wb.z, b.w * inv * wb.w);
        *(uint2*)&g_xn[(size_t)row * DIMM + tid * 4]        = o0;
        *(uint2*)&g_xn[(size_t)row * DIMM + 1024 + tid * 4] = o1;
    }
}

// ---------------- fp16 GEMM v1: block 128x256, warp 64x64, KSTEP 64, 4-stage (out-proj, fp32 out) ----------------
#define GS 4
#define A_LD 72
#define B_LD 264
#define ASZ (128 * A_LD)
#define BSZ (64 * B_LD)
#define G_SMEM_BYTES (GS * (ASZ + BSZ) * 2)

__global__ void __launch_bounds__(256, 1) gemm_hp(const __half* __restrict__ A,
                                                  const __half* __restrict__ B,
                                                  float* __restrict__ C,
                                                  int M, int N, int K) {
    extern __shared__ __half hsm[];
    __half* As = hsm;
    __half* Bs = hsm + GS * ASZ;

    int tid = threadIdx.x;
    int n0 = blockIdx.x * 256;
    int m0 = blockIdx.y * 128;
    int w = tid >> 5;
    int wm = w >> 2;
    int wn = w & 3;

    wmma::fragment<wmma::accumulator, 16, 16, 16, float> acc[4][4];
    #pragma unroll
    for (int i = 0; i < 4; i++)
        #pragma unroll
        for (int j = 0; j < 4; j++) wmma::fill_fragment(acc[i][j], 0.0f);

    #define LOAD_STAGE(st, kk)                                                          \
        {                                                                               \
            __half* as_ = As + (st) * ASZ;                                              \
            __half* bs_ = Bs + (st) * BSZ;                                              \
            _Pragma("unroll")                                                           \
            for (int i = 0; i < 4; i++) {                                               \
                int c = tid + 256 * i;                                                  \
                int r = c >> 3, c8 = (c & 7) * 8;                                       \
                cpa16(&as_[r * A_LD + c8], &A[(size_t)(m0 + r) * K + (kk) + c8]);       \
            }                                                                           \
            _Pragma("unroll")                                                           \
            for (int i = 0; i < 8; i++) {                                               \
                int c = tid + 256 * i;                                                  \
                int r = c >> 5, c8 = (c & 31) * 8;                                      \
                cpa16(&bs_[r * B_LD + c8], &B[(size_t)((kk) + r) * N + n0 + c8]);       \
            }                                                                           \
            asm volatile("cp.async.commit_group;\n");                                   \
        }

    LOAD_STAGE(0, 0);
    LOAD_STAGE(1, 64);
    LOAD_STAGE(2, 128);

    int nk = K >> 6;
    for (int kt = 0; kt < nk; kt++) {
        int rem = nk - 1 - kt;
        if (rem >= 2)      asm volatile("cp.async.wait_group 2;\n");
        else if (rem == 1) asm volatile("cp.async.wait_group 1;\n");
        else               asm volatile("cp.async.wait_group 0;\n");
        __syncthreads();

        if (kt + 3 < nk) {
            LOAD_STAGE((kt + 3) & 3, (kt + 3) << 6);
        }

        const __half* as = As + (kt & 3) * ASZ;
        const __half* bs = Bs + (kt & 3) * BSZ;

        #pragma unroll
        for (int kf = 0; kf < 4; kf++) {
            wmma::fragment<wmma::matrix_a, 16, 16, 16, __half, wmma::row_major> af[4];
            wmma::fragment<wmma::matrix_b, 16, 16, 16, __half, wmma::row_major> bf[4];
            #pragma unroll
            for (int i = 0; i < 4; i++)
                wmma::load_matrix_sync(af[i], &as[(wm * 64 + i * 16) * A_LD + kf * 16], A_LD);
            #pragma unroll
            for (int j = 0; j < 4; j++)
                wmma::load_matrix_sync(bf[j], &bs[(kf * 16) * B_LD + wn * 64 + j * 16], B_LD);
            #pragma unroll
            for (int i = 0; i < 4; i++)
                #pragma unroll
                for (int j = 0; j < 4; j++)
                    wmma::mma_sync(acc[i][j], af[i], bf[j], acc[i][j]);
        }
    }

    #pragma unroll
    for (int i = 0; i < 4; i++)
        #pragma unroll
        for (int j = 0; j < 4; j++)
            wmma::store_matrix_sync(&C[(size_t)(m0 + wm * 64 + i * 16) * N + n0 + wn * 64 + j * 16],
                                    acc[i][j], N, wmma::mem_row_major);
    #undef LOAD_STAGE
}

// ---------------- fp16 GEMM v2: block 128x192, warp 64x48, KSTEP 64, 4-stage (QKV; half output) ----------------
#define A_LD2 72
#define B_LD2 200
#define ASZ2 (128 * A_LD2)
#define BSZ2 (64 * B_LD2)
#define G2_SMEM_BYTES (GS * (ASZ2 + BSZ2) * 2)

__global__ void __launch_bounds__(256, 1) gemm_hp192(const __half* __restrict__ A,
                                                     const __half* __restrict__ B,
                                                     __half* __restrict__ C,
                                                     int M, int N, int K) {
    extern __shared__ __half hsm[];
    __half* As = hsm;
    __half* Bs = hsm + GS * ASZ2;

    int tid = threadIdx.x;
    int lane = tid & 31;
    int n0 = blockIdx.x * 192;
    int m0 = blockIdx.y * 128;
    int w = tid >> 5;
    int wm = w >> 2;    // 0..1 : 64 rows
    int wn = w & 3;     // 0..3 : 48 cols

    wmma::fragment<wmma::accumulator, 16, 16, 16, float> acc[4][3];
    #pragma unroll
    for (int i = 0; i < 4; i++)
        #pragma unroll
        for (int j = 0; j < 3; j++) wmma::fill_fragment(acc[i][j], 0.0f);

    #define LOAD_STAGE2(st, kk)                                                         \
        {                                                                               \
            __half* as_ = As + (st) * ASZ2;                                             \
            __half* bs_ = Bs + (st) * BSZ2;                                             \
            _Pragma("unroll")                                                           \
            for (int i = 0; i < 4; i++) {                                               \
                int c = tid + 256 * i;                                                  \
                int r = c >> 3, c8 = (c & 7) * 8;                                       \
                cpa16(&as_[r * A_LD2 + c8], &A[(size_t)(m0 + r) * K + (kk) + c8]);      \
            }                                                                           \
            _Pragma("unroll")                                                           \
            for (int i = 0; i < 6; i++) {                                               \
                int c = tid + 256 * i;                                                  \
                int r = c / 24, cc = (c % 24) * 8;                                      \
                cpa16(&bs_[r * B_LD2 + cc], &B[(size_t)((kk) + r) * N + n0 + cc]);      \
            }                                                                           \
            asm volatile("cp.async.commit_group;\n");                                   \
        }

    LOAD_STAGE2(0, 0);
    LOAD_STAGE2(1, 64);
    LOAD_STAGE2(2, 128);

    int nk = K >> 6;
    for (int kt = 0; kt < nk; kt++) {
        int rem = nk - 1 - kt;
        if (rem >= 2)      asm volatile("cp.async.wait_group 2;\n");
        else if (rem == 1) asm volatile("cp.async.wait_group 1;\n");
        else               asm volatile("cp.async.wait_group 0;\n");
        __syncthreads();

        if (kt + 3 < nk) {
            LOAD_STAGE2((kt + 3) & 3, (kt + 3) << 6);
        }

        const __half* as = As + (kt & 3) * ASZ2;
        const __half* bs = Bs + (kt & 3) * BSZ2;

        #pragma unroll
        for (int kf = 0; kf < 4; kf++) {
            wmma::fragment<wmma::matrix_a, 16, 16, 16, __half, wmma::row_major> af[4];
            wmma::fragment<wmma::matrix_b, 16, 16, 16, __half, wmma::row_major> bf[3];
            #pragma unroll
            for (int i = 0; i < 4; i++)
                wmma::load_matrix_sync(af[i], &as[(wm * 64 + i * 16) * A_LD2 + kf * 16], A_LD2);
            #pragma unroll
            for (int j = 0; j < 3; j++)
                wmma::load_matrix_sync(bf[j], &bs[(kf * 16) * B_LD2 + wn * 48 + j * 16], B_LD2);
            #pragma unroll
            for (int i = 0; i < 4; i++)
                #pragma unroll
                for (int j = 0; j < 3; j++)
                    wmma::mma_sync(acc[i][j], af[i], bf[j], acc[i][j]);
        }
    }

    // epilogue: per-warp smem staging, convert fp32 -> half, vectorized store
    __syncthreads();   // all warps done reading stage buffers
    float* stage = (float*)hsm + w * (16 * 52);
    #pragma unroll
    for (int i = 0; i < 4; i++) {
        #pragma unroll
        for (int j = 0; j < 3; j++)
            wmma::store_matrix_sync(stage + j * 16, acc[i][j], 52, wmma::mem_row_major);
        __syncwarp();
        int rbase = m0 + wm * 64 + i * 16;
        #pragma unroll
        for (int e = 0; e < 12; e++) {
            int idx = lane + e * 32;            // 0..383 = 16 rows x 24 half2
            int r = idx / 24, c2 = (idx % 24) * 2;
            float x0 = stage[r * 52 + c2];
            float x1 = stage[r * 52 + c2 + 1];
            *(uint32_t*)&C[(size_t)(rbase + r) * N + n0 + wn * 48 + c2] = f2h2(x0, x1);
        }
        __syncwarp();
    }
    #undef LOAD_STAGE2
}

// ---------------- scatter + rotary: half qkv input, (d, d+64) pair per thread ----------------
__global__ void __launch_bounds__(256) scatter_rotary_kernel(const float* __restrict__ cache,
                                                             float* __restrict__ kv_out) {
    int idx = blockIdx.x * 256 + threadIdx.x;    // 2^21 threads
    int d4 = (idx & 15) * 4;                     // 0..60
    int j  = (idx >> 4) & 2047;
    int h  = (idx >> 15) & 15;
    int b  = idx >> 19;

    float4 cl = *(const float4*)&g_cos[j * DD + d4];
    float4 ch = *(const float4*)&g_cos[j * DD + d4 + 64];
    float4 sl = *(const float4*)&g_sin[j * DD + d4];
    float4 sh = *(const float4*)&g_sin[j * DD + d4 + 64];

    float4 kl, kh, vl, vh;
    if (j < 1024) {
        const float* ckb = cache + (((size_t)(b * 2 + 0) * HH + h) * 1024 + j) * DD;
        const float* cvb = cache + (((size_t)(b * 2 + 1) * HH + h) * 1024 + j) * DD;
        kl = *(const float4*)(ckb + d4);
        kh = *(const float4*)(ckb + d4 + 64);
        vl = *(const float4*)(cvb + d4);
        vh = *(const float4*)(cvb + d4 + 64);
    } else {
        int rrow = b * NN + (j - 1024);
        const __half* qr = g_qkv_h + (size_t)rrow * NQKV;
        kl = ld_half4(qr + 2048 + h * DD + d4);
        kh = ld_half4(qr + 2048 + h * DD + d4 + 64);
        vl = ld_half4(qr + 4096 + h * DD + d4);
        vh = ld_half4(qr + 4096 + h * DD + d4 + 64);
        float4 ql = ld_half4(qr + h * DD + d4);
        float4 qh = ld_half4(qr + h * DD + d4 + 64);
        size_t qidx = (((size_t)(b * HH + h) * NN + (j - 1024)) * DD) + d4;
        uint2 qlo, qhi;
        qlo.x = f2h2(ql.x * cl.x - qh.x * sl.x, ql.y * cl.y - qh.y * sl.y);
        qlo.y = f2h2(ql.z * cl.z - qh.z * sl.z, ql.w * cl.w - qh.w * sl.w);
        qhi.x = f2h2(qh.x * ch.x + ql.x * sh.x, qh.y * ch.y + ql.y * sh.y);
        qhi.y = f2h2(qh.z * ch.z + ql.z * sh.z, qh.w * ch.w + ql.w * sh.w);
        *(uint2*)&g_qrot[qidx]      = qlo;
        *(uint2*)&g_qrot[qidx + 64] = qhi;
    }

    size_t kvidx = ((size_t)(b * HH + h) * JJ + j) * DD + d4;
    uint2 klo, khi, vlo, vhi;
    klo.x = f2h2(kl.x * cl.x - kh.x * sl.x, kl.y * cl.y - kh.y * sl.y);
    klo.y = f2h2(kl.z * cl.z - kh.z * sl.z, kl.w * cl.w - kh.w * sl.w);
    khi.x = f2h2(kh.x * ch.x + kl.x * sh.x, kh.y * ch.y + kl.y * sh.y);
    khi.y = f2h2(kh.z * ch.z + kl.z * sh.z, kh.w * ch.w + kl.w * sh.w);
    vlo.x = f2h2(vl.x, vl.y);  vlo.y = f2h2(vl.z, vl.w);
    vhi.x = f2h2(vh.x, vh.y);  vhi.y = f2h2(vh.z, vh.w);
    *(uint2*)&g_krot[kvidx]       = klo;
    *(uint2*)&g_krot[kvidx + 64]  = khi;
    *(uint2*)&g_vfull[kvidx]      = vlo;
    *(uint2*)&g_vfull[kvidx + 64] = vhi;

    float* ko = &kv_out[(((size_t)(b * 2 + 0) * HH + h) * JJ + j) * DD + d4];
    float* vo = &kv_out[(((size_t)(b * 2 + 1) * HH + h) * JJ + j) * DD + d4];
    *(float4*)(ko)      = kl;
    *(float4*)(ko + 64) = kh;
    *(float4*)(vo)      = vl;
    *(float4*)(vo + 64) = vh;
}

// ---------------- flash attention: register-resident, ldmatrix ----------------
#define KLD 136
#define TILE_H (128 * KLD)
#define AT_SMEM_BYTES (5 * TILE_H * 2 + 2 * 128 * 4)

__global__ void __launch_bounds__(256, 1) attn_kernel(const int* __restrict__ mask) {
    extern __shared__ char asmem[];
    __half* Qs = (__half*)asmem;
    __half* Kb[2] = { Qs + 1 * TILE_H, Qs + 3 * TILE_H };
    __half* Vb[2] = { Qs + 2 * TILE_H, Qs + 4 * TILE_H };
    int* Ms = (int*)(Qs + 5 * TILE_H);

    int tid = threadIdx.x;
    int w = tid >> 5;
    int lane = tid & 31;
    int g = lane >> 2;
    int t2 = (lane & 3) * 2;

    int bid = blockIdx.x;
    int b  = bid & 3;
    int h  = (bid >> 2) & 15;
    int qb = 7 - (bid >> 6);
    int m0 = qb * 128;

    const __half* qp = g_qrot + ((size_t)(b * HH + h) * NN + m0) * DD;
    const __half* kp = g_krot + (size_t)(b * HH + h) * JJ * DD;
    const __half* vp = g_vfull + (size_t)(b * HH + h) * JJ * DD;
    const int* mrow = mask + (size_t)b * JJ;

    int nt = qb + 9;

    #pragma unroll
    for (int i = tid; i < 128 * 16; i += 256) {
        int r = i >> 4, c8 = (i & 15) * 8;
        *(float4*)&Qs[r * KLD + c8] = *(const float4*)&qp[(size_t)r * DD + c8];
    }
    if (tid < 128) Ms[tid] = mrow[tid];
    #pragma unroll
    for (int i = tid; i < 128 * 16; i += 256) {
        int r = i >> 4, c8 = (i & 15) * 8;
        cpa16(&Kb[0][r * KLD + c8], &kp[(size_t)r * DD + c8]);
    }
    asm volatile("cp.async.commit_group;\n");
    #pragma unroll
    for (int i = tid; i < 128 * 16; i += 256) {
        int r = i >> 4, c8 = (i & 15) * 8;
        cpa16(&Vb[0][r * KLD + c8], &vp[(size_t)r * DD + c8]);
    }
    asm volatile("cp.async.commit_group;\n");
    __syncthreads();

    uint32_t qa[8][4];
    int qr0 = (w * 16 + g) * KLD;
    int qr1 = (w * 16 + g + 8) * KLD;
    #pragma unroll
    for (int ks = 0; ks < 8; ks++) {
        qa[ks][0] = *(uint32_t*)&Qs[qr0 + ks * 16 + t2];
        qa[ks][1] = *(uint32_t*)&Qs[qr1 + ks * 16 + t2];
        qa[ks][2] = *(uint32_t*)&Qs[qr0 + ks * 16 + t2 + 8];
        qa[ks][3] = *(uint32_t*)&Qs[qr1 + ks * 16 + t2 + 8];
    }

    float oc[16][4];
    #pragma unroll
    for (int n = 0; n < 16; n++)
        #pragma unroll
        for (int i = 0; i < 4; i++) oc[n][i] = 0.0f;

    float m0r = -1e30f, m1r = -1e30f;
    float l0 = 0.0f, l1 = 0.0f;
    int row0 = m0 + w * 16 + g;
    int rowlim0 = row0 + 1024;
    int rowlim1 = rowlim0 + 8;
    const float scale = 0.08838834764831845f;

    uint32_t koff = ((lane & 7) * KLD + (lane >> 3) * 8) * 2;
    uint32_t voff = ((((lane >> 3) & 1) * 8 + (lane & 7)) * KLD + (lane >> 4) * 8) * 2;

    for (int kt = 0; kt < nt; kt++) {
        asm volatile("cp.async.wait_group 0;\n");
        __syncthreads();

        if (tid < 128 && kt + 1 < nt) Ms[((kt + 1) & 1) * 128 + tid] = mrow[(kt + 1) * 128 + tid];

        if (kt + 1 < nt) {
            int bn = (kt + 1) & 1;
            #pragma unroll
            for (int i = tid; i < 128 * 16; i += 256) {
                int r = i >> 4, c8 = (i & 15) * 8;
                cpa16(&Kb[bn][r * KLD + c8], &kp[(size_t)((kt + 1) * 128 + r) * DD + c8]);
            }
            asm volatile("cp.async.commit_group;\n");
            #pragma unroll
            for (int i = tid; i < 128 * 16; i += 256) {
                int r = i >> 4, c8 = (i & 15) * 8;
                cpa16(&Vb[bn][r * KLD + c8], &vp[(size_t)((kt + 1) * 128 + r) * DD + c8]);
            }
            asm volatile("cp.async.commit_group;\n");
        }

        const __half* Kt = Kb[kt & 1];
        const __half* Vt = Vb[kt & 1];
        const int* Mt = Ms + (kt & 1) * 128;

        float sc[16][4];
        #pragma unroll
        for (int n = 0; n < 16; n++)
            #pragma unroll
            for (int i = 0; i < 4; i++) sc[n][i] = 0.0f;

        uint32_t ktu = smem_u32(Kt) + koff;
        #pragma unroll
        for (int ksp = 0; ksp < 4; ksp++) {
            #pragma unroll
            for (int nb = 0; nb < 16; nb++) {
                uint32_t br[4];
                ldsm4(br, ktu + (uint32_t)(nb * 8 * KLD + ksp * 32) * 2);
                mma16816(sc[nb], qa[2 * ksp],     br[0], br[1]);
                mma16816(sc[nb], qa[2 * ksp + 1], br[2], br[3]);
            }
        }

        bool lastt = (kt == nt - 1);
        float mx0 = -1e30f, mx1 = -1e30f;
        #pragma unroll
        for (int nb = 0; nb < 16; nb++) {
            int col = kt * 128 + nb * 8 + t2;
            int2 mv = *(const int2*)&Mt[nb * 8 + t2];
            float v0 = sc[nb][0] * scale;
            float v1 = sc[nb][1] * scale;
            float v2 = sc[nb][2] * scale;
            float v3 = sc[nb][3] * scale;
            if (mv.x == 0) { v0 = -1e30f; v2 = -1e30f; }
            if (mv.y == 0) { v1 = -1e30f; v3 = -1e30f; }
            if (lastt) {
                if (col     > rowlim0) v0 = -1e30f;
                if (col + 1 > rowlim0) v1 = -1e30f;
                if (col     > rowlim1) v2 = -1e30f;
                if (col + 1 > rowlim1) v3 = -1e30f;
            }
            sc[nb][0] = v0; sc[nb][1] = v1; sc[nb][2] = v2; sc[nb][3] = v3;
            mx0 = fmaxf(mx0, fmaxf(v0, v1));
            mx1 = fmaxf(mx1, fmaxf(v2, v3));
        }
        mx0 = fmaxf(mx0, __shfl_xor_sync(0xffffffffu, mx0, 1));
        mx0 = fmaxf(mx0, __shfl_xor_sync(0xffffffffu, mx0, 2));
        mx1 = fmaxf(mx1, __shfl_xor_sync(0xffffffffu, mx1, 1));
        mx1 = fmaxf(mx1, __shfl_xor_sync(0xffffffffu, mx1, 2));

        float mn0 = fmaxf(m0r, mx0), mn1 = fmaxf(m1r, mx1);
        float al0 = __expf(m0r - mn0), al1 = __expf(m1r - mn1);
        m0r = mn0; m1r = mn1;

        float s0 = 0.0f, s1 = 0.0f;
        #pragma unroll
        for (int nb = 0; nb < 16; nb++) {
            float p0 = __expf(sc[nb][0] - mn0);
            float p1 = __expf(sc[nb][1] - mn0);
            float p2 = __expf(sc[nb][2] - mn1);
            float p3 = __expf(sc[nb][3] - mn1);
            sc[nb][0] = p0; sc[nb][1] = p1; sc[nb][2] = p2; sc[nb][3] = p3;
            s0 += p0 + p1; s1 += p2 + p3;
        }
        l0 = l0 * al0 + s0;
        l1 = l1 * al1 + s1;
        #pragma unroll
        for (int n = 0; n < 16; n++) {
            oc[n][0] *= al0; oc[n][1] *= al0;
            oc[n][2] *= al1; oc[n][3] *= al1;
        }

        uint32_t vtu = smem_u32(Vt) + voff;
        #pragma unroll
        for (int kk = 0; kk < 8; kk++) {
            uint32_t pa[4];
            pa[0] = f2h2(sc[2 * kk][0],     sc[2 * kk][1]);
            pa[1] = f2h2(sc[2 * kk][2],     sc[2 * kk][3]);
            pa[2] = f2h2(sc[2 * kk + 1][0], sc[2 * kk + 1][1]);
            pa[3] = f2h2(sc[2 * kk + 1][2], sc[2 * kk + 1][3]);
            #pragma unroll
            for (int ndp = 0; ndp < 8; ndp++) {
                uint32_t br[4];
                ldsm4t(br, vtu + (uint32_t)(kk * 16 * KLD + ndp * 16) * 2);
                mma16816(oc[2 * ndp],     pa, br[0], br[1]);
                mma16816(oc[2 * ndp + 1], pa, br[2], br[3]);
            }
        }
    }

    l0 += __shfl_xor_sync(0xffffffffu, l0, 1);
    l0 += __shfl_xor_sync(0xffffffffu, l0, 2);
    l1 += __shfl_xor_sync(0xffffffffu, l1, 1);
    l1 += __shfl_xor_sync(0xffffffffu, l1, 2);
    float inv0 = 1.0f / l0, inv1 = 1.0f / l1;

    __half* out0 = g_attnout + (size_t)(b * NN + row0) * DIMM + h * DD;
    __half* out1 = out0 + (size_t)8 * DIMM;
    #pragma unroll
    for (int nd = 0; nd < 16; nd++) {
        *(uint32_t*)&out0[nd * 8 + t2] = f2h2(oc[nd][0] * inv0, oc[nd][1] * inv0);
        *(uint32_t*)&out1[nd * 8 + t2] = f2h2(oc[nd][2] * inv1, oc[nd][3] * inv1);
    }
}

// ---------------- launch ----------------
extern "C" void kernel_launch(void* const* d_in, const int* in_sizes, int n_in,
                              void* d_out, int out_size) {
    const float* x       = (const float*)d_in[0];
    const float* cache   = (const float*)d_in[1];
    const float* rotary  = (const float*)d_in[2];
    const int*   mask    = (const int*)d_in[3];
    const float* norm_w  = (const float*)d_in[4];
    const float* w_qkv   = (const float*)d_in[5];
    const float* w_out   = (const float*)d_in[6];

    float* out    = (float*)d_out;
    float* kv_out = out + (size_t)ROWS * DIMM;

    __half *xn_ptr, *wqkv_ptr, *wout_ptr, *ao_ptr, *qkvh_ptr;
    cudaGetSymbolAddress((void**)&xn_ptr, g_xn);
    cudaGetSymbolAddress((void**)&qkvh_ptr, g_qkv_h);
    cudaGetSymbolAddress((void**)&ao_ptr, g_attnout);
    cudaGetSymbolAddress((void**)&wqkv_ptr, g_wqkv_h);
    cudaGetSymbolAddress((void**)&wout_ptr, g_wout_h);

    cudaFuncSetAttribute(attn_kernel, cudaFuncAttributeMaxDynamicSharedMemorySize, AT_SMEM_BYTES);
    cudaFuncSetAttribute(gemm_hp, cudaFuncAttributeMaxDynamicSharedMemorySize, G_SMEM_BYTES);
    cudaFuncSetAttribute(gemm_hp192, cudaFuncAttributeMaxDynamicSharedMemorySize, G2_SMEM_BYTES);

    prep_kernel<<<PREP_BLKS, 256>>>(rotary, w_qkv, w_out, x, norm_w);

    gemm_hp192<<<dim3(NQKV / 192, ROWS / 128), 256, G2_SMEM_BYTES>>>(xn_ptr, wqkv_ptr, qkvh_ptr,
                                                                     ROWS, NQKV, DIMM);

    scatter_rotary_kernel<<<(BB * HH * JJ * 16) / 256, 256>>>(cache, kv_out);

    attn_kernel<<<BB * HH * (NN / 128), 256, AT_SMEM_BYTES>>>(mask);

    gemm_hp<<<dim3(DIMM / 256, ROWS / 128), 256, G_SMEM_BYTES>>>(ao_ptr, wout_ptr, out,
                                                                 ROWS, DIMM, DIMM);
}

// round 15
// speedup vs baseline: 6.7096x; 1.0050x over previous
#include <cuda_runtime.h>
#include <cuda_fp16.h>
#include <mma.h>
#include <cstdint>

using namespace nvcuda;

#define BB 4
#define NN 1024
#define JJ 2048
#define HH 16
#define DD 128
#define DIMM 2048
#define NQKV 6144
#define ROWS 4096

__device__ __half g_xn[(size_t)ROWS * DIMM];
__device__ __half g_qkv_h[(size_t)ROWS * NQKV];
__device__ __half g_qrot[(size_t)BB * HH * NN * DD];
__device__ __half g_krot[(size_t)BB * HH * JJ * DD];
__device__ __half g_vfull[(size_t)BB * HH * JJ * DD];
__device__ __half g_attnout[(size_t)ROWS * DIMM];
__device__ __half g_wqkv_h[(size_t)DIMM * NQKV];
__device__ __half g_wout_h[(size_t)DIMM * DIMM];
__device__ float  g_cos[JJ * DD];
__device__ float  g_sin[JJ * DD];

__device__ __forceinline__ void cpa16(void* smem, const void* gmem) {
    unsigned s = (unsigned)__cvta_generic_to_shared(smem);
    asm volatile("cp.async.cg.shared.global [%0], [%1], 16;\n" :: "r"(s), "l"(gmem));
}

__device__ __forceinline__ uint32_t smem_u32(const void* p) {
    uint32_t a;
    asm("{ .reg .u64 t; cvta.to.shared.u64 t, %1; cvt.u32.u64 %0, t; }" : "=r"(a) : "l"(p));
    return a;
}

__device__ __forceinline__ void ldsm4(uint32_t* r, uint32_t a) {
    asm volatile("ldmatrix.sync.aligned.m8n8.x4.shared.b16 {%0,%1,%2,%3}, [%4];"
                 : "=r"(r[0]), "=r"(r[1]), "=r"(r[2]), "=r"(r[3]) : "r"(a));
}
__device__ __forceinline__ void ldsm4t(uint32_t* r, uint32_t a) {
    asm volatile("ldmatrix.sync.aligned.m8n8.x4.trans.shared.b16 {%0,%1,%2,%3}, [%4];"
                 : "=r"(r[0]), "=r"(r[1]), "=r"(r[2]), "=r"(r[3]) : "r"(a));
}

__device__ __forceinline__ void mma16816(float* c, const uint32_t* a, uint32_t b0, uint32_t b1) {
    asm volatile(
        "mma.sync.aligned.m16n8k16.row.col.f32.f16.f16.f32 "
        "{%0,%1,%2,%3}, {%4,%5,%6,%7}, {%8,%9}, {%0,%1,%2,%3};"
        : "+f"(c[0]), "+f"(c[1]), "+f"(c[2]), "+f"(c[3])
        : "r"(a[0]), "r"(a[1]), "r"(a[2]), "r"(a[3]), "r"(b0), "r"(b1));
}

__device__ __forceinline__ uint32_t f2h2(float x, float y) {
    __half2 h = __floats2half2_rn(x, y);
    return *(uint32_t*)&h;
}

__device__ __forceinline__ float4 ld_half4(const __half* p) {
    uint2 u = *(const uint2*)p;
    __half2 a = *(__half2*)&u.x, b = *(__half2*)&u.y;
    float2 fa = __half22float2(a), fb = __half22float2(b);
    return make_float4(fa.x, fa.y, fb.x, fb.y);
}

// ---------------- merged prep: weight converts + rope table + rmsnorm ----------------
#define PREP_WQKV_BLKS 12288
#define PREP_WOUT_BLKS 4096
#define PREP_ROPE_BLKS 256
#define PREP_CONV_BLKS (PREP_WQKV_BLKS + PREP_WOUT_BLKS + PREP_ROPE_BLKS)
#define PREP_BLKS (PREP_CONV_BLKS + ROWS)

__global__ void __launch_bounds__(256) prep_kernel(const float* __restrict__ rot,
                                                   const float* __restrict__ wqkv,
                                                   const float* __restrict__ wout,
                                                   const float* __restrict__ x,
                                                   const float* __restrict__ w) {
    int bid = blockIdx.x;
    int tid = threadIdx.x;
    if (bid < PREP_WQKV_BLKS) {
        int idx = (bid * 256 + tid) * 4;
        float4 v = *(const float4*)(wqkv + idx);
        *(__half2*)(g_wqkv_h + idx)     = __floats2half2_rn(v.x, v.y);
        *(__half2*)(g_wqkv_h + idx + 2) = __floats2half2_rn(v.z, v.w);
    } else if (bid < PREP_WQKV_BLKS + PREP_WOUT_BLKS) {
        int idx = ((bid - PREP_WQKV_BLKS) * 256 + tid) * 4;
        float4 v = *(const float4*)(wout + idx);
        *(__half2*)(g_wout_h + idx)     = __floats2half2_rn(v.x, v.y);
        *(__half2*)(g_wout_h + idx + 2) = __floats2half2_rn(v.z, v.w);
    } else if (bid < PREP_CONV_BLKS) {
        int idx = ((bid - PREP_WQKV_BLKS - PREP_WOUT_BLKS) * 256 + tid) * 4;
        float4 p = *(const float4*)(rot + idx);
        *(float4*)&g_cos[idx] = make_float4(cosf(p.x), cosf(p.y), cosf(p.z), cosf(p.w));
        *(float4*)&g_sin[idx] = make_float4(sinf(p.x), sinf(p.y), sinf(p.z), sinf(p.w));
    } else {
        int row = bid - PREP_CONV_BLKS;
        const float4* xr = (const float4*)(x + (size_t)row * DIMM);
        float4 a = xr[tid];
        float4 b = xr[tid + 256];
        float ss = a.x * a.x + a.y * a.y + a.z * a.z + a.w * a.w
                 + b.x * b.x + b.y * b.y + b.z * b.z + b.w * b.w;
        #pragma unroll
        for (int o = 16; o; o >>= 1) ss += __shfl_xor_sync(0xffffffffu, ss, o);
        __shared__ float red[8];
        if ((tid & 31) == 0) red[tid >> 5] = ss;
        __syncthreads();
        float tot = red[0] + red[1] + red[2] + red[3] + red[4] + red[5] + red[6] + red[7];
        float inv = rsqrtf(tot * (1.0f / (float)DIMM) + 1.1920929e-7f);

        const float4* wr = (const float4*)w;
        float4 wa = wr[tid];
        float4 wb = wr[tid + 256];
        uint2 o0, o1;
        o0.x = f2h2(a.x * inv * wa.x, a.y * inv * wa.y);
        o0.y = f2h2(a.z * inv * wa.z, a.w * inv * wa.w);
        o1.x = f2h2(b.x * inv * wb.x, b.y * inv * wb.y);
        o1.y = f2h2(b.z * inv * wb.z, b.w * inv * wb.w);
        *(uint2*)&g_xn[(size_t)row * DIMM + tid * 4]        = o0;
        *(uint2*)&g_xn[(size_t)row * DIMM + 1024 + tid * 4] = o1;
    }
}

// ---------------- fp16 GEMM v1: block 128x256, warp 64x64, KSTEP 64, 4-stage (out-proj, fp32 out) ----------------
#define GS 4
#define A_LD 72
#define B_LD 264
#define ASZ (128 * A_LD)
#define BSZ (64 * B_LD)
#define G_SMEM_BYTES (GS * (ASZ + BSZ) * 2)

__global__ void __launch_bounds__(256, 1) gemm_hp(const __half* __restrict__ A,
                                                  const __half* __restrict__ B,
                                                  float* __restrict__ C,
                                                  int M, int N, int K) {
    extern __shared__ __half hsm[];
    __half* As = hsm;
    __half* Bs = hsm + GS * ASZ;

    int tid = threadIdx.x;
    int n0 = blockIdx.x * 256;
    int m0 = blockIdx.y * 128;
    int w = tid >> 5;
    int wm = w >> 2;
    int wn = w & 3;

    wmma::fragment<wmma::accumulator, 16, 16, 16, float> acc[4][4];
    #pragma unroll
    for (int i = 0; i < 4; i++)
        #pragma unroll
        for (int j = 0; j < 4; j++) wmma::fill_fragment(acc[i][j], 0.0f);

    #define LOAD_STAGE(st, kk)                                                          \
        {                                                                               \
            __half* as_ = As + (st) * ASZ;                                              \
            __half* bs_ = Bs + (st) * BSZ;                                              \
            _Pragma("unroll")                                                           \
            for (int i = 0; i < 4; i++) {                                               \
                int c = tid + 256 * i;                                                  \
                int r = c >> 3, c8 = (c & 7) * 8;                                       \
                cpa16(&as_[r * A_LD + c8], &A[(size_t)(m0 + r) * K + (kk) + c8]);       \
            }                                                                           \
            _Pragma("unroll")                                                           \
            for (int i = 0; i < 8; i++) {                                               \
                int c = tid + 256 * i;                                                  \
                int r = c >> 5, c8 = (c & 31) * 8;                                      \
                cpa16(&bs_[r * B_LD + c8], &B[(size_t)((kk) + r) * N + n0 + c8]);       \
            }                                                                           \
            asm volatile("cp.async.commit_group;\n");                                   \
        }

    LOAD_STAGE(0, 0);
    LOAD_STAGE(1, 64);
    LOAD_STAGE(2, 128);

    int nk = K >> 6;
    for (int kt = 0; kt < nk; kt++) {
        int rem = nk - 1 - kt;
        if (rem >= 2)      asm volatile("cp.async.wait_group 2;\n");
        else if (rem == 1) asm volatile("cp.async.wait_group 1;\n");
        else               asm volatile("cp.async.wait_group 0;\n");
        __syncthreads();

        if (kt + 3 < nk) {
            LOAD_STAGE((kt + 3) & 3, (kt + 3) << 6);
        }

        const __half* as = As + (kt & 3) * ASZ;
        const __half* bs = Bs + (kt & 3) * BSZ;

        #pragma unroll
        for (int kf = 0; kf < 4; kf++) {
            wmma::fragment<wmma::matrix_a, 16, 16, 16, __half, wmma::row_major> af[4];
            wmma::fragment<wmma::matrix_b, 16, 16, 16, __half, wmma::row_major> bf[4];
            #pragma unroll
            for (int i = 0; i < 4; i++)
                wmma::load_matrix_sync(af[i], &as[(wm * 64 + i * 16) * A_LD + kf * 16], A_LD);
            #pragma unroll
            for (int j = 0; j < 4; j++)
                wmma::load_matrix_sync(bf[j], &bs[(kf * 16) * B_LD + wn * 64 + j * 16], B_LD);
            #pragma unroll
            for (int i = 0; i < 4; i++)
                #pragma unroll
                for (int j = 0; j < 4; j++)
                    wmma::mma_sync(acc[i][j], af[i], bf[j], acc[i][j]);
        }
    }

    #pragma unroll
    for (int i = 0; i < 4; i++)
        #pragma unroll
        for (int j = 0; j < 4; j++)
            wmma::store_matrix_sync(&C[(size_t)(m0 + wm * 64 + i * 16) * N + n0 + wn * 64 + j * 16],
                                    acc[i][j], N, wmma::mem_row_major);
    #undef LOAD_STAGE
}

// ---------------- fp16 GEMM v2: block 128x192, warp 64x48, KSTEP 64, 4-stage (QKV; half output) ----------------
#define A_LD2 72
#define B_LD2 200
#define ASZ2 (128 * A_LD2)
#define BSZ2 (64 * B_LD2)
#define G2_SMEM_BYTES (GS * (ASZ2 + BSZ2) * 2)

__global__ void __launch_bounds__(256, 1) gemm_hp192(const __half* __restrict__ A,
                                                     const __half* __restrict__ B,
                                                     __half* __restrict__ C,
                                                     int M, int N, int K) {
    extern __shared__ __half hsm[];
    __half* As = hsm;
    __half* Bs = hsm + GS * ASZ2;

    int tid = threadIdx.x;
    int lane = tid & 31;
    int n0 = blockIdx.x * 192;
    int m0 = blockIdx.y * 128;
    int w = tid >> 5;
    int wm = w >> 2;
    int wn = w & 3;

    wmma::fragment<wmma::accumulator, 16, 16, 16, float> acc[4][3];
    #pragma unroll
    for (int i = 0; i < 4; i++)
        #pragma unroll
        for (int j = 0; j < 3; j++) wmma::fill_fragment(acc[i][j], 0.0f);

    #define LOAD_STAGE2(st, kk)                                                         \
        {                                                                               \
            __half* as_ = As + (st) * ASZ2;                                             \
            __half* bs_ = Bs + (st) * BSZ2;                                             \
            _Pragma("unroll")                                                           \
            for (int i = 0; i < 4; i++) {                                               \
                int c = tid + 256 * i;                                                  \
                int r = c >> 3, c8 = (c & 7) * 8;                                       \
                cpa16(&as_[r * A_LD2 + c8], &A[(size_t)(m0 + r) * K + (kk) + c8]);      \
            }                                                                           \
            _Pragma("unroll")                                                           \
            for (int i = 0; i < 6; i++) {                                               \
                int c = tid + 256 * i;                                                  \
                int r = c / 24, cc = (c % 24) * 8;                                      \
                cpa16(&bs_[r * B_LD2 + cc], &B[(size_t)((kk) + r) * N + n0 + cc]);      \
            }                                                                           \
            asm volatile("cp.async.commit_group;\n");                                   \
        }

    LOAD_STAGE2(0, 0);
    LOAD_STAGE2(1, 64);
    LOAD_STAGE2(2, 128);

    int nk = K >> 6;
    for (int kt = 0; kt < nk; kt++) {
        int rem = nk - 1 - kt;
        if (rem >= 2)      asm volatile("cp.async.wait_group 2;\n");
        else if (rem == 1) asm volatile("cp.async.wait_group 1;\n");
        else               asm volatile("cp.async.wait_group 0;\n");
        __syncthreads();

        if (kt + 3 < nk) {
            LOAD_STAGE2((kt + 3) & 3, (kt + 3) << 6);
        }

        const __half* as = As + (kt & 3) * ASZ2;
        const __half* bs = Bs + (kt & 3) * BSZ2;

        #pragma unroll
        for (int kf = 0; kf < 4; kf++) {
            wmma::fragment<wmma::matrix_a, 16, 16, 16, __half, wmma::row_major> af[4];
            wmma::fragment<wmma::matrix_b, 16, 16, 16, __half, wmma::row_major> bf[3];
            #pragma unroll
            for (int i = 0; i < 4; i++)
                wmma::load_matrix_sync(af[i], &as[(wm * 64 + i * 16) * A_LD2 + kf * 16], A_LD2);
            #pragma unroll
            for (int j = 0; j < 3; j++)
                wmma::load_matrix_sync(bf[j], &bs[(kf * 16) * B_LD2 + wn * 48 + j * 16], B_LD2);
            #pragma unroll
            for (int i = 0; i < 4; i++)
                #pragma unroll
                for (int j = 0; j < 3; j++)
                    wmma::mma_sync(acc[i][j], af[i], bf[j], acc[i][j]);
        }
    }

    __syncthreads();
    float* stage = (float*)hsm + w * (16 * 52);
    #pragma unroll
    for (int i = 0; i < 4; i++) {
        #pragma unroll
        for (int j = 0; j < 3; j++)
            wmma::store_matrix_sync(stage + j * 16, acc[i][j], 52, wmma::mem_row_major);
        __syncwarp();
        int rbase = m0 + wm * 64 + i * 16;
        #pragma unroll
        for (int e = 0; e < 12; e++) {
            int idx = lane + e * 32;
            int r = idx / 24, c2 = (idx % 24) * 2;
            float x0 = stage[r * 52 + c2];
            float x1 = stage[r * 52 + c2 + 1];
            *(uint32_t*)&C[(size_t)(rbase + r) * N + n0 + wn * 48 + c2] = f2h2(x0, x1);
        }
        __syncwarp();
    }
    #undef LOAD_STAGE2
}

// ---------------- scatter + rotary: q pre-scaled by 1/sqrt(d) ----------------
#define QSCALE 0.08838834764831845f

__global__ void __launch_bounds__(256) scatter_rotary_kernel(const float* __restrict__ cache,
                                                             float* __restrict__ kv_out) {
    int idx = blockIdx.x * 256 + threadIdx.x;
    int d4 = (idx & 15) * 4;
    int j  = (idx >> 4) & 2047;
    int h  = (idx >> 15) & 15;
    int b  = idx >> 19;

    float4 cl = *(const float4*)&g_cos[j * DD + d4];
    float4 ch = *(const float4*)&g_cos[j * DD + d4 + 64];
    float4 sl = *(const float4*)&g_sin[j * DD + d4];
    float4 sh = *(const float4*)&g_sin[j * DD + d4 + 64];

    float4 kl, kh, vl, vh;
    if (j < 1024) {
        const float* ckb = cache + (((size_t)(b * 2 + 0) * HH + h) * 1024 + j) * DD;
        const float* cvb = cache + (((size_t)(b * 2 + 1) * HH + h) * 1024 + j) * DD;
        kl = *(const float4*)(ckb + d4);
        kh = *(const float4*)(ckb + d4 + 64);
        vl = *(const float4*)(cvb + d4);
        vh = *(const float4*)(cvb + d4 + 64);
    } else {
        int rrow = b * NN + (j - 1024);
        const __half* qr = g_qkv_h + (size_t)rrow * NQKV;
        kl = ld_half4(qr + 2048 + h * DD + d4);
        kh = ld_half4(qr + 2048 + h * DD + d4 + 64);
        vl = ld_half4(qr + 4096 + h * DD + d4);
        vh = ld_half4(qr + 4096 + h * DD + d4 + 64);
        float4 ql = ld_half4(qr + h * DD + d4);
        float4 qh = ld_half4(qr + h * DD + d4 + 64);
        size_t qidx = (((size_t)(b * HH + h) * NN + (j - 1024)) * DD) + d4;
        uint2 qlo, qhi;
        qlo.x = f2h2((ql.x * cl.x - qh.x * sl.x) * QSCALE, (ql.y * cl.y - qh.y * sl.y) * QSCALE);
        qlo.y = f2h2((ql.z * cl.z - qh.z * sl.z) * QSCALE, (ql.w * cl.w - qh.w * sl.w) * QSCALE);
        qhi.x = f2h2((qh.x * ch.x + ql.x * sh.x) * QSCALE, (qh.y * ch.y + ql.y * sh.y) * QSCALE);
        qhi.y = f2h2((qh.z * ch.z + ql.z * sh.z) * QSCALE, (qh.w * ch.w + ql.w * sh.w) * QSCALE);
        *(uint2*)&g_qrot[qidx]      = qlo;
        *(uint2*)&g_qrot[qidx + 64] = qhi;
    }

    size_t kvidx = ((size_t)(b * HH + h) * JJ + j) * DD + d4;
    uint2 klo, khi, vlo, vhi;
    klo.x = f2h2(kl.x * cl.x - kh.x * sl.x, kl.y * cl.y - kh.y * sl.y);
    klo.y = f2h2(kl.z * cl.z - kh.z * sl.z, kl.w * cl.w - kh.w * sl.w);
    khi.x = f2h2(kh.x * ch.x + kl.x * sh.x, kh.y * ch.y + kl.y * sh.y);
    khi.y = f2h2(kh.z * ch.z + kl.z * sh.z, kh.w * ch.w + kl.w * sh.w);
    vlo.x = f2h2(vl.x, vl.y);  vlo.y = f2h2(vl.z, vl.w);
    vhi.x = f2h2(vh.x, vh.y);  vhi.y = f2h2(vh.z, vh.w);
    *(uint2*)&g_krot[kvidx]       = klo;
    *(uint2*)&g_krot[kvidx + 64]  = khi;
    *(uint2*)&g_vfull[kvidx]      = vlo;
    *(uint2*)&g_vfull[kvidx + 64] = vhi;

    float* ko = &kv_out[(((size_t)(b * 2 + 0) * HH + h) * JJ + j) * DD + d4];
    float* vo = &kv_out[(((size_t)(b * 2 + 1) * HH + h) * JJ + j) * DD + d4];
    *(float4*)(ko)      = kl;
    *(float4*)(ko + 64) = kh;
    *(float4*)(vo)      = vl;
    *(float4*)(vo + 64) = vh;
}

// ---------------- flash attention: register-resident, ldmatrix, early P->half ----------------
#define KLD 136
#define TILE_H (128 * KLD)
#define AT_SMEM_BYTES (5 * TILE_H * 2 + 2 * 128 * 4)

__global__ void __launch_bounds__(256, 1) attn_kernel(const int* __restrict__ mask) {
    extern __shared__ char asmem[];
    __half* Qs = (__half*)asmem;
    __half* Kb[2] = { Qs + 1 * TILE_H, Qs + 3 * TILE_H };
    __half* Vb[2] = { Qs + 2 * TILE_H, Qs + 4 * TILE_H };
    int* Ms = (int*)(Qs + 5 * TILE_H);

    int tid = threadIdx.x;
    int w = tid >> 5;
    int lane = tid & 31;
    int g = lane >> 2;
    int t2 = (lane & 3) * 2;

    int bid = blockIdx.x;
    int b  = bid & 3;
    int h  = (bid >> 2) & 15;
    int qb = 7 - (bid >> 6);
    int m0 = qb * 128;

    const __half* qp = g_qrot + ((size_t)(b * HH + h) * NN + m0) * DD;
    const __half* kp = g_krot + (size_t)(b * HH + h) * JJ * DD;
    const __half* vp = g_vfull + (size_t)(b * HH + h) * JJ * DD;
    const int* mrow = mask + (size_t)b * JJ;

    int nt = qb + 9;

    #pragma unroll
    for (int i = tid; i < 128 * 16; i += 256) {
        int r = i >> 4, c8 = (i & 15) * 8;
        *(float4*)&Qs[r * KLD + c8] = *(const float4*)&qp[(size_t)r * DD + c8];
    }
    if (tid < 128) Ms[tid] = mrow[tid];
    #pragma unroll
    for (int i = tid; i < 128 * 16; i += 256) {
        int r = i >> 4, c8 = (i & 15) * 8;
        cpa16(&Kb[0][r * KLD + c8], &kp[(size_t)r * DD + c8]);
    }
    asm volatile("cp.async.commit_group;\n");
    #pragma unroll
    for (int i = tid; i < 128 * 16; i += 256) {
        int r = i >> 4, c8 = (i & 15) * 8;
        cpa16(&Vb[0][r * KLD + c8], &vp[(size_t)r * DD + c8]);
    }
    asm volatile("cp.async.commit_group;\n");
    __syncthreads();

    uint32_t qa[8][4];
    int qr0 = (w * 16 + g) * KLD;
    int qr1 = (w * 16 + g + 8) * KLD;
    #pragma unroll
    for (int ks = 0; ks < 8; ks++) {
        qa[ks][0] = *(uint32_t*)&Qs[qr0 + ks * 16 + t2];
        qa[ks][1] = *(uint32_t*)&Qs[qr1 + ks * 16 + t2];
        qa[ks][2] = *(uint32_t*)&Qs[qr0 + ks * 16 + t2 + 8];
        qa[ks][3] = *(uint32_t*)&Qs[qr1 + ks * 16 + t2 + 8];
    }

    float oc[16][4];
    #pragma unroll
    for (int n = 0; n < 16; n++)
        #pragma unroll
        for (int i = 0; i < 4; i++) oc[n][i] = 0.0f;

    float m0r = -1e30f, m1r = -1e30f;
    float l0 = 0.0f, l1 = 0.0f;
    int row0 = m0 + w * 16 + g;
    int rowlim0 = row0 + 1024;
    int rowlim1 = rowlim0 + 8;

    uint32_t koff = ((lane & 7) * KLD + (lane >> 3) * 8) * 2;
    uint32_t voff = ((((lane >> 3) & 1) * 8 + (lane & 7)) * KLD + (lane >> 4) * 8) * 2;

    for (int kt = 0; kt < nt; kt++) {
        asm volatile("cp.async.wait_group 0;\n");
        __syncthreads();

        if (tid < 128 && kt + 1 < nt) Ms[((kt + 1) & 1) * 128 + tid] = mrow[(kt + 1) * 128 + tid];

        if (kt + 1 < nt) {
            int bn = (kt + 1) & 1;
            #pragma unroll
            for (int i = tid; i < 128 * 16; i += 256) {
                int r = i >> 4, c8 = (i & 15) * 8;
                cpa16(&Kb[bn][r * KLD + c8], &kp[(size_t)((kt + 1) * 128 + r) * DD + c8]);
            }
            asm volatile("cp.async.commit_group;\n");
            #pragma unroll
            for (int i = tid; i < 128 * 16; i += 256) {
                int r = i >> 4, c8 = (i & 15) * 8;
                cpa16(&Vb[bn][r * KLD + c8], &vp[(size_t)((kt + 1) * 128 + r) * DD + c8]);
            }
            asm volatile("cp.async.commit_group;\n");
        }

        const __half* Kt = Kb[kt & 1];
        const __half* Vt = Vb[kt & 1];
        const int* Mt = Ms + (kt & 1) * 128;

        // S = Q K^T (Q pre-scaled)
        float sc[16][4];
        #pragma unroll
        for (int n = 0; n < 16; n++)
            #pragma unroll
            for (int i = 0; i < 4; i++) sc[n][i] = 0.0f;

        uint32_t ktu = smem_u32(Kt) + koff;
        #pragma unroll
        for (int ksp = 0; ksp < 4; ksp++) {
            #pragma unroll
            for (int nb = 0; nb < 16; nb++) {
                uint32_t br[4];
                ldsm4(br, ktu + (uint32_t)(nb * 8 * KLD + ksp * 32) * 2);
                mma16816(sc[nb], qa[2 * ksp],     br[0], br[1]);
                mma16816(sc[nb], qa[2 * ksp + 1], br[2], br[3]);
            }
        }

        // mask + row max
        bool lastt = (kt == nt - 1);
        float mx0 = -1e30f, mx1 = -1e30f;
        #pragma unroll
        for (int nb = 0; nb < 16; nb++) {
            int col = kt * 128 + nb * 8 + t2;
            int2 mv = *(const int2*)&Mt[nb * 8 + t2];
            float v0 = sc[nb][0];
            float v1 = sc[nb][1];
            float v2 = sc[nb][2];
            float v3 = sc[nb][3];
            if (mv.x == 0) { v0 = -1e30f; v2 = -1e30f; }
            if (mv.y == 0) { v1 = -1e30f; v3 = -1e30f; }
            if (lastt) {
                if (col     > rowlim0) v0 = -1e30f;
                if (col + 1 > rowlim0) v1 = -1e30f;
                if (col     > rowlim1) v2 = -1e30f;
                if (col + 1 > rowlim1) v3 = -1e30f;
            }
            sc[nb][0] = v0; sc[nb][1] = v1; sc[nb][2] = v2; sc[nb][3] = v3;
            mx0 = fmaxf(mx0, fmaxf(v0, v1));
            mx1 = fmaxf(mx1, fmaxf(v2, v3));
        }
        mx0 = fmaxf(mx0, __shfl_xor_sync(0xffffffffu, mx0, 1));
        mx0 = fmaxf(mx0, __shfl_xor_sync(0xffffffffu, mx0, 2));
        mx1 = fmaxf(mx1, __shfl_xor_sync(0xffffffffu, mx1, 1));
        mx1 = fmaxf(mx1, __shfl_xor_sync(0xffffffffu, mx1, 2));

        float mn0 = fmaxf(m0r, mx0), mn1 = fmaxf(m1r, mx1);
        float al0 = __expf(m0r - mn0), al1 = __expf(m1r - mn1);
        m0r = mn0; m1r = mn1;

        // exp + immediate pack to half (ends sc's live range here)
        uint32_t ph0[16], ph1[16];
        float s0 = 0.0f, s1 = 0.0f;
        #pragma unroll
        for (int nb = 0; nb < 16; nb++) {
            float p0 = __expf(sc[nb][0] - mn0);
            float p1 = __expf(sc[nb][1] - mn0);
            float p2 = __expf(sc[nb][2] - mn1);
            float p3 = __expf(sc[nb][3] - mn1);
            s0 += p0 + p1; s1 += p2 + p3;
            ph0[nb] = f2h2(p0, p1);
            ph1[nb] = f2h2(p2, p3);
        }
        l0 = l0 * al0 + s0;
        l1 = l1 * al1 + s1;
        #pragma unroll
        for (int n = 0; n < 16; n++) {
            oc[n][0] *= al0; oc[n][1] *= al0;
            oc[n][2] *= al1; oc[n][3] *= al1;
        }

        // PV
        uint32_t vtu = smem_u32(Vt) + voff;
        #pragma unroll
        for (int kk = 0; kk < 8; kk++) {
            uint32_t pa[4];
            pa[0] = ph0[2 * kk];
            pa[1] = ph1[2 * kk];
            pa[2] = ph0[2 * kk + 1];
            pa[3] = ph1[2 * kk + 1];
            #pragma unroll
            for (int ndp = 0; ndp < 8; ndp++) {
                uint32_t br[4];
                ldsm4t(br, vtu + (uint32_t)(kk * 16 * KLD + ndp * 16) * 2);
                mma16816(oc[2 * ndp],     pa, br[0], br[1]);
                mma16816(oc[2 * ndp + 1], pa, br[2], br[3]);
            }
        }
    }

    l0 += __shfl_xor_sync(0xffffffffu, l0, 1);
    l0 += __shfl_xor_sync(0xffffffffu, l0, 2);
    l1 += __shfl_xor_sync(0xffffffffu, l1, 1);
    l1 += __shfl_xor_sync(0xffffffffu, l1, 2);
    float inv0 = 1.0f / l0, inv1 = 1.0f / l1;

    __half* out0 = g_attnout + (size_t)(b * NN + row0) * DIMM + h * DD;
    __half* out1 = out0 + (size_t)8 * DIMM;
    #pragma unroll
    for (int nd = 0; nd < 16; nd++) {
        *(uint32_t*)&out0[nd * 8 + t2] = f2h2(oc[nd][0] * inv0, oc[nd][1] * inv0);
        *(uint32_t*)&out1[nd * 8 + t2] = f2h2(oc[nd][2] * inv1, oc[nd][3] * inv1);
    }
}

// ---------------- launch ----------------
extern "C" void kernel_launch(void* const* d_in, const int* in_sizes, int n_in,
                              void* d_out, int out_size) {
    const float* x       = (const float*)d_in[0];
    const float* cache   = (const float*)d_in[1];
    const float* rotary  = (const float*)d_in[2];
    const int*   mask    = (const int*)d_in[3];
    const float* norm_w  = (const float*)d_in[4];
    const float* w_qkv   = (const float*)d_in[5];
    const float* w_out   = (const float*)d_in[6];

    float* out    = (float*)d_out;
    float* kv_out = out + (size_t)ROWS * DIMM;

    __half *xn_ptr, *wqkv_ptr, *wout_ptr, *ao_ptr, *qkvh_ptr;
    cudaGetSymbolAddress((void**)&xn_ptr, g_xn);
    cudaGetSymbolAddress((void**)&qkvh_ptr, g_qkv_h);
    cudaGetSymbolAddress((void**)&ao_ptr, g_attnout);
    cudaGetSymbolAddress((void**)&wqkv_ptr, g_wqkv_h);
    cudaGetSymbolAddress((void**)&wout_ptr, g_wout_h);

    cudaFuncSetAttribute(attn_kernel, cudaFuncAttributeMaxDynamicSharedMemorySize, AT_SMEM_BYTES);
    cudaFuncSetAttribute(gemm_hp, cudaFuncAttributeMaxDynamicSharedMemorySize, G_SMEM_BYTES);
    cudaFuncSetAttribute(gemm_hp192, cudaFuncAttributeMaxDynamicSharedMemorySize, G2_SMEM_BYTES);

    prep_kernel<<<PREP_BLKS, 256>>>(rotary, w_qkv, w_out, x, norm_w);

    gemm_hp192<<<dim3(NQKV / 192, ROWS / 128), 256, G2_SMEM_BYTES>>>(xn_ptr, wqkv_ptr, qkvh_ptr,
                                                                     ROWS, NQKV, DIMM);

    scatter_rotary_kernel<<<(BB * HH * JJ * 16) / 256, 256>>>(cache, kv_out);

    attn_kernel<<<BB * HH * (NN / 128), 256, AT_SMEM_BYTES>>>(mask);

    gemm_hp<<<dim3(DIMM / 256, ROWS / 128), 256, G_SMEM_BYTES>>>(ao_ptr, wout_ptr, out,
                                                                 ROWS, DIMM, DIMM);
}